// round 10
// baseline (speedup 1.0000x reference)
#include <cuda_runtime.h>
#include <cuda_bf16.h>
#include <cstdint>

// Problem constants (fixed by setup_inputs)
#define DIM   128
#define LMAX  60000
#define CMAX  30000
#define EMAX  360000
#define NITER 8

// ---------------- scratch (device globals; no allocations allowed) ----------
__device__ float g_l2c_msg[(size_t)LMAX * DIM];
__device__ float g_c2l_msg[(size_t)CMAX * DIM];
__device__ float g_l2l_msg[(size_t)LMAX * DIM];
__device__ float g_aggr_c [(size_t)CMAX * DIM];
__device__ float g_aggr_l [(size_t)LMAX * DIM];
__device__ float g_rz_c   [(size_t)CMAX * 2 * DIM];
__device__ float g_n_c    [(size_t)CMAX * 2 * DIM];
__device__ float g_rz_l   [(size_t)LMAX * 2 * DIM];
__device__ float g_n_l    [(size_t)LMAX * 2 * DIM];
// CSR scratch
__device__ int g_cnt_c[CMAX];
__device__ int g_cnt_l[LMAX];
__device__ int g_off_c[CMAX + 1];
__device__ int g_off_l[LMAX + 1];
__device__ int g_cur_c[CMAX];
__device__ int g_cur_l[LMAX];
__device__ int g_src_c[EMAX];
__device__ int g_src_l[EMAX];
// pre-split bf16 weight planes (u32 = 2 bf16), fragment-ordered
#define WSPLIT_TOTAL 172032
__device__ uint32_t g_whi[WSPLIT_TOTAL];
__device__ uint32_t g_wlo[WSPLIT_TOTAL];

// ======================= helpers =============================================
__device__ __forceinline__ uint32_t smem_u32(const void* p) {
    uint32_t a;
    asm("{ .reg .u64 t; cvta.to.shared.u64 t, %1; cvt.u32.u64 %0, t; }"
        : "=r"(a) : "l"(p));
    return a;
}

__device__ __forceinline__ uint32_t pack_bf16(float lo, float hi) {
    uint32_t r;
    asm("cvt.rn.bf16x2.f32 %0, %1, %2;" : "=r"(r) : "f"(hi), "f"(lo));
    return r;
}

__device__ __forceinline__ void split2(float x, float y, uint32_t& hi, uint32_t& lo) {
    uint32_t h = pack_bf16(x, y);
    float hx = __uint_as_float(h << 16);
    float hy = __uint_as_float(h & 0xffff0000u);
    hi = h;
    lo = pack_bf16(x - hx, y - hy);
}

__device__ __forceinline__ void cp16(uint32_t dst, const void* src) {
    asm volatile("cp.async.ca.shared.global [%0], [%1], 16;"
                 :: "r"(dst), "l"(src) : "memory");
}
#define CP_COMMIT() asm volatile("cp.async.commit_group;" ::: "memory")
#define CP_WAIT0()  asm volatile("cp.async.wait_group 0;" ::: "memory")
#define CP_WAIT1()  asm volatile("cp.async.wait_group 1;" ::: "memory")

__device__ __forceinline__ void mma_bf16(float* d, const uint32_t* a,
                                         uint32_t b0, uint32_t b1) {
    asm volatile(
        "mma.sync.aligned.m16n8k16.row.col.f32.bf16.bf16.f32 "
        "{%0,%1,%2,%3}, {%4,%5,%6,%7}, {%8,%9}, {%0,%1,%2,%3};"
        : "+f"(d[0]), "+f"(d[1]), "+f"(d[2]), "+f"(d[3])
        : "r"(a[0]), "r"(a[1]), "r"(a[2]), "r"(a[3]), "r"(b0), "r"(b1));
}

#define IDX(r, q) ((((r) << 3)) | ((q) ^ ((r) & 7)))

__device__ __forceinline__ float fsigmoid(float x) { return 1.f / (1.f + __expf(-x)); }
__device__ __forceinline__ float ftanh(float x) {
    float t = __expf(2.f * fabsf(x));
    float r = 1.f - 2.f / (t + 1.f);
    return copysignf(r, x);
}

// ======================= weight pre-split (fragment-ordered) =================
__global__ void split_w(const float* __restrict__ W, uint32_t* __restrict__ hi,
                        uint32_t* __restrict__ lo, int total_pairs, int kp)
{
    int i = blockIdx.x * 256 + threadIdx.x;
    if (i >= total_pairs) return;
    int R = i / kp, p = i - R * kp;
    float2 f = ((const float2*)W)[i];
    uint32_t h, l;
    split2(f.x, f.y, h, l);
    int ngroup = R >> 7, n = R & 127;
    int ch = p >> 3, q = p & 7;
    int nt = n >> 3, l4 = n & 7;
    int region = l4 * 4 + (q & 3);
    int idx = region * 32 + (((nt >> 1) ^ (region & 7)) << 2) + ((nt & 1) << 1) + (q >> 2);
    size_t base = ((size_t)(ngroup * (kp >> 3) + ch)) << 10;
    hi[base + idx] = h;
    lo[base + idx] = l;
}

// ======================= MMA chunk ===========================================
// A: [Ah 1024][Al 1024]; B: [Bh 1024][Bl 1024]. Interleaved chains (RAW dist 2).
__device__ __forceinline__ void mma_chunk(const uint32_t* __restrict__ A,
                                          const uint32_t* __restrict__ B,
                                          float (&acc)[16][4], int lane, int wid)
{
    const uint32_t* Ah = A;
    const uint32_t* Al = A + 1024;
    const int r = wid * 16 + (lane >> 2);
    const int q = lane & 3;
    uint32_t ah[4], al[4];
    ah[0] = Ah[IDX(r, q)];     ah[1] = Ah[IDX(r + 8, q)];
    ah[2] = Ah[IDX(r, q + 4)]; ah[3] = Ah[IDX(r + 8, q + 4)];
    al[0] = Al[IDX(r, q)];     al[1] = Al[IDX(r + 8, q)];
    al[2] = Al[IDX(r, q + 4)]; al[3] = Al[IDX(r + 8, q + 4)];
    const uint32_t* Bh = B + lane * 32;
    const uint32_t* Bl = Bh + 1024;
#pragma unroll
    for (int c = 0; c < 8; c++) {
        const int sw = ((c ^ (lane & 7)) << 2);
        uint4 vh = *(const uint4*)(Bh + sw);
        uint4 vl = *(const uint4*)(Bl + sw);
        mma_bf16(acc[2 * c],     ah, vh.x, vh.y);
        mma_bf16(acc[2 * c + 1], ah, vh.z, vh.w);
        mma_bf16(acc[2 * c],     al, vh.x, vh.y);
        mma_bf16(acc[2 * c + 1], al, vh.z, vh.w);
        mma_bf16(acc[2 * c],     ah, vl.x, vl.y);
        mma_bf16(acc[2 * c + 1], ah, vl.z, vl.w);
    }
}

// ======================= fused 2-layer MLP (occ 2) ===========================
#define MLP2_DSMEM (22528 * 4)

__global__ __launch_bounds__(256, 2)
void mlp2_bf3(const float* __restrict__ A0,
              const uint32_t* __restrict__ W0h, const uint32_t* __restrict__ W0l,
              const float* __restrict__ b0,
              const uint32_t* __restrict__ W1h, const uint32_t* __restrict__ W1l,
              const float* __restrict__ b1,
              float* __restrict__ out, int N, int perm)
{
    extern __shared__ __align__(16) uint32_t sm[];
    __shared__ float sb0[128];

    const int t = threadIdx.x, lane = t & 31, wid = t >> 5;
    const int m0 = blockIdx.x * 128;

    if (t < 128) sb0[t] = b0[t];

    float acc1[16][4];
#pragma unroll
    for (int i = 0; i < 16; i++)
#pragma unroll
        for (int j = 0; j < 4; j++) acc1[i][j] = 0.f;

    const int arow_l = t >> 1;
    const int afl = (t & 1) * 8;
    const int grow = m0 + arow_l;
    int arow = (perm ? (grow ^ 1) : grow);
    if (grow >= N) arow = 0;
    float4 ra0, ra1;

    const int wrow = t & 127;
    const int wpl = t >> 7;
    const uint32_t* w0p = wpl ? W0l : W0h;
    const uint32_t* w1p = wpl ? W1l : W1h;

#define LDA1(ch) do { \
        const float* p = A0 + (size_t)arow * 128 + ((ch) << 4) + afl; \
        ra0 = *(const float4*)p; ra1 = *(const float4*)(p + 4); \
    } while (0)
#define STA1(buf) do { \
        uint32_t* Ah = sm + (buf) * 4096; \
        uint32_t* Al = Ah + 1024; \
        uint32_t h0, l0; \
        split2(ra0.x, ra0.y, h0, l0); Ah[IDX(arow_l, (afl >> 1) + 0)] = h0; Al[IDX(arow_l, (afl >> 1) + 0)] = l0; \
        split2(ra0.z, ra0.w, h0, l0); Ah[IDX(arow_l, (afl >> 1) + 1)] = h0; Al[IDX(arow_l, (afl >> 1) + 1)] = l0; \
        split2(ra1.x, ra1.y, h0, l0); Ah[IDX(arow_l, (afl >> 1) + 2)] = h0; Al[IDX(arow_l, (afl >> 1) + 2)] = l0; \
        split2(ra1.z, ra1.w, h0, l0); Ah[IDX(arow_l, (afl >> 1) + 3)] = h0; Al[IDX(arow_l, (afl >> 1) + 3)] = l0; \
    } while (0)
#define CPW1(wb, ch, buf) do { \
        const uint32_t* gp = (wb) + ((size_t)(ch) << 10) + wrow * 8; \
        uint32_t daddr = smem_u32(sm + (buf) * 4096 + (2 + wpl) * 1024 + wrow * 8); \
        cp16(daddr, gp); cp16(daddr + 16, gp + 4); \
    } while (0)
#define CPW2(ch, buf) do { \
        const uint32_t* gp = w1p + ((size_t)(ch) << 10) + wrow * 8; \
        uint32_t daddr = smem_u32(sm + 16384 + (buf) * 2048 + wpl * 1024 + wrow * 8); \
        cp16(daddr, gp); cp16(daddr + 16, gp + 4); \
    } while (0)

    // ---- stage 1 ----
    LDA1(0); CPW1(w0p, 0, 0); CP_COMMIT(); STA1(0);
    LDA1(1); CPW1(w0p, 1, 1); CP_COMMIT(); STA1(1); CP_WAIT1();
    __syncthreads();
    for (int ch = 0; ch < 8; ch++) {
        const uint32_t* sb = sm + (ch % 3) * 4096;
        mma_chunk(sb, sb + 2048, acc1, lane, wid);
        if (ch + 1 < 8) {
            if (ch + 2 < 8) {
                LDA1(ch + 2); CPW1(w0p, ch + 2, (ch + 2) % 3); CP_COMMIT();
                STA1((ch + 2) % 3);
                CP_WAIT1();
            } else CP_WAIT0();
            __syncthreads();
        }
    }
    __syncthreads();

    // ---- bias + relu, spill stage-1 result into A region (pre-split) ----
    {
        const int rlo = wid * 16 + (lane >> 2);
        const int rhi = rlo + 8;
#pragma unroll
        for (int nt = 0; nt < 16; nt++) {
            const int col = nt * 8 + 2 * (lane & 3);
            float bx = sb0[col], by = sb0[col + 1];
            float v0 = fmaxf(acc1[nt][0] + bx, 0.f);
            float v1 = fmaxf(acc1[nt][1] + by, 0.f);
            float v2 = fmaxf(acc1[nt][2] + bx, 0.f);
            float v3 = fmaxf(acc1[nt][3] + by, 0.f);
            const int ch = nt >> 1;
            const int q = (nt & 1) * 4 + (lane & 3);
            uint32_t h, l;
            split2(v0, v1, h, l);
            sm[ch * 2048 + IDX(rlo, q)] = h;
            sm[ch * 2048 + 1024 + IDX(rlo, q)] = l;
            split2(v2, v3, h, l);
            sm[ch * 2048 + IDX(rhi, q)] = h;
            sm[ch * 2048 + 1024 + IDX(rhi, q)] = l;
        }
    }
    __syncthreads();

    float acc2[16][4];
#pragma unroll
    for (int i = 0; i < 16; i++)
#pragma unroll
        for (int j = 0; j < 4; j++) acc2[i][j] = 0.f;

    // ---- stage 2 ----
    CPW2(0, 0); CP_COMMIT();
    CPW2(1, 1); CP_COMMIT(); CP_WAIT1();
    __syncthreads();
    for (int ch = 0; ch < 8; ch++) {
        mma_chunk(sm + ch * 2048, sm + 16384 + (ch % 3) * 2048, acc2, lane, wid);
        if (ch + 1 < 8) {
            if (ch + 2 < 8) { CPW2(ch + 2, (ch + 2) % 3); CP_COMMIT(); CP_WAIT1(); }
            else CP_WAIT0();
            __syncthreads();
        }
    }

    const int r0 = m0 + wid * 16 + (lane >> 2);
#pragma unroll
    for (int nt = 0; nt < 16; nt++) {
        const int col = nt * 8 + 2 * (lane & 3);
        float bx = b1[col], by = b1[col + 1];
        if (r0 < N)
            *(float2*)(out + (size_t)r0 * 128 + col) =
                make_float2(acc2[nt][0] + bx, acc2[nt][1] + by);
        if (r0 + 8 < N)
            *(float2*)(out + (size_t)(r0 + 8) * 128 + col) =
                make_float2(acc2[nt][2] + bx, acc2[nt][3] + by);
    }
#undef LDA1
#undef STA1
#undef CPW1
#undef CPW2
}

// ======================= GRU gate GEMMs ======================================
// gemm_rz: grid (gx, 2). For gate g = blockIdx.y (0=r, 1=z):
//   rz[node, g*128 + c] = sigmoid( concat(S0,S1,h) @ (Wih_g ++ Whh_g)^T + bih_g + bhh_g )
__global__ __launch_bounds__(256, 2)
void gemm_rz(const float* __restrict__ S0, const float* __restrict__ S1,
             int n0, int n1,
             const uint32_t* __restrict__ Wih_h, const uint32_t* __restrict__ Wih_l,
             const uint32_t* __restrict__ Whh_h, const uint32_t* __restrict__ Whh_l,
             const float* __restrict__ bih, const float* __restrict__ bhh,
             const float* __restrict__ hprev, float* __restrict__ rz, int N)
{
    __shared__ __align__(16) uint32_t sm[3 * 4096];

    const int t = threadIdx.x, lane = t & 31, wid = t >> 5;
    const int m0 = blockIdx.x * 128;
    const int g  = blockIdx.y;
    const int nchi = n0 + n1;
    const int nch = nchi + 8;

    float acc[16][4];
#pragma unroll
    for (int i = 0; i < 16; i++)
#pragma unroll
        for (int j = 0; j < 4; j++) acc[i][j] = 0.f;

    const int arow_l = t >> 1;
    const int afl = (t & 1) * 8;
    int arow = m0 + arow_l;
    if (arow >= N) arow = 0;
    float4 ra0, ra1;

    const int wrow = t & 127;
    const int wpl = t >> 7;
    const uint32_t* pih = wpl ? Wih_l : Wih_h;
    const uint32_t* phh = wpl ? Whh_l : Whh_h;

#define LDA(ch) do { \
        const float* src; int col; \
        if ((ch) < n0)            { src = S0;   col = (ch) << 4; } \
        else if ((ch) < nchi)     { src = S1;   col = ((ch) - n0) << 4; } \
        else                      { src = hprev; col = ((ch) - nchi) << 4; } \
        const float* p = src + (size_t)arow * 128 + col + afl; \
        ra0 = *(const float4*)p; ra1 = *(const float4*)(p + 4); \
    } while (0)
#define STA(buf) do { \
        uint32_t* Ah = sm + (buf) * 4096; \
        uint32_t* Al = Ah + 1024; \
        uint32_t h0, l0; \
        split2(ra0.x, ra0.y, h0, l0); Ah[IDX(arow_l, (afl >> 1) + 0)] = h0; Al[IDX(arow_l, (afl >> 1) + 0)] = l0; \
        split2(ra0.z, ra0.w, h0, l0); Ah[IDX(arow_l, (afl >> 1) + 1)] = h0; Al[IDX(arow_l, (afl >> 1) + 1)] = l0; \
        split2(ra1.x, ra1.y, h0, l0); Ah[IDX(arow_l, (afl >> 1) + 2)] = h0; Al[IDX(arow_l, (afl >> 1) + 2)] = l0; \
        split2(ra1.z, ra1.w, h0, l0); Ah[IDX(arow_l, (afl >> 1) + 3)] = h0; Al[IDX(arow_l, (afl >> 1) + 3)] = l0; \
    } while (0)
#define CPW(ch, buf) do { \
        const uint32_t* gp = ((ch) < nchi) \
            ? pih + (((size_t)(g * nchi + (ch))) << 10) + wrow * 8 \
            : phh + (((size_t)(g * 8 + (ch) - nchi)) << 10) + wrow * 8; \
        uint32_t daddr = smem_u32(sm + (buf) * 4096 + (2 + wpl) * 1024 + wrow * 8); \
        cp16(daddr, gp); cp16(daddr + 16, gp + 4); \
    } while (0)

    LDA(0); CPW(0, 0); CP_COMMIT(); STA(0);
    LDA(1); CPW(1, 1); CP_COMMIT(); STA(1); CP_WAIT1();
    __syncthreads();
    for (int ch = 0; ch < nch; ch++) {
        const uint32_t* sb = sm + (ch % 3) * 4096;
        mma_chunk(sb, sb + 2048, acc, lane, wid);
        if (ch + 1 < nch) {
            if (ch + 2 < nch) {
                LDA(ch + 2); CPW(ch + 2, (ch + 2) % 3); CP_COMMIT();
                STA((ch + 2) % 3);
                CP_WAIT1();
            } else CP_WAIT0();
            __syncthreads();
        }
    }

    const int r0 = m0 + wid * 16 + (lane >> 2);
#pragma unroll
    for (int nt = 0; nt < 16; nt++) {
        const int col = nt * 8 + 2 * (lane & 3);
        float bx = bih[g * 128 + col]     + bhh[g * 128 + col];
        float by = bih[g * 128 + col + 1] + bhh[g * 128 + col + 1];
        if (r0 < N)
            *(float2*)(rz + (size_t)r0 * 256 + g * 128 + col) =
                make_float2(fsigmoid(acc[nt][0] + bx), fsigmoid(acc[nt][1] + by));
        if (r0 + 8 < N)
            *(float2*)(rz + (size_t)(r0 + 8) * 256 + g * 128 + col) =
                make_float2(fsigmoid(acc[nt][2] + bx), fsigmoid(acc[nt][3] + by));
    }
#undef LDA
#undef STA
#undef CPW
}

// gemm_n: grid (gx, 2). y=0: n_i = gi_n + bih_n (K=nchi*16); y=1: n_h = gh_n + bhh_n (K=128)
__global__ __launch_bounds__(256, 2)
void gemm_n(const float* __restrict__ S0, const float* __restrict__ S1,
            int n0, int n1,
            const uint32_t* __restrict__ Wih_h, const uint32_t* __restrict__ Wih_l,
            const uint32_t* __restrict__ Whh_h, const uint32_t* __restrict__ Whh_l,
            const float* __restrict__ bih, const float* __restrict__ bhh,
            const float* __restrict__ hprev, float* __restrict__ nbuf, int N)
{
    __shared__ __align__(16) uint32_t sm[3 * 4096];

    const int t = threadIdx.x, lane = t & 31, wid = t >> 5;
    const int m0 = blockIdx.x * 128;
    const int g  = blockIdx.y;       // 0: input part, 1: hidden part
    const int nchi = n0 + n1;
    const int nch = g ? 8 : nchi;

    float acc[16][4];
#pragma unroll
    for (int i = 0; i < 16; i++)
#pragma unroll
        for (int j = 0; j < 4; j++) acc[i][j] = 0.f;

    const int arow_l = t >> 1;
    const int afl = (t & 1) * 8;
    int arow = m0 + arow_l;
    if (arow >= N) arow = 0;
    float4 ra0, ra1;

    const int wrow = t & 127;
    const int wpl = t >> 7;
    const uint32_t* pih = wpl ? Wih_l : Wih_h;
    const uint32_t* phh = wpl ? Whh_l : Whh_h;

#define LDA(ch) do { \
        const float* src; int col; \
        if (g) { src = hprev; col = (ch) << 4; } \
        else if ((ch) < n0) { src = S0; col = (ch) << 4; } \
        else { src = S1; col = ((ch) - n0) << 4; } \
        const float* p = src + (size_t)arow * 128 + col + afl; \
        ra0 = *(const float4*)p; ra1 = *(const float4*)(p + 4); \
    } while (0)
#define STA(buf) do { \
        uint32_t* Ah = sm + (buf) * 4096; \
        uint32_t* Al = Ah + 1024; \
        uint32_t h0, l0; \
        split2(ra0.x, ra0.y, h0, l0); Ah[IDX(arow_l, (afl >> 1) + 0)] = h0; Al[IDX(arow_l, (afl >> 1) + 0)] = l0; \
        split2(ra0.z, ra0.w, h0, l0); Ah[IDX(arow_l, (afl >> 1) + 1)] = h0; Al[IDX(arow_l, (afl >> 1) + 1)] = l0; \
        split2(ra1.x, ra1.y, h0, l0); Ah[IDX(arow_l, (afl >> 1) + 2)] = h0; Al[IDX(arow_l, (afl >> 1) + 2)] = l0; \
        split2(ra1.z, ra1.w, h0, l0); Ah[IDX(arow_l, (afl >> 1) + 3)] = h0; Al[IDX(arow_l, (afl >> 1) + 3)] = l0; \
    } while (0)
#define CPW(ch, buf) do { \
        const uint32_t* gp = g \
            ? phh + (((size_t)(16 + (ch))) << 10) + wrow * 8 \
            : pih + (((size_t)(2 * nchi + (ch))) << 10) + wrow * 8; \
        uint32_t daddr = smem_u32(sm + (buf) * 4096 + (2 + wpl) * 1024 + wrow * 8); \
        cp16(daddr, gp); cp16(daddr + 16, gp + 4); \
    } while (0)

    LDA(0); CPW(0, 0); CP_COMMIT(); STA(0);
    if (nch > 1) { LDA(1); CPW(1, 1); CP_COMMIT(); STA(1); CP_WAIT1(); }
    else CP_WAIT0();
    __syncthreads();
    for (int ch = 0; ch < nch; ch++) {
        const uint32_t* sb = sm + (ch % 3) * 4096;
        mma_chunk(sb, sb + 2048, acc, lane, wid);
        if (ch + 1 < nch) {
            if (ch + 2 < nch) {
                LDA(ch + 2); CPW(ch + 2, (ch + 2) % 3); CP_COMMIT();
                STA((ch + 2) % 3);
                CP_WAIT1();
            } else CP_WAIT0();
            __syncthreads();
        }
    }

    const float* bsrc = g ? bhh : bih;
    const int r0 = m0 + wid * 16 + (lane >> 2);
#pragma unroll
    for (int nt = 0; nt < 16; nt++) {
        const int col = nt * 8 + 2 * (lane & 3);
        float bx = bsrc[256 + col], by = bsrc[256 + col + 1];
        if (r0 < N)
            *(float2*)(nbuf + (size_t)r0 * 256 + g * 128 + col) =
                make_float2(acc[nt][0] + bx, acc[nt][1] + by);
        if (r0 + 8 < N)
            *(float2*)(nbuf + (size_t)(r0 + 8) * 256 + g * 128 + col) =
                make_float2(acc[nt][2] + bx, acc[nt][3] + by);
    }
#undef LDA
#undef STA
#undef CPW
}

// ======================= CSR build ===========================================
__global__ void hist2(const int* __restrict__ l_e, const int* __restrict__ c_e,
                      int* __restrict__ cnt_l, int* __restrict__ cnt_c, int E)
{
    int i = blockIdx.x * blockDim.x + threadIdx.x;
    if (i < E) {
        atomicAdd(&cnt_l[l_e[i]], 1);
        atomicAdd(&cnt_c[c_e[i]], 1);
    }
}

__global__ void exscan(const int* __restrict__ cnt, int* __restrict__ off, int n)
{
    __shared__ int part[1024];
    const int t = threadIdx.x;
    const int chunk = (n + 1023) >> 10;
    const int b = t * chunk;
    const int e = min(b + chunk, n);
    int s = 0;
    for (int i = b; i < e; i++) s += cnt[i];
    part[t] = s;
    __syncthreads();
    for (int d = 1; d < 1024; d <<= 1) {
        int v = (t >= d) ? part[t - d] : 0;
        __syncthreads();
        if (t >= d) part[t] += v;
        __syncthreads();
    }
    int run = (t == 0) ? 0 : part[t - 1];
    for (int i = b; i < e; i++) { off[i] = run; run += cnt[i]; }
    if (t == 0) off[n] = part[1023];
}

__global__ void fill2(const int* __restrict__ l_e, const int* __restrict__ c_e,
                      int* __restrict__ cur_l, int* __restrict__ cur_c,
                      int* __restrict__ src_l, int* __restrict__ src_c, int E)
{
    int i = blockIdx.x * blockDim.x + threadIdx.x;
    if (i < E) {
        int l = l_e[i], c = c_e[i];
        src_c[atomicAdd(&cur_c[c], 1)] = l;
        src_l[atomicAdd(&cur_l[l], 1)] = c;
    }
}

// ======================= gather-sum ==========================================
__global__ __launch_bounds__(256)
void gather(const float* __restrict__ msg, const int* __restrict__ off,
            const int* __restrict__ srcs, float* __restrict__ aggr, int n)
{
    int node = blockIdx.x * 8 + (threadIdx.x >> 5);
    if (node >= n) return;
    int lane = threadIdx.x & 31;
    int b = off[node], e = off[node + 1];
    float4 acc = {0.f, 0.f, 0.f, 0.f};
    for (int i = b; i < e; i++) {
        const float4 v = *((const float4*)(msg + (size_t)srcs[i] * DIM) + lane);
        acc.x += v.x; acc.y += v.y; acc.z += v.z; acc.w += v.w;
    }
    *((float4*)(aggr + (size_t)node * DIM) + lane) = acc;
}

// ---------------- GRU elementwise (reduced traffic) ---------------------------
__global__ void gru_elem2(const float* __restrict__ rz, const float* __restrict__ nbuf,
                          const float* __restrict__ h, float* __restrict__ hnew, int N)
{
    int idx = blockIdx.x * blockDim.x + threadIdx.x;
    if (idx >= N * 32) return;            // float4 granularity
    int row = idx >> 5, c4 = (idx & 31) * 4;
    const float4 r4 = *(const float4*)(rz + (size_t)row * 256 + c4);
    const float4 z4 = *(const float4*)(rz + (size_t)row * 256 + 128 + c4);
    const float4 ni = *(const float4*)(nbuf + (size_t)row * 256 + c4);
    const float4 nh = *(const float4*)(nbuf + (size_t)row * 256 + 128 + c4);
    const float4 h4 = *(const float4*)(h + (size_t)row * 128 + c4);
    float4 o;
    o.x = (1.f - z4.x) * ftanh(ni.x + r4.x * nh.x) + z4.x * h4.x;
    o.y = (1.f - z4.y) * ftanh(ni.y + r4.y * nh.y) + z4.y * h4.y;
    o.z = (1.f - z4.z) * ftanh(ni.z + r4.z * nh.z) + z4.z * h4.z;
    o.w = (1.f - z4.w) * ftanh(ni.w + r4.w * nh.w) + z4.w * h4.w;
    *(float4*)(hnew + (size_t)row * 128 + c4) = o;
}

// ---------------- launch ------------------------------------------------------
extern "C" void kernel_launch(void* const* d_in, const int* in_sizes, int n_in,
                              void* d_out, int out_size)
{
    const int D = DIM;
    const int E = in_sizes[2];
    const int L = in_sizes[4] / D;
    const int C = in_sizes[5] / D;

    const int*   l_edge = (const int*)d_in[2];
    const int*   c_edge = (const int*)d_in[3];
    const float* l_emb0 = (const float*)d_in[4];
    const float* c_emb0 = (const float*)d_in[5];

    const float* l2c_W0 = (const float*)d_in[6];
    const float* l2c_b0 = (const float*)d_in[7];
    const float* l2c_W1 = (const float*)d_in[8];
    const float* l2c_b1 = (const float*)d_in[9];
    const float* c2l_W0 = (const float*)d_in[10];
    const float* c2l_b0 = (const float*)d_in[11];
    const float* c2l_W1 = (const float*)d_in[12];
    const float* c2l_b1 = (const float*)d_in[13];
    const float* l2l_W0 = (const float*)d_in[14];
    const float* l2l_b0 = (const float*)d_in[15];
    const float* l2l_W1 = (const float*)d_in[16];
    const float* l2l_b1 = (const float*)d_in[17];
    const float* c_Wih  = (const float*)d_in[18];
    const float* c_Whh  = (const float*)d_in[19];
    const float* c_bih  = (const float*)d_in[20];
    const float* c_bhh  = (const float*)d_in[21];
    const float* l_Wih  = (const float*)d_in[22];
    const float* l_Whh  = (const float*)d_in[23];
    const float* l_bih  = (const float*)d_in[24];
    const float* l_bhh  = (const float*)d_in[25];

    float* out   = (float*)d_out;
    float* louts = out;                                // [9, L, D]
    float* couts = out + (size_t)(NITER + 1) * L * D;  // [9, C, D]

    float *l2c_msg, *c2l_msg, *l2l_msg, *aggr_c, *aggr_l, *rz_c, *n_c, *rz_l, *n_l;
    cudaGetSymbolAddress((void**)&l2c_msg, g_l2c_msg);
    cudaGetSymbolAddress((void**)&c2l_msg, g_c2l_msg);
    cudaGetSymbolAddress((void**)&l2l_msg, g_l2l_msg);
    cudaGetSymbolAddress((void**)&aggr_c,  g_aggr_c);
    cudaGetSymbolAddress((void**)&aggr_l,  g_aggr_l);
    cudaGetSymbolAddress((void**)&rz_c,    g_rz_c);
    cudaGetSymbolAddress((void**)&n_c,     g_n_c);
    cudaGetSymbolAddress((void**)&rz_l,    g_rz_l);
    cudaGetSymbolAddress((void**)&n_l,     g_n_l);

    int *cnt_c, *cnt_l, *off_c, *off_l, *cur_c, *cur_l, *src_c, *src_l;
    cudaGetSymbolAddress((void**)&cnt_c, g_cnt_c);
    cudaGetSymbolAddress((void**)&cnt_l, g_cnt_l);
    cudaGetSymbolAddress((void**)&off_c, g_off_c);
    cudaGetSymbolAddress((void**)&off_l, g_off_l);
    cudaGetSymbolAddress((void**)&cur_c, g_cur_c);
    cudaGetSymbolAddress((void**)&cur_l, g_cur_l);
    cudaGetSymbolAddress((void**)&src_c, g_src_c);
    cudaGetSymbolAddress((void**)&src_l, g_src_l);

    uint32_t *whi, *wlo;
    cudaGetSymbolAddress((void**)&whi, g_whi);
    cudaGetSymbolAddress((void**)&wlo, g_wlo);

    cudaFuncSetAttribute(mlp2_bf3, cudaFuncAttributeMaxDynamicSharedMemorySize,
                         MLP2_DSMEM);

    const int o_l2c0 = 0,      o_l2c1 = 8192,  o_c2l0 = 16384, o_c2l1 = 24576;
    const int o_l2l0 = 32768,  o_l2l1 = 40960;
    const int o_cih  = 49152,  o_chh  = 73728;
    const int o_lih  = 98304,  o_lhh  = 147456;

    // ---- pre-split weights into fragment-ordered bf16 hi/lo planes ----
    split_w<<<32, 256>>>(l2c_W0, whi + o_l2c0, wlo + o_l2c0, 8192, 64);
    split_w<<<32, 256>>>(l2c_W1, whi + o_l2c1, wlo + o_l2c1, 8192, 64);
    split_w<<<32, 256>>>(c2l_W0, whi + o_c2l0, wlo + o_c2l0, 8192, 64);
    split_w<<<32, 256>>>(c2l_W1, whi + o_c2l1, wlo + o_c2l1, 8192, 64);
    split_w<<<32, 256>>>(l2l_W0, whi + o_l2l0, wlo + o_l2l0, 8192, 64);
    split_w<<<32, 256>>>(l2l_W1, whi + o_l2l1, wlo + o_l2l1, 8192, 64);
    split_w<<<96, 256>>>(c_Wih,  whi + o_cih,  wlo + o_cih,  24576, 64);
    split_w<<<96, 256>>>(c_Whh,  whi + o_chh,  wlo + o_chh,  24576, 64);
    split_w<<<192, 256>>>(l_Wih, whi + o_lih,  wlo + o_lih,  49152, 128);
    split_w<<<96, 256>>>(l_Whh,  whi + o_lhh,  wlo + o_lhh,  24576, 64);

    // ---- CSR build (edge structure static across iterations) ----
    cudaMemsetAsync(cnt_c, 0, (size_t)C * sizeof(int));
    cudaMemsetAsync(cnt_l, 0, (size_t)L * sizeof(int));
    hist2<<<(E + 255) / 256, 256>>>(l_edge, c_edge, cnt_l, cnt_c, E);
    exscan<<<1, 1024>>>(cnt_c, off_c, C);
    exscan<<<1, 1024>>>(cnt_l, off_l, L);
    cudaMemcpyAsync(cur_c, off_c, (size_t)C * sizeof(int), cudaMemcpyDeviceToDevice);
    cudaMemcpyAsync(cur_l, off_l, (size_t)L * sizeof(int), cudaMemcpyDeviceToDevice);
    fill2<<<(E + 255) / 256, 256>>>(l_edge, c_edge, cur_l, cur_c, src_l, src_c, E);

    // iteration-0 slices = inputs
    cudaMemcpyAsync(louts, l_emb0, (size_t)L * D * sizeof(float), cudaMemcpyDeviceToDevice);
    cudaMemcpyAsync(couts, c_emb0, (size_t)C * D * sizeof(float), cudaMemcpyDeviceToDevice);

    const int gLx = (L + 127) / 128;
    const int gCx = (C + 127) / 128;
    const dim3 gC2(gCx, 2), gL2(gLx, 2);

    for (int it = 0; it < NITER; it++) {
        const float* l_prev = louts + (size_t)it * L * D;
        const float* c_prev = couts + (size_t)it * C * D;
        float* l_next = louts + (size_t)(it + 1) * L * D;
        float* c_next = couts + (size_t)(it + 1) * C * D;

        // message MLPs (fused 2-layer)
        mlp2_bf3<<<gLx, 256, MLP2_DSMEM>>>(l_prev, whi + o_l2c0, wlo + o_l2c0, l2c_b0,
                                           whi + o_l2c1, wlo + o_l2c1, l2c_b1, l2c_msg, L, 0);
        mlp2_bf3<<<gCx, 256, MLP2_DSMEM>>>(c_prev, whi + o_c2l0, wlo + o_c2l0, c2l_b0,
                                           whi + o_c2l1, wlo + o_c2l1, c2l_b1, c2l_msg, C, 0);
        mlp2_bf3<<<gLx, 256, MLP2_DSMEM>>>(l_prev, whi + o_l2l0, wlo + o_l2l0, l2l_b0,
                                           whi + o_l2l1, wlo + o_l2l1, l2l_b1, l2l_msg, L, 1);

        // clause side (gi K = 128 -> n0=8, n1=0)
        gather<<<(C + 7) / 8, 256>>>(l2c_msg, off_c, src_c, aggr_c, C);
        gemm_rz<<<gC2, 256>>>(aggr_c, nullptr, 8, 0,
                              whi + o_cih, wlo + o_cih, whi + o_chh, wlo + o_chh,
                              c_bih, c_bhh, c_prev, rz_c, C);
        gemm_n<<<gC2, 256>>>(aggr_c, nullptr, 8, 0,
                             whi + o_cih, wlo + o_cih, whi + o_chh, wlo + o_chh,
                             c_bih, c_bhh, c_prev, n_c, C);
        gru_elem2<<<(C * 32 + 255) / 256, 256>>>(rz_c, n_c, c_prev, c_next, C);

        // literal side (gi = concat(aggr_l, l2l_msg), n0=n1=8)
        gather<<<(L + 7) / 8, 256>>>(c2l_msg, off_l, src_l, aggr_l, L);
        gemm_rz<<<gL2, 256>>>(aggr_l, l2l_msg, 8, 8,
                              whi + o_lih, wlo + o_lih, whi + o_lhh, wlo + o_lhh,
                              l_bih, l_bhh, l_prev, rz_l, L);
        gemm_n<<<gL2, 256>>>(aggr_l, l2l_msg, 8, 8,
                             whi + o_lih, wlo + o_lih, whi + o_lhh, wlo + o_lhh,
                             l_bih, l_bhh, l_prev, n_l, L);
        gru_elem2<<<(L * 32 + 255) / 256, 256>>>(rz_l, n_l, l_prev, l_next, L);
    }
}

// round 11
// speedup vs baseline: 1.1780x; 1.1780x over previous
#include <cuda_runtime.h>
#include <cuda_bf16.h>
#include <cstdint>

// Problem constants (fixed by setup_inputs)
#define DIM   128
#define LMAX  60000
#define CMAX  30000
#define EMAX  360000
#define NITER 8

// ---------------- scratch (device globals; no allocations allowed) ----------
__device__ float g_l2c_msg[(size_t)LMAX * DIM];
__device__ float g_c2l_msg[(size_t)CMAX * DIM];
__device__ float g_l2l_msg[(size_t)LMAX * DIM];
__device__ float g_aggr_c [(size_t)CMAX * DIM];
__device__ float g_aggr_l [(size_t)LMAX * DIM];
__device__ float g_rz_c   [(size_t)CMAX * 2 * DIM];
__device__ float g_n_c    [(size_t)CMAX * 2 * DIM];
__device__ float g_rz_l   [(size_t)LMAX * 2 * DIM];
__device__ float g_n_l    [(size_t)LMAX * 2 * DIM];
// CSR scratch
__device__ int g_cnt_c[CMAX];
__device__ int g_cnt_l[LMAX];
__device__ int g_off_c[CMAX + 1];
__device__ int g_off_l[LMAX + 1];
__device__ int g_cur_c[CMAX];
__device__ int g_cur_l[LMAX];
__device__ int g_src_c[EMAX];
__device__ int g_src_l[EMAX];
// pre-split bf16 weight planes (u32 = 2 bf16), fragment-ordered
#define WSPLIT_TOTAL 172032
__device__ uint32_t g_whi[WSPLIT_TOTAL];
__device__ uint32_t g_wlo[WSPLIT_TOTAL];

// ======================= helpers =============================================
__device__ __forceinline__ uint32_t smem_u32(const void* p) {
    uint32_t a;
    asm("{ .reg .u64 t; cvta.to.shared.u64 t, %1; cvt.u32.u64 %0, t; }"
        : "=r"(a) : "l"(p));
    return a;
}

__device__ __forceinline__ uint32_t pack_bf16(float lo, float hi) {
    uint32_t r;
    asm("cvt.rn.bf16x2.f32 %0, %1, %2;" : "=r"(r) : "f"(hi), "f"(lo));
    return r;
}

__device__ __forceinline__ void split2(float x, float y, uint32_t& hi, uint32_t& lo) {
    uint32_t h = pack_bf16(x, y);
    float hx = __uint_as_float(h << 16);
    float hy = __uint_as_float(h & 0xffff0000u);
    hi = h;
    lo = pack_bf16(x - hx, y - hy);
}

__device__ __forceinline__ void cp16(uint32_t dst, const void* src) {
    asm volatile("cp.async.ca.shared.global [%0], [%1], 16;"
                 :: "r"(dst), "l"(src) : "memory");
}
#define CP_COMMIT() asm volatile("cp.async.commit_group;" ::: "memory")
#define CP_WAIT0()  asm volatile("cp.async.wait_group 0;" ::: "memory")
#define CP_WAIT1()  asm volatile("cp.async.wait_group 1;" ::: "memory")

__device__ __forceinline__ void mma_bf16(float* d, const uint32_t* a,
                                         uint32_t b0, uint32_t b1) {
    asm volatile(
        "mma.sync.aligned.m16n8k16.row.col.f32.bf16.bf16.f32 "
        "{%0,%1,%2,%3}, {%4,%5,%6,%7}, {%8,%9}, {%0,%1,%2,%3};"
        : "+f"(d[0]), "+f"(d[1]), "+f"(d[2]), "+f"(d[3])
        : "r"(a[0]), "r"(a[1]), "r"(a[2]), "r"(a[3]), "r"(b0), "r"(b1));
}

#define IDX(r, q) ((((r) << 3)) | ((q) ^ ((r) & 7)))

__device__ __forceinline__ float fsigmoid(float x) { return 1.f / (1.f + __expf(-x)); }
__device__ __forceinline__ float ftanh(float x) {
    float t = __expf(2.f * fabsf(x));
    float r = 1.f - 2.f / (t + 1.f);
    return copysignf(r, x);
}

// ======================= weight pre-split (fragment-ordered) =================
__global__ void split_w(const float* __restrict__ W, uint32_t* __restrict__ hi,
                        uint32_t* __restrict__ lo, int total_pairs, int kp)
{
    int i = blockIdx.x * 256 + threadIdx.x;
    if (i >= total_pairs) return;
    int R = i / kp, p = i - R * kp;
    float2 f = ((const float2*)W)[i];
    uint32_t h, l;
    split2(f.x, f.y, h, l);
    int ngroup = R >> 7, n = R & 127;
    int ch = p >> 3, q = p & 7;
    int nt = n >> 3, l4 = n & 7;
    int region = l4 * 4 + (q & 3);
    int idx = region * 32 + (((nt >> 1) ^ (region & 7)) << 2) + ((nt & 1) << 1) + (q >> 2);
    size_t base = ((size_t)(ngroup * (kp >> 3) + ch)) << 10;
    hi[base + idx] = h;
    lo[base + idx] = l;
}

// ======================= MMA chunk ===========================================
__device__ __forceinline__ void mma_chunk(const uint32_t* __restrict__ A,
                                          const uint32_t* __restrict__ B,
                                          float (&acc)[16][4], int lane, int wid)
{
    const uint32_t* Ah = A;
    const uint32_t* Al = A + 1024;
    const int r = wid * 16 + (lane >> 2);
    const int q = lane & 3;
    uint32_t ah[4], al[4];
    ah[0] = Ah[IDX(r, q)];     ah[1] = Ah[IDX(r + 8, q)];
    ah[2] = Ah[IDX(r, q + 4)]; ah[3] = Ah[IDX(r + 8, q + 4)];
    al[0] = Al[IDX(r, q)];     al[1] = Al[IDX(r + 8, q)];
    al[2] = Al[IDX(r, q + 4)]; al[3] = Al[IDX(r + 8, q + 4)];
    const uint32_t* Bh = B + lane * 32;
    const uint32_t* Bl = Bh + 1024;
#pragma unroll
    for (int c = 0; c < 8; c++) {
        const int sw = ((c ^ (lane & 7)) << 2);
        uint4 vh = *(const uint4*)(Bh + sw);
        uint4 vl = *(const uint4*)(Bl + sw);
        mma_bf16(acc[2 * c],     ah, vh.x, vh.y);
        mma_bf16(acc[2 * c + 1], ah, vh.z, vh.w);
        mma_bf16(acc[2 * c],     al, vh.x, vh.y);
        mma_bf16(acc[2 * c + 1], al, vh.z, vh.w);
        mma_bf16(acc[2 * c],     ah, vl.x, vl.y);
        mma_bf16(acc[2 * c + 1], ah, vl.z, vl.w);
    }
}

// ======================= param structs =======================================
struct MlpP {
    const float* A0;
    const uint32_t *W0h, *W0l;
    const float* b0;
    const uint32_t *W1h, *W1l;
    const float* b1;
    float* out;
    int N, perm, gx;
};

struct GruP {
    const float *S0, *S1;
    int n0, n1;
    const uint32_t *Wih_h, *Wih_l, *Whh_h, *Whh_l;
    const float *bih, *bhh, *hprev;
    float *rz, *nbuf;
    int N, gx;
};

// ======================= combined fused 2-layer MLP (occ 2) ==================
#define MLP2_DSMEM (22528 * 4)

__global__ __launch_bounds__(256, 2)
void mlp2_multi(MlpP p0, MlpP p1, MlpP p2)
{
    extern __shared__ __align__(16) uint32_t sm[];
    __shared__ float sb0[128];

    int bx = blockIdx.x;
    MlpP p;
    if (bx < p0.gx) { p = p0; }
    else if (bx < p0.gx + p1.gx) { p = p1; bx -= p0.gx; }
    else { p = p2; bx -= p0.gx + p1.gx; }

    const int t = threadIdx.x, lane = t & 31, wid = t >> 5;
    const int m0 = bx * 128;

    if (t < 128) sb0[t] = p.b0[t];

    float acc1[16][4];
#pragma unroll
    for (int i = 0; i < 16; i++)
#pragma unroll
        for (int j = 0; j < 4; j++) acc1[i][j] = 0.f;

    const int arow_l = t >> 1;
    const int afl = (t & 1) * 8;
    const int grow = m0 + arow_l;
    int arow = (p.perm ? (grow ^ 1) : grow);
    if (grow >= p.N) arow = 0;
    float4 ra0, ra1;

    const int wrow = t & 127;
    const int wpl = t >> 7;
    const uint32_t* w0p = wpl ? p.W0l : p.W0h;
    const uint32_t* w1p = wpl ? p.W1l : p.W1h;

#define LDA1(ch) do { \
        const float* pp = p.A0 + (size_t)arow * 128 + ((ch) << 4) + afl; \
        ra0 = *(const float4*)pp; ra1 = *(const float4*)(pp + 4); \
    } while (0)
#define STA1(buf) do { \
        uint32_t* Ah = sm + (buf) * 4096; \
        uint32_t* Al = Ah + 1024; \
        uint32_t h0, l0; \
        split2(ra0.x, ra0.y, h0, l0); Ah[IDX(arow_l, (afl >> 1) + 0)] = h0; Al[IDX(arow_l, (afl >> 1) + 0)] = l0; \
        split2(ra0.z, ra0.w, h0, l0); Ah[IDX(arow_l, (afl >> 1) + 1)] = h0; Al[IDX(arow_l, (afl >> 1) + 1)] = l0; \
        split2(ra1.x, ra1.y, h0, l0); Ah[IDX(arow_l, (afl >> 1) + 2)] = h0; Al[IDX(arow_l, (afl >> 1) + 2)] = l0; \
        split2(ra1.z, ra1.w, h0, l0); Ah[IDX(arow_l, (afl >> 1) + 3)] = h0; Al[IDX(arow_l, (afl >> 1) + 3)] = l0; \
    } while (0)
#define CPW1(wb, ch, buf) do { \
        const uint32_t* gp = (wb) + ((size_t)(ch) << 10) + wrow * 8; \
        uint32_t daddr = smem_u32(sm + (buf) * 4096 + (2 + wpl) * 1024 + wrow * 8); \
        cp16(daddr, gp); cp16(daddr + 16, gp + 4); \
    } while (0)
#define CPW2(ch, buf) do { \
        const uint32_t* gp = w1p + ((size_t)(ch) << 10) + wrow * 8; \
        uint32_t daddr = smem_u32(sm + 16384 + (buf) * 2048 + wpl * 1024 + wrow * 8); \
        cp16(daddr, gp); cp16(daddr + 16, gp + 4); \
    } while (0)

    // ---- stage 1 ----
    LDA1(0); CPW1(w0p, 0, 0); CP_COMMIT(); STA1(0);
    LDA1(1); CPW1(w0p, 1, 1); CP_COMMIT(); STA1(1); CP_WAIT1();
    __syncthreads();
    for (int ch = 0; ch < 8; ch++) {
        const uint32_t* sb = sm + (ch % 3) * 4096;
        mma_chunk(sb, sb + 2048, acc1, lane, wid);
        if (ch + 1 < 8) {
            if (ch + 2 < 8) {
                LDA1(ch + 2); CPW1(w0p, ch + 2, (ch + 2) % 3); CP_COMMIT();
                STA1((ch + 2) % 3);
                CP_WAIT1();
            } else CP_WAIT0();
            __syncthreads();
        }
    }
    __syncthreads();

    // ---- bias + relu, spill stage-1 result into A region (pre-split) ----
    {
        const int rlo = wid * 16 + (lane >> 2);
        const int rhi = rlo + 8;
#pragma unroll
        for (int nt = 0; nt < 16; nt++) {
            const int col = nt * 8 + 2 * (lane & 3);
            float bx2 = sb0[col], by = sb0[col + 1];
            float v0 = fmaxf(acc1[nt][0] + bx2, 0.f);
            float v1 = fmaxf(acc1[nt][1] + by, 0.f);
            float v2 = fmaxf(acc1[nt][2] + bx2, 0.f);
            float v3 = fmaxf(acc1[nt][3] + by, 0.f);
            const int ch = nt >> 1;
            const int q = (nt & 1) * 4 + (lane & 3);
            uint32_t h, l;
            split2(v0, v1, h, l);
            sm[ch * 2048 + IDX(rlo, q)] = h;
            sm[ch * 2048 + 1024 + IDX(rlo, q)] = l;
            split2(v2, v3, h, l);
            sm[ch * 2048 + IDX(rhi, q)] = h;
            sm[ch * 2048 + 1024 + IDX(rhi, q)] = l;
        }
    }
    __syncthreads();

    float acc2[16][4];
#pragma unroll
    for (int i = 0; i < 16; i++)
#pragma unroll
        for (int j = 0; j < 4; j++) acc2[i][j] = 0.f;

    // ---- stage 2 ----
    CPW2(0, 0); CP_COMMIT();
    CPW2(1, 1); CP_COMMIT(); CP_WAIT1();
    __syncthreads();
    for (int ch = 0; ch < 8; ch++) {
        mma_chunk(sm + ch * 2048, sm + 16384 + (ch % 3) * 2048, acc2, lane, wid);
        if (ch + 1 < 8) {
            if (ch + 2 < 8) { CPW2(ch + 2, (ch + 2) % 3); CP_COMMIT(); CP_WAIT1(); }
            else CP_WAIT0();
            __syncthreads();
        }
    }

    const int r0 = m0 + wid * 16 + (lane >> 2);
#pragma unroll
    for (int nt = 0; nt < 16; nt++) {
        const int col = nt * 8 + 2 * (lane & 3);
        float bx2 = p.b1[col], by = p.b1[col + 1];
        if (r0 < p.N)
            *(float2*)(p.out + (size_t)r0 * 128 + col) =
                make_float2(acc2[nt][0] + bx2, acc2[nt][1] + by);
        if (r0 + 8 < p.N)
            *(float2*)(p.out + (size_t)(r0 + 8) * 128 + col) =
                make_float2(acc2[nt][2] + bx2, acc2[nt][3] + by);
    }
#undef LDA1
#undef STA1
#undef CPW1
#undef CPW2
}

// ======================= combined GRU gate GEMM ==============================
// grid (pc.gx + pl.gx, 4). y: 0=r, 1=z (sigmoid -> rz), 2=n_input, 3=n_hidden (-> nbuf)
__global__ __launch_bounds__(256, 2)
void gru_gemm_multi(GruP pc, GruP pl)
{
    __shared__ __align__(16) uint32_t sm[3 * 4096];

    int bx = blockIdx.x;
    GruP p;
    if (bx < pc.gx) { p = pc; }
    else { p = pl; bx -= pc.gx; }

    const int t = threadIdx.x, lane = t & 31, wid = t >> 5;
    const int m0 = bx * 128;
    const int g  = blockIdx.y;
    const int nchi = p.n0 + p.n1;
    const int nch = (g < 2) ? nchi + 8 : (g == 2 ? nchi : 8);

    float acc[16][4];
#pragma unroll
    for (int i = 0; i < 16; i++)
#pragma unroll
        for (int j = 0; j < 4; j++) acc[i][j] = 0.f;

    const int arow_l = t >> 1;
    const int afl = (t & 1) * 8;
    int arow = m0 + arow_l;
    if (arow >= p.N) arow = 0;
    float4 ra0, ra1;

    const int wrow = t & 127;
    const int wpl = t >> 7;
    const uint32_t* pih = wpl ? p.Wih_l : p.Wih_h;
    const uint32_t* phh = wpl ? p.Whh_l : p.Whh_h;

#define LDA(ch) do { \
        const float* src; int col; \
        if (g == 3)               { src = p.hprev; col = (ch) << 4; } \
        else if ((ch) < p.n0)     { src = p.S0;    col = (ch) << 4; } \
        else if ((ch) < nchi)     { src = p.S1;    col = ((ch) - p.n0) << 4; } \
        else                      { src = p.hprev; col = ((ch) - nchi) << 4; } \
        const float* pp = src + (size_t)arow * 128 + col + afl; \
        ra0 = *(const float4*)pp; ra1 = *(const float4*)(pp + 4); \
    } while (0)
#define STA(buf) do { \
        uint32_t* Ah = sm + (buf) * 4096; \
        uint32_t* Al = Ah + 1024; \
        uint32_t h0, l0; \
        split2(ra0.x, ra0.y, h0, l0); Ah[IDX(arow_l, (afl >> 1) + 0)] = h0; Al[IDX(arow_l, (afl >> 1) + 0)] = l0; \
        split2(ra0.z, ra0.w, h0, l0); Ah[IDX(arow_l, (afl >> 1) + 1)] = h0; Al[IDX(arow_l, (afl >> 1) + 1)] = l0; \
        split2(ra1.x, ra1.y, h0, l0); Ah[IDX(arow_l, (afl >> 1) + 2)] = h0; Al[IDX(arow_l, (afl >> 1) + 2)] = l0; \
        split2(ra1.z, ra1.w, h0, l0); Ah[IDX(arow_l, (afl >> 1) + 3)] = h0; Al[IDX(arow_l, (afl >> 1) + 3)] = l0; \
    } while (0)
#define CPW(ch, buf) do { \
        const uint32_t* gp; \
        if (g < 2) gp = ((ch) < nchi) \
            ? pih + (((size_t)(g * nchi + (ch))) << 10) + wrow * 8 \
            : phh + (((size_t)(g * 8 + (ch) - nchi)) << 10) + wrow * 8; \
        else if (g == 2) gp = pih + (((size_t)(2 * nchi + (ch))) << 10) + wrow * 8; \
        else gp = phh + (((size_t)(16 + (ch))) << 10) + wrow * 8; \
        uint32_t daddr = smem_u32(sm + (buf) * 4096 + (2 + wpl) * 1024 + wrow * 8); \
        cp16(daddr, gp); cp16(daddr + 16, gp + 4); \
    } while (0)

    LDA(0); CPW(0, 0); CP_COMMIT(); STA(0);
    if (nch > 1) { LDA(1); CPW(1, 1); CP_COMMIT(); STA(1); CP_WAIT1(); }
    else CP_WAIT0();
    __syncthreads();
    for (int ch = 0; ch < nch; ch++) {
        const uint32_t* sb = sm + (ch % 3) * 4096;
        mma_chunk(sb, sb + 2048, acc, lane, wid);
        if (ch + 1 < nch) {
            if (ch + 2 < nch) {
                LDA(ch + 2); CPW(ch + 2, (ch + 2) % 3); CP_COMMIT();
                STA((ch + 2) % 3);
                CP_WAIT1();
            } else CP_WAIT0();
            __syncthreads();
        }
    }

    const int r0 = m0 + wid * 16 + (lane >> 2);
    if (g < 2) {
#pragma unroll
        for (int nt = 0; nt < 16; nt++) {
            const int col = nt * 8 + 2 * (lane & 3);
            float bx2 = p.bih[g * 128 + col]     + p.bhh[g * 128 + col];
            float by  = p.bih[g * 128 + col + 1] + p.bhh[g * 128 + col + 1];
            if (r0 < p.N)
                *(float2*)(p.rz + (size_t)r0 * 256 + g * 128 + col) =
                    make_float2(fsigmoid(acc[nt][0] + bx2), fsigmoid(acc[nt][1] + by));
            if (r0 + 8 < p.N)
                *(float2*)(p.rz + (size_t)(r0 + 8) * 256 + g * 128 + col) =
                    make_float2(fsigmoid(acc[nt][2] + bx2), fsigmoid(acc[nt][3] + by));
        }
    } else {
        const float* bs = (g == 2) ? p.bih : p.bhh;
        const int go = (g - 2) * 128;
#pragma unroll
        for (int nt = 0; nt < 16; nt++) {
            const int col = nt * 8 + 2 * (lane & 3);
            float bx2 = bs[256 + col], by = bs[256 + col + 1];
            if (r0 < p.N)
                *(float2*)(p.nbuf + (size_t)r0 * 256 + go + col) =
                    make_float2(acc[nt][0] + bx2, acc[nt][1] + by);
            if (r0 + 8 < p.N)
                *(float2*)(p.nbuf + (size_t)(r0 + 8) * 256 + go + col) =
                    make_float2(acc[nt][2] + bx2, acc[nt][3] + by);
        }
    }
#undef LDA
#undef STA
#undef CPW
}

// ======================= CSR build ===========================================
__global__ void hist2(const int* __restrict__ l_e, const int* __restrict__ c_e,
                      int* __restrict__ cnt_l, int* __restrict__ cnt_c, int E)
{
    int i = blockIdx.x * blockDim.x + threadIdx.x;
    if (i < E) {
        atomicAdd(&cnt_l[l_e[i]], 1);
        atomicAdd(&cnt_c[c_e[i]], 1);
    }
}

__global__ void exscan(const int* __restrict__ cnt, int* __restrict__ off, int n)
{
    __shared__ int part[1024];
    const int t = threadIdx.x;
    const int chunk = (n + 1023) >> 10;
    const int b = t * chunk;
    const int e = min(b + chunk, n);
    int s = 0;
    for (int i = b; i < e; i++) s += cnt[i];
    part[t] = s;
    __syncthreads();
    for (int d = 1; d < 1024; d <<= 1) {
        int v = (t >= d) ? part[t - d] : 0;
        __syncthreads();
        if (t >= d) part[t] += v;
        __syncthreads();
    }
    int run = (t == 0) ? 0 : part[t - 1];
    for (int i = b; i < e; i++) { off[i] = run; run += cnt[i]; }
    if (t == 0) off[n] = part[1023];
}

__global__ void fill2(const int* __restrict__ l_e, const int* __restrict__ c_e,
                      int* __restrict__ cur_l, int* __restrict__ cur_c,
                      int* __restrict__ src_l, int* __restrict__ src_c, int E)
{
    int i = blockIdx.x * blockDim.x + threadIdx.x;
    if (i < E) {
        int l = l_e[i], c = c_e[i];
        src_c[atomicAdd(&cur_c[c], 1)] = l;
        src_l[atomicAdd(&cur_l[l], 1)] = c;
    }
}

// ======================= combined gather-sum =================================
__global__ __launch_bounds__(256)
void gather2(const float* __restrict__ msgA, const int* __restrict__ offA,
             const int* __restrict__ srcA, float* __restrict__ aggrA, int nA,
             const float* __restrict__ msgB, const int* __restrict__ offB,
             const int* __restrict__ srcB, float* __restrict__ aggrB, int nB)
{
    int node = blockIdx.x * 8 + (threadIdx.x >> 5);
    int lane = threadIdx.x & 31;
    const float* msg;
    const int *off, *srcs;
    float* aggr;
    if (node < nA) { msg = msgA; off = offA; srcs = srcA; aggr = aggrA; }
    else {
        node -= nA;
        if (node >= nB) return;
        msg = msgB; off = offB; srcs = srcB; aggr = aggrB;
    }
    int b = off[node], e = off[node + 1];
    float4 acc = {0.f, 0.f, 0.f, 0.f};
    for (int i = b; i < e; i++) {
        const float4 v = *((const float4*)(msg + (size_t)srcs[i] * DIM) + lane);
        acc.x += v.x; acc.y += v.y; acc.z += v.z; acc.w += v.w;
    }
    *((float4*)(aggr + (size_t)node * DIM) + lane) = acc;
}

// ---------------- combined GRU elementwise ------------------------------------
__global__ void gru_elem2x2(const float* __restrict__ rzA, const float* __restrict__ nA,
                            const float* __restrict__ hA, float* __restrict__ hnA, int NA,
                            const float* __restrict__ rzB, const float* __restrict__ nB,
                            const float* __restrict__ hB, float* __restrict__ hnB, int NB)
{
    int idx = blockIdx.x * blockDim.x + threadIdx.x;
    int row = idx >> 5, c4 = (idx & 31) * 4;
    const float *rz, *nbuf, *h;
    float* hnew;
    if (row < NA) { rz = rzA; nbuf = nA; h = hA; hnew = hnA; }
    else {
        row -= NA;
        if (row >= NB) return;
        rz = rzB; nbuf = nB; h = hB; hnew = hnB;
    }
    const float4 r4 = *(const float4*)(rz + (size_t)row * 256 + c4);
    const float4 z4 = *(const float4*)(rz + (size_t)row * 256 + 128 + c4);
    const float4 ni = *(const float4*)(nbuf + (size_t)row * 256 + c4);
    const float4 nh = *(const float4*)(nbuf + (size_t)row * 256 + 128 + c4);
    const float4 h4 = *(const float4*)(h + (size_t)row * 128 + c4);
    float4 o;
    o.x = (1.f - z4.x) * ftanh(ni.x + r4.x * nh.x) + z4.x * h4.x;
    o.y = (1.f - z4.y) * ftanh(ni.y + r4.y * nh.y) + z4.y * h4.y;
    o.z = (1.f - z4.z) * ftanh(ni.z + r4.z * nh.z) + z4.z * h4.z;
    o.w = (1.f - z4.w) * ftanh(ni.w + r4.w * nh.w) + z4.w * h4.w;
    *(float4*)(hnew + (size_t)row * 128 + c4) = o;
}

// ---------------- launch ------------------------------------------------------
extern "C" void kernel_launch(void* const* d_in, const int* in_sizes, int n_in,
                              void* d_out, int out_size)
{
    const int D = DIM;
    const int E = in_sizes[2];
    const int L = in_sizes[4] / D;
    const int C = in_sizes[5] / D;

    const int*   l_edge = (const int*)d_in[2];
    const int*   c_edge = (const int*)d_in[3];
    const float* l_emb0 = (const float*)d_in[4];
    const float* c_emb0 = (const float*)d_in[5];

    const float* l2c_W0 = (const float*)d_in[6];
    const float* l2c_b0 = (const float*)d_in[7];
    const float* l2c_W1 = (const float*)d_in[8];
    const float* l2c_b1 = (const float*)d_in[9];
    const float* c2l_W0 = (const float*)d_in[10];
    const float* c2l_b0 = (const float*)d_in[11];
    const float* c2l_W1 = (const float*)d_in[12];
    const float* c2l_b1 = (const float*)d_in[13];
    const float* l2l_W0 = (const float*)d_in[14];
    const float* l2l_b0 = (const float*)d_in[15];
    const float* l2l_W1 = (const float*)d_in[16];
    const float* l2l_b1 = (const float*)d_in[17];
    const float* c_Wih  = (const float*)d_in[18];
    const float* c_Whh  = (const float*)d_in[19];
    const float* c_bih  = (const float*)d_in[20];
    const float* c_bhh  = (const float*)d_in[21];
    const float* l_Wih  = (const float*)d_in[22];
    const float* l_Whh  = (const float*)d_in[23];
    const float* l_bih  = (const float*)d_in[24];
    const float* l_bhh  = (const float*)d_in[25];

    float* out   = (float*)d_out;
    float* louts = out;                                // [9, L, D]
    float* couts = out + (size_t)(NITER + 1) * L * D;  // [9, C, D]

    float *l2c_msg, *c2l_msg, *l2l_msg, *aggr_c, *aggr_l, *rz_c, *n_c, *rz_l, *n_l;
    cudaGetSymbolAddress((void**)&l2c_msg, g_l2c_msg);
    cudaGetSymbolAddress((void**)&c2l_msg, g_c2l_msg);
    cudaGetSymbolAddress((void**)&l2l_msg, g_l2l_msg);
    cudaGetSymbolAddress((void**)&aggr_c,  g_aggr_c);
    cudaGetSymbolAddress((void**)&aggr_l,  g_aggr_l);
    cudaGetSymbolAddress((void**)&rz_c,    g_rz_c);
    cudaGetSymbolAddress((void**)&n_c,     g_n_c);
    cudaGetSymbolAddress((void**)&rz_l,    g_rz_l);
    cudaGetSymbolAddress((void**)&n_l,     g_n_l);

    int *cnt_c, *cnt_l, *off_c, *off_l, *cur_c, *cur_l, *src_c, *src_l;
    cudaGetSymbolAddress((void**)&cnt_c, g_cnt_c);
    cudaGetSymbolAddress((void**)&cnt_l, g_cnt_l);
    cudaGetSymbolAddress((void**)&off_c, g_off_c);
    cudaGetSymbolAddress((void**)&off_l, g_off_l);
    cudaGetSymbolAddress((void**)&cur_c, g_cur_c);
    cudaGetSymbolAddress((void**)&cur_l, g_cur_l);
    cudaGetSymbolAddress((void**)&src_c, g_src_c);
    cudaGetSymbolAddress((void**)&src_l, g_src_l);

    uint32_t *whi, *wlo;
    cudaGetSymbolAddress((void**)&whi, g_whi);
    cudaGetSymbolAddress((void**)&wlo, g_wlo);

    cudaFuncSetAttribute(mlp2_multi, cudaFuncAttributeMaxDynamicSharedMemorySize,
                         MLP2_DSMEM);

    const int o_l2c0 = 0,      o_l2c1 = 8192,  o_c2l0 = 16384, o_c2l1 = 24576;
    const int o_l2l0 = 32768,  o_l2l1 = 40960;
    const int o_cih  = 49152,  o_chh  = 73728;
    const int o_lih  = 98304,  o_lhh  = 147456;

    // ---- pre-split weights into fragment-ordered bf16 hi/lo planes ----
    split_w<<<32, 256>>>(l2c_W0, whi + o_l2c0, wlo + o_l2c0, 8192, 64);
    split_w<<<32, 256>>>(l2c_W1, whi + o_l2c1, wlo + o_l2c1, 8192, 64);
    split_w<<<32, 256>>>(c2l_W0, whi + o_c2l0, wlo + o_c2l0, 8192, 64);
    split_w<<<32, 256>>>(c2l_W1, whi + o_c2l1, wlo + o_c2l1, 8192, 64);
    split_w<<<32, 256>>>(l2l_W0, whi + o_l2l0, wlo + o_l2l0, 8192, 64);
    split_w<<<32, 256>>>(l2l_W1, whi + o_l2l1, wlo + o_l2l1, 8192, 64);
    split_w<<<96, 256>>>(c_Wih,  whi + o_cih,  wlo + o_cih,  24576, 64);
    split_w<<<96, 256>>>(c_Whh,  whi + o_chh,  wlo + o_chh,  24576, 64);
    split_w<<<192, 256>>>(l_Wih, whi + o_lih,  wlo + o_lih,  49152, 128);
    split_w<<<96, 256>>>(l_Whh,  whi + o_lhh,  wlo + o_lhh,  24576, 64);

    // ---- CSR build (edge structure static across iterations) ----
    cudaMemsetAsync(cnt_c, 0, (size_t)C * sizeof(int));
    cudaMemsetAsync(cnt_l, 0, (size_t)L * sizeof(int));
    hist2<<<(E + 255) / 256, 256>>>(l_edge, c_edge, cnt_l, cnt_c, E);
    exscan<<<1, 1024>>>(cnt_c, off_c, C);
    exscan<<<1, 1024>>>(cnt_l, off_l, L);
    cudaMemcpyAsync(cur_c, off_c, (size_t)C * sizeof(int), cudaMemcpyDeviceToDevice);
    cudaMemcpyAsync(cur_l, off_l, (size_t)L * sizeof(int), cudaMemcpyDeviceToDevice);
    fill2<<<(E + 255) / 256, 256>>>(l_edge, c_edge, cur_l, cur_c, src_l, src_c, E);

    // iteration-0 slices = inputs
    cudaMemcpyAsync(louts, l_emb0, (size_t)L * D * sizeof(float), cudaMemcpyDeviceToDevice);
    cudaMemcpyAsync(couts, c_emb0, (size_t)C * D * sizeof(float), cudaMemcpyDeviceToDevice);

    const int gLx = (L + 127) / 128;
    const int gCx = (C + 127) / 128;
    const int total_nodes = C + L;
    const dim3 gGemm(gCx + gLx, 4);

    for (int it = 0; it < NITER; it++) {
        const float* l_prev = louts + (size_t)it * L * D;
        const float* c_prev = couts + (size_t)it * C * D;
        float* l_next = louts + (size_t)(it + 1) * L * D;
        float* c_next = couts + (size_t)(it + 1) * C * D;

        // phase 1: all three message MLPs in one launch
        MlpP p0 = {l_prev, whi + o_l2c0, wlo + o_l2c0, l2c_b0,
                   whi + o_l2c1, wlo + o_l2c1, l2c_b1, l2c_msg, L, 0, gLx};
        MlpP p1 = {c_prev, whi + o_c2l0, wlo + o_c2l0, c2l_b0,
                   whi + o_c2l1, wlo + o_c2l1, c2l_b1, c2l_msg, C, 0, gCx};
        MlpP p2 = {l_prev, whi + o_l2l0, wlo + o_l2l0, l2l_b0,
                   whi + o_l2l1, wlo + o_l2l1, l2l_b1, l2l_msg, L, 1, gLx};
        mlp2_multi<<<gLx + gCx + gLx, 256, MLP2_DSMEM>>>(p0, p1, p2);

        // phase 2: both gathers in one launch
        gather2<<<(total_nodes + 7) / 8, 256>>>(l2c_msg, off_c, src_c, aggr_c, C,
                                                c2l_msg, off_l, src_l, aggr_l, L);

        // phase 3: all GRU gate GEMMs in one launch
        GruP pc = {aggr_c, nullptr, 8, 0,
                   whi + o_cih, wlo + o_cih, whi + o_chh, wlo + o_chh,
                   c_bih, c_bhh, c_prev, rz_c, n_c, C, gCx};
        GruP pl = {aggr_l, l2l_msg, 8, 8,
                   whi + o_lih, wlo + o_lih, whi + o_lhh, wlo + o_lhh,
                   l_bih, l_bhh, l_prev, rz_l, n_l, L, gLx};
        gru_gemm_multi<<<gGemm, 256>>>(pc, pl);

        // phase 4: both elementwise GRU updates in one launch
        gru_elem2x2<<<(total_nodes * 32 + 255) / 256, 256>>>(
            rz_c, n_c, c_prev, c_next, C,
            rz_l, n_l, l_prev, l_next, L);
    }
}

// round 12
// speedup vs baseline: 1.2320x; 1.0458x over previous
#include <cuda_runtime.h>
#include <cuda_bf16.h>
#include <cstdint>

// Problem constants (fixed by setup_inputs)
#define DIM   128
#define LMAX  60000
#define CMAX  30000
#define EMAX  360000
#define NITER 8

// ---------------- scratch (device globals; no allocations allowed) ----------
__device__ float g_l2c_msg[(size_t)LMAX * DIM];
__device__ float g_c2l_msg[(size_t)CMAX * DIM];
__device__ float g_l2l_msg[(size_t)LMAX * DIM];
__device__ float g_aggr_c [(size_t)CMAX * DIM];
__device__ float g_aggr_l [(size_t)LMAX * DIM];
__device__ float g_rz_c   [(size_t)CMAX * 2 * DIM];
__device__ float g_n_c    [(size_t)CMAX * 2 * DIM];
__device__ float g_rz_l   [(size_t)LMAX * 2 * DIM];
__device__ float g_n_l    [(size_t)LMAX * 2 * DIM];
// CSR scratch
__device__ int g_cnt_c[CMAX];
__device__ int g_cnt_l[LMAX];
__device__ int g_off_c[CMAX + 1];
__device__ int g_off_l[LMAX + 1];
__device__ int g_cur_c[CMAX];
__device__ int g_cur_l[LMAX];
__device__ int g_src_c[EMAX];
__device__ int g_src_l[EMAX];
// pre-split bf16 weight planes (u32 = 2 bf16), fragment-ordered
#define WSPLIT_TOTAL 172032
__device__ uint32_t g_whi[WSPLIT_TOTAL];
__device__ uint32_t g_wlo[WSPLIT_TOTAL];

// ======================= helpers =============================================
__device__ __forceinline__ uint32_t smem_u32(const void* p) {
    uint32_t a;
    asm("{ .reg .u64 t; cvta.to.shared.u64 t, %1; cvt.u32.u64 %0, t; }"
        : "=r"(a) : "l"(p));
    return a;
}

__device__ __forceinline__ uint32_t pack_bf16(float lo, float hi) {
    uint32_t r;
    asm("cvt.rn.bf16x2.f32 %0, %1, %2;" : "=r"(r) : "f"(hi), "f"(lo));
    return r;
}

__device__ __forceinline__ void split2(float x, float y, uint32_t& hi, uint32_t& lo) {
    uint32_t h = pack_bf16(x, y);
    float hx = __uint_as_float(h << 16);
    float hy = __uint_as_float(h & 0xffff0000u);
    hi = h;
    lo = pack_bf16(x - hx, y - hy);
}

__device__ __forceinline__ void cp16(uint32_t dst, const void* src) {
    asm volatile("cp.async.ca.shared.global [%0], [%1], 16;"
                 :: "r"(dst), "l"(src) : "memory");
}
#define CP_COMMIT() asm volatile("cp.async.commit_group;" ::: "memory")
#define CP_WAIT0()  asm volatile("cp.async.wait_group 0;" ::: "memory")

__device__ __forceinline__ void mma_bf16(float* d, const uint32_t* a,
                                         uint32_t b0, uint32_t b1) {
    asm volatile(
        "mma.sync.aligned.m16n8k16.row.col.f32.bf16.bf16.f32 "
        "{%0,%1,%2,%3}, {%4,%5,%6,%7}, {%8,%9}, {%0,%1,%2,%3};"
        : "+f"(d[0]), "+f"(d[1]), "+f"(d[2]), "+f"(d[3])
        : "r"(a[0]), "r"(a[1]), "r"(a[2]), "r"(a[3]), "r"(b0), "r"(b1));
}

#define IDX(r, q) ((((r) << 3)) | ((q) ^ ((r) & 7)))

__device__ __forceinline__ float fsigmoid(float x) { return 1.f / (1.f + __expf(-x)); }
__device__ __forceinline__ float ftanh(float x) {
    float t = __expf(2.f * fabsf(x));
    float r = 1.f - 2.f / (t + 1.f);
    return copysignf(r, x);
}

// ======================= weight pre-split (fragment-ordered) =================
__global__ void split_w(const float* __restrict__ W, uint32_t* __restrict__ hi,
                        uint32_t* __restrict__ lo, int total_pairs, int kp)
{
    int i = blockIdx.x * 256 + threadIdx.x;
    if (i >= total_pairs) return;
    int R = i / kp, p = i - R * kp;
    float2 f = ((const float2*)W)[i];
    uint32_t h, l;
    split2(f.x, f.y, h, l);
    int ngroup = R >> 7, n = R & 127;
    int ch = p >> 3, q = p & 7;
    int nt = n >> 3, l4 = n & 7;
    int region = l4 * 4 + (q & 3);
    int idx = region * 32 + (((nt >> 1) ^ (region & 7)) << 2) + ((nt & 1) << 1) + (q >> 2);
    size_t base = ((size_t)(ngroup * (kp >> 3) + ch)) << 10;
    hi[base + idx] = h;
    lo[base + idx] = l;
}

// ======================= MMA K16 sub-chunk ===================================
// A: [Ah 1024][Al 1024]; B: [Bh 1024][Bl 1024]. Interleaved chains (RAW dist 2).
__device__ __forceinline__ void mma_chunk(const uint32_t* __restrict__ A,
                                          const uint32_t* __restrict__ B,
                                          float (&acc)[16][4], int lane, int wid)
{
    const uint32_t* Ah = A;
    const uint32_t* Al = A + 1024;
    const int r = wid * 16 + (lane >> 2);
    const int q = lane & 3;
    uint32_t ah[4], al[4];
    ah[0] = Ah[IDX(r, q)];     ah[1] = Ah[IDX(r + 8, q)];
    ah[2] = Ah[IDX(r, q + 4)]; ah[3] = Ah[IDX(r + 8, q + 4)];
    al[0] = Al[IDX(r, q)];     al[1] = Al[IDX(r + 8, q)];
    al[2] = Al[IDX(r, q + 4)]; al[3] = Al[IDX(r + 8, q + 4)];
    const uint32_t* Bh = B + lane * 32;
    const uint32_t* Bl = Bh + 1024;
#pragma unroll
    for (int c = 0; c < 8; c++) {
        const int sw = ((c ^ (lane & 7)) << 2);
        uint4 vh = *(const uint4*)(Bh + sw);
        uint4 vl = *(const uint4*)(Bl + sw);
        mma_bf16(acc[2 * c],     ah, vh.x, vh.y);
        mma_bf16(acc[2 * c + 1], ah, vh.z, vh.w);
        mma_bf16(acc[2 * c],     al, vh.x, vh.y);
        mma_bf16(acc[2 * c + 1], al, vh.z, vh.w);
        mma_bf16(acc[2 * c],     ah, vl.x, vl.y);
        mma_bf16(acc[2 * c + 1], ah, vl.z, vl.w);
    }
}

// ======================= param structs =======================================
struct MlpP {
    const float* A0;
    const uint32_t *W0h, *W0l;
    const float* b0;
    const uint32_t *W1h, *W1l;
    const float* b1;
    float* out;
    int N, perm, gx;
};

struct GruP {
    const float *S0, *S1;
    int n0, n1;
    const uint32_t *Wih_h, *Wih_l, *Whh_h, *Whh_l;
    const float *bih, *bhh, *hprev;
    float *rz, *nbuf;
    int N, gx;
};

// shared K32 A-store: thread handles row = t>>1, 16-float half sub = t&1.
// Writes [Ah 1024][Al 1024] at Sbase (u32*).
#define STA_K32(Sbase) do { \
        uint32_t* Ah = (Sbase); \
        uint32_t* Al = Ah + 1024; \
        uint32_t h0, l0; \
        split2(ra0.x, ra0.y, h0, l0); Ah[IDX(row, 0)] = h0; Al[IDX(row, 0)] = l0; \
        split2(ra0.z, ra0.w, h0, l0); Ah[IDX(row, 1)] = h0; Al[IDX(row, 1)] = l0; \
        split2(ra1.x, ra1.y, h0, l0); Ah[IDX(row, 2)] = h0; Al[IDX(row, 2)] = l0; \
        split2(ra1.z, ra1.w, h0, l0); Ah[IDX(row, 3)] = h0; Al[IDX(row, 3)] = l0; \
        split2(ra2.x, ra2.y, h0, l0); Ah[IDX(row, 4)] = h0; Al[IDX(row, 4)] = l0; \
        split2(ra2.z, ra2.w, h0, l0); Ah[IDX(row, 5)] = h0; Al[IDX(row, 5)] = l0; \
        split2(ra3.x, ra3.y, h0, l0); Ah[IDX(row, 6)] = h0; Al[IDX(row, 6)] = l0; \
        split2(ra3.z, ra3.w, h0, l0); Ah[IDX(row, 7)] = h0; Al[IDX(row, 7)] = l0; \
    } while (0)

// ======================= combined fused 2-layer MLP (occ 2, K32 chunks) ======
// dyn smem (u32): stage1 ring 2 x 8192 = [0,16384); stage2 A region [0,16384)
// (reused after stage1), stage2 B ring 2 x 4096 at [16384, 24576).
#define MLP2_DSMEM (24576 * 4)

__global__ __launch_bounds__(256, 2)
void mlp2_multi(MlpP p0, MlpP p1, MlpP p2)
{
    extern __shared__ __align__(16) uint32_t sm[];
    __shared__ float sb0[128];

    int bx = blockIdx.x;
    MlpP p;
    if (bx < p0.gx) { p = p0; }
    else if (bx < p0.gx + p1.gx) { p = p1; bx -= p0.gx; }
    else { p = p2; bx -= p0.gx + p1.gx; }

    const int t = threadIdx.x, lane = t & 31, wid = t >> 5;
    const int m0 = bx * 128;

    if (t < 128) sb0[t] = p.b0[t];

    float acc1[16][4];
#pragma unroll
    for (int i = 0; i < 16; i++)
#pragma unroll
        for (int j = 0; j < 4; j++) acc1[i][j] = 0.f;

    const int row = t >> 1;
    const int sub = t & 1;
    const int grow = m0 + row;
    int arow = (p.perm ? (grow ^ 1) : grow);
    if (grow >= p.N) arow = 0;
    float4 ra0, ra1, ra2, ra3;

    const int wrow = t & 127;
    const int wpl = t >> 7;
    const uint32_t* w0p = wpl ? p.W0l : p.W0h;
    const uint32_t* w1p = wpl ? p.W1l : p.W1h;

#define LDA1(ch) do { \
        const float* pp = p.A0 + (size_t)arow * 128 + ((ch) << 5) + sub * 16; \
        ra0 = *(const float4*)pp;       ra1 = *(const float4*)(pp + 4); \
        ra2 = *(const float4*)(pp + 8); ra3 = *(const float4*)(pp + 12); \
    } while (0)
#define CPW1(wb, ch, buf) do { \
        _Pragma("unroll") \
        for (int si = 0; si < 2; si++) { \
            const uint32_t* gp = (wb) + ((size_t)(2 * (ch) + si) << 10) + wrow * 8; \
            uint32_t daddr = smem_u32(sm + (buf) * 8192 + si * 4096 + 2048 + wpl * 1024 + wrow * 8); \
            cp16(daddr, gp); cp16(daddr + 16, gp + 4); \
        } \
    } while (0)
#define CPW2(ch, buf) do { \
        _Pragma("unroll") \
        for (int si = 0; si < 2; si++) { \
            const uint32_t* gp = w1p + ((size_t)(2 * (ch) + si) << 10) + wrow * 8; \
            uint32_t daddr = smem_u32(sm + 16384 + (buf) * 4096 + si * 2048 + wpl * 1024 + wrow * 8); \
            cp16(daddr, gp); cp16(daddr + 16, gp + 4); \
        } \
    } while (0)

    // ---- stage 1: 4 K32 chunks, 2-deep ring ----
    LDA1(0); CPW1(w0p, 0, 0); CP_COMMIT();
    STA_K32(sm + 0 * 8192 + sub * 4096);
    LDA1(1);
    CP_WAIT0(); __syncthreads();
    for (int ch = 0; ch < 4; ch++) {
        if (ch + 1 < 4) {
            const int nb = (ch + 1) & 1;
            CPW1(w0p, ch + 1, nb); CP_COMMIT();
            STA_K32(sm + nb * 8192 + sub * 4096);
        }
        if (ch + 2 < 4) LDA1(ch + 2);
        const uint32_t* S = sm + (ch & 1) * 8192;
        mma_chunk(S,        S + 2048, acc1, lane, wid);
        mma_chunk(S + 4096, S + 6144, acc1, lane, wid);
        if (ch + 1 < 4) { CP_WAIT0(); __syncthreads(); }
    }
    __syncthreads();   // all warps done with stage-1 ring before spill

    // ---- bias + relu, spill stage-1 result into A region (pre-split) ----
    {
        const int rlo = wid * 16 + (lane >> 2);
        const int rhi = rlo + 8;
#pragma unroll
        for (int nt = 0; nt < 16; nt++) {
            const int col = nt * 8 + 2 * (lane & 3);
            float bx2 = sb0[col], by = sb0[col + 1];
            float v0 = fmaxf(acc1[nt][0] + bx2, 0.f);
            float v1 = fmaxf(acc1[nt][1] + by, 0.f);
            float v2 = fmaxf(acc1[nt][2] + bx2, 0.f);
            float v3 = fmaxf(acc1[nt][3] + by, 0.f);
            const int ch16 = nt >> 1;
            const int q = (nt & 1) * 4 + (lane & 3);
            uint32_t h, l;
            split2(v0, v1, h, l);
            sm[ch16 * 2048 + IDX(rlo, q)] = h;
            sm[ch16 * 2048 + 1024 + IDX(rlo, q)] = l;
            split2(v2, v3, h, l);
            sm[ch16 * 2048 + IDX(rhi, q)] = h;
            sm[ch16 * 2048 + 1024 + IDX(rhi, q)] = l;
        }
    }

    float acc2[16][4];
#pragma unroll
    for (int i = 0; i < 16; i++)
#pragma unroll
        for (int j = 0; j < 4; j++) acc2[i][j] = 0.f;

    // ---- stage 2: A from smem region, W1 streamed, 4 K32 chunks ----
    CPW2(0, 0); CP_COMMIT();
    CP_WAIT0(); __syncthreads();   // also publishes the spill
    for (int ch = 0; ch < 4; ch++) {
        if (ch + 1 < 4) { CPW2(ch + 1, (ch + 1) & 1); CP_COMMIT(); }
        const uint32_t* B = sm + 16384 + (ch & 1) * 4096;
        mma_chunk(sm + (2 * ch) * 2048,     B,        acc2, lane, wid);
        mma_chunk(sm + (2 * ch + 1) * 2048, B + 2048, acc2, lane, wid);
        if (ch + 1 < 4) { CP_WAIT0(); __syncthreads(); }
    }

    const int r0 = m0 + wid * 16 + (lane >> 2);
#pragma unroll
    for (int nt = 0; nt < 16; nt++) {
        const int col = nt * 8 + 2 * (lane & 3);
        float bx2 = p.b1[col], by = p.b1[col + 1];
        if (r0 < p.N)
            *(float2*)(p.out + (size_t)r0 * 128 + col) =
                make_float2(acc2[nt][0] + bx2, acc2[nt][1] + by);
        if (r0 + 8 < p.N)
            *(float2*)(p.out + (size_t)(r0 + 8) * 128 + col) =
                make_float2(acc2[nt][2] + bx2, acc2[nt][3] + by);
    }
#undef LDA1
#undef CPW1
#undef CPW2
}

// ======================= combined GRU gate GEMM (K32 chunks) =================
// grid (pc.gx + pl.gx, 4). y: 0=r, 1=z (sigmoid -> rz), 2=n_input, 3=n_hidden (-> nbuf)
#define GRU_DSMEM (16384 * 4)

__global__ __launch_bounds__(256, 2)
void gru_gemm_multi(GruP pc, GruP pl)
{
    extern __shared__ __align__(16) uint32_t sm[];

    int bx = blockIdx.x;
    GruP p;
    if (bx < pc.gx) { p = pc; }
    else { p = pl; bx -= pc.gx; }

    const int t = threadIdx.x, lane = t & 31, wid = t >> 5;
    const int m0 = bx * 128;
    const int g  = blockIdx.y;
    const int nchi = p.n0 + p.n1;          // K16 units
    const int n0h = p.n0 >> 1;             // K32 units
    const int nchi32 = nchi >> 1;
    const int nch32 = (g < 2) ? nchi32 + 4 : (g == 2 ? nchi32 : 4);

    float acc[16][4];
#pragma unroll
    for (int i = 0; i < 16; i++)
#pragma unroll
        for (int j = 0; j < 4; j++) acc[i][j] = 0.f;

    const int row = t >> 1;
    const int sub = t & 1;
    int arow = m0 + row;
    if (arow >= p.N) arow = 0;
    float4 ra0, ra1, ra2, ra3;

    const int wrow = t & 127;
    const int wpl = t >> 7;
    const uint32_t* pih = wpl ? p.Wih_l : p.Wih_h;
    const uint32_t* phh = wpl ? p.Whh_l : p.Whh_h;

#define LDA(ch) do { \
        const float* src; int col; \
        if (g == 3)               { src = p.hprev; col = (ch) << 5; } \
        else if ((ch) < n0h)      { src = p.S0;    col = (ch) << 5; } \
        else if ((ch) < nchi32)   { src = p.S1;    col = ((ch) - n0h) << 5; } \
        else                      { src = p.hprev; col = ((ch) - nchi32) << 5; } \
        const float* pp = src + (size_t)arow * 128 + col + sub * 16; \
        ra0 = *(const float4*)pp;       ra1 = *(const float4*)(pp + 4); \
        ra2 = *(const float4*)(pp + 8); ra3 = *(const float4*)(pp + 12); \
    } while (0)
#define CPW(ch, buf) do { \
        _Pragma("unroll") \
        for (int si = 0; si < 2; si++) { \
            const int c16 = 2 * (ch) + si; \
            const uint32_t* gp; \
            if (g < 2) gp = (c16 < nchi) \
                ? pih + (((size_t)(g * nchi + c16)) << 10) + wrow * 8 \
                : phh + (((size_t)(g * 8 + c16 - nchi)) << 10) + wrow * 8; \
            else if (g == 2) gp = pih + (((size_t)(2 * nchi + c16)) << 10) + wrow * 8; \
            else gp = phh + (((size_t)(16 + c16)) << 10) + wrow * 8; \
            uint32_t daddr = smem_u32(sm + (buf) * 8192 + si * 4096 + 2048 + wpl * 1024 + wrow * 8); \
            cp16(daddr, gp); cp16(daddr + 16, gp + 4); \
        } \
    } while (0)

    LDA(0); CPW(0, 0); CP_COMMIT();
    STA_K32(sm + 0 * 8192 + sub * 4096);
    if (nch32 > 1) LDA(1);
    CP_WAIT0(); __syncthreads();
    for (int ch = 0; ch < nch32; ch++) {
        if (ch + 1 < nch32) {
            const int nb = (ch + 1) & 1;
            CPW(ch + 1, nb); CP_COMMIT();
            STA_K32(sm + nb * 8192 + sub * 4096);
        }
        if (ch + 2 < nch32) LDA(ch + 2);
        const uint32_t* S = sm + (ch & 1) * 8192;
        mma_chunk(S,        S + 2048, acc, lane, wid);
        mma_chunk(S + 4096, S + 6144, acc, lane, wid);
        if (ch + 1 < nch32) { CP_WAIT0(); __syncthreads(); }
    }

    const int r0 = m0 + wid * 16 + (lane >> 2);
    if (g < 2) {
#pragma unroll
        for (int nt = 0; nt < 16; nt++) {
            const int col = nt * 8 + 2 * (lane & 3);
            float bx2 = p.bih[g * 128 + col]     + p.bhh[g * 128 + col];
            float by  = p.bih[g * 128 + col + 1] + p.bhh[g * 128 + col + 1];
            if (r0 < p.N)
                *(float2*)(p.rz + (size_t)r0 * 256 + g * 128 + col) =
                    make_float2(fsigmoid(acc[nt][0] + bx2), fsigmoid(acc[nt][1] + by));
            if (r0 + 8 < p.N)
                *(float2*)(p.rz + (size_t)(r0 + 8) * 256 + g * 128 + col) =
                    make_float2(fsigmoid(acc[nt][2] + bx2), fsigmoid(acc[nt][3] + by));
        }
    } else {
        const float* bs = (g == 2) ? p.bih : p.bhh;
        const int go = (g - 2) * 128;
#pragma unroll
        for (int nt = 0; nt < 16; nt++) {
            const int col = nt * 8 + 2 * (lane & 3);
            float bx2 = bs[256 + col], by = bs[256 + col + 1];
            if (r0 < p.N)
                *(float2*)(p.nbuf + (size_t)r0 * 256 + go + col) =
                    make_float2(acc[nt][0] + bx2, acc[nt][1] + by);
            if (r0 + 8 < p.N)
                *(float2*)(p.nbuf + (size_t)(r0 + 8) * 256 + go + col) =
                    make_float2(acc[nt][2] + bx2, acc[nt][3] + by);
        }
    }
#undef LDA
#undef CPW
}

// ======================= CSR build ===========================================
__global__ void hist2(const int* __restrict__ l_e, const int* __restrict__ c_e,
                      int* __restrict__ cnt_l, int* __restrict__ cnt_c, int E)
{
    int i = blockIdx.x * blockDim.x + threadIdx.x;
    if (i < E) {
        atomicAdd(&cnt_l[l_e[i]], 1);
        atomicAdd(&cnt_c[c_e[i]], 1);
    }
}

__global__ void exscan(const int* __restrict__ cnt, int* __restrict__ off, int n)
{
    __shared__ int part[1024];
    const int t = threadIdx.x;
    const int chunk = (n + 1023) >> 10;
    const int b = t * chunk;
    const int e = min(b + chunk, n);
    int s = 0;
    for (int i = b; i < e; i++) s += cnt[i];
    part[t] = s;
    __syncthreads();
    for (int d = 1; d < 1024; d <<= 1) {
        int v = (t >= d) ? part[t - d] : 0;
        __syncthreads();
        if (t >= d) part[t] += v;
        __syncthreads();
    }
    int run = (t == 0) ? 0 : part[t - 1];
    for (int i = b; i < e; i++) { off[i] = run; run += cnt[i]; }
    if (t == 0) off[n] = part[1023];
}

__global__ void fill2(const int* __restrict__ l_e, const int* __restrict__ c_e,
                      int* __restrict__ cur_l, int* __restrict__ cur_c,
                      int* __restrict__ src_l, int* __restrict__ src_c, int E)
{
    int i = blockIdx.x * blockDim.x + threadIdx.x;
    if (i < E) {
        int l = l_e[i], c = c_e[i];
        src_c[atomicAdd(&cur_c[c], 1)] = l;
        src_l[atomicAdd(&cur_l[l], 1)] = c;
    }
}

// ======================= combined gather-sum =================================
__global__ __launch_bounds__(256)
void gather2(const float* __restrict__ msgA, const int* __restrict__ offA,
             const int* __restrict__ srcA, float* __restrict__ aggrA, int nA,
             const float* __restrict__ msgB, const int* __restrict__ offB,
             const int* __restrict__ srcB, float* __restrict__ aggrB, int nB)
{
    int node = blockIdx.x * 8 + (threadIdx.x >> 5);
    int lane = threadIdx.x & 31;
    const float* msg;
    const int *off, *srcs;
    float* aggr;
    if (node < nA) { msg = msgA; off = offA; srcs = srcA; aggr = aggrA; }
    else {
        node -= nA;
        if (node >= nB) return;
        msg = msgB; off = offB; srcs = srcB; aggr = aggrB;
    }
    int b = off[node], e = off[node + 1];
    float4 acc = {0.f, 0.f, 0.f, 0.f};
    for (int i = b; i < e; i++) {
        const float4 v = *((const float4*)(msg + (size_t)srcs[i] * DIM) + lane);
        acc.x += v.x; acc.y += v.y; acc.z += v.z; acc.w += v.w;
    }
    *((float4*)(aggr + (size_t)node * DIM) + lane) = acc;
}

// ---------------- combined GRU elementwise ------------------------------------
__global__ void gru_elem2x2(const float* __restrict__ rzA, const float* __restrict__ nA,
                            const float* __restrict__ hA, float* __restrict__ hnA, int NA,
                            const float* __restrict__ rzB, const float* __restrict__ nB,
                            const float* __restrict__ hB, float* __restrict__ hnB, int NB)
{
    int idx = blockIdx.x * blockDim.x + threadIdx.x;
    int row = idx >> 5, c4 = (idx & 31) * 4;
    const float *rz, *nbuf, *h;
    float* hnew;
    if (row < NA) { rz = rzA; nbuf = nA; h = hA; hnew = hnA; }
    else {
        row -= NA;
        if (row >= NB) return;
        rz = rzB; nbuf = nB; h = hB; hnew = hnB;
    }
    const float4 r4 = *(const float4*)(rz + (size_t)row * 256 + c4);
    const float4 z4 = *(const float4*)(rz + (size_t)row * 256 + 128 + c4);
    const float4 ni = *(const float4*)(nbuf + (size_t)row * 256 + c4);
    const float4 nh = *(const float4*)(nbuf + (size_t)row * 256 + 128 + c4);
    const float4 h4 = *(const float4*)(h + (size_t)row * 128 + c4);
    float4 o;
    o.x = (1.f - z4.x) * ftanh(ni.x + r4.x * nh.x) + z4.x * h4.x;
    o.y = (1.f - z4.y) * ftanh(ni.y + r4.y * nh.y) + z4.y * h4.y;
    o.z = (1.f - z4.z) * ftanh(ni.z + r4.z * nh.z) + z4.z * h4.z;
    o.w = (1.f - z4.w) * ftanh(ni.w + r4.w * nh.w) + z4.w * h4.w;
    *(float4*)(hnew + (size_t)row * 128 + c4) = o;
}

// ---------------- launch ------------------------------------------------------
extern "C" void kernel_launch(void* const* d_in, const int* in_sizes, int n_in,
                              void* d_out, int out_size)
{
    const int D = DIM;
    const int E = in_sizes[2];
    const int L = in_sizes[4] / D;
    const int C = in_sizes[5] / D;

    const int*   l_edge = (const int*)d_in[2];
    const int*   c_edge = (const int*)d_in[3];
    const float* l_emb0 = (const float*)d_in[4];
    const float* c_emb0 = (const float*)d_in[5];

    const float* l2c_W0 = (const float*)d_in[6];
    const float* l2c_b0 = (const float*)d_in[7];
    const float* l2c_W1 = (const float*)d_in[8];
    const float* l2c_b1 = (const float*)d_in[9];
    const float* c2l_W0 = (const float*)d_in[10];
    const float* c2l_b0 = (const float*)d_in[11];
    const float* c2l_W1 = (const float*)d_in[12];
    const float* c2l_b1 = (const float*)d_in[13];
    const float* l2l_W0 = (const float*)d_in[14];
    const float* l2l_b0 = (const float*)d_in[15];
    const float* l2l_W1 = (const float*)d_in[16];
    const float* l2l_b1 = (const float*)d_in[17];
    const float* c_Wih  = (const float*)d_in[18];
    const float* c_Whh  = (const float*)d_in[19];
    const float* c_bih  = (const float*)d_in[20];
    const float* c_bhh  = (const float*)d_in[21];
    const float* l_Wih  = (const float*)d_in[22];
    const float* l_Whh  = (const float*)d_in[23];
    const float* l_bih  = (const float*)d_in[24];
    const float* l_bhh  = (const float*)d_in[25];

    float* out   = (float*)d_out;
    float* louts = out;                                // [9, L, D]
    float* couts = out + (size_t)(NITER + 1) * L * D;  // [9, C, D]

    float *l2c_msg, *c2l_msg, *l2l_msg, *aggr_c, *aggr_l, *rz_c, *n_c, *rz_l, *n_l;
    cudaGetSymbolAddress((void**)&l2c_msg, g_l2c_msg);
    cudaGetSymbolAddress((void**)&c2l_msg, g_c2l_msg);
    cudaGetSymbolAddress((void**)&l2l_msg, g_l2l_msg);
    cudaGetSymbolAddress((void**)&aggr_c,  g_aggr_c);
    cudaGetSymbolAddress((void**)&aggr_l,  g_aggr_l);
    cudaGetSymbolAddress((void**)&rz_c,    g_rz_c);
    cudaGetSymbolAddress((void**)&n_c,     g_n_c);
    cudaGetSymbolAddress((void**)&rz_l,    g_rz_l);
    cudaGetSymbolAddress((void**)&n_l,     g_n_l);

    int *cnt_c, *cnt_l, *off_c, *off_l, *cur_c, *cur_l, *src_c, *src_l;
    cudaGetSymbolAddress((void**)&cnt_c, g_cnt_c);
    cudaGetSymbolAddress((void**)&cnt_l, g_cnt_l);
    cudaGetSymbolAddress((void**)&off_c, g_off_c);
    cudaGetSymbolAddress((void**)&off_l, g_off_l);
    cudaGetSymbolAddress((void**)&cur_c, g_cur_c);
    cudaGetSymbolAddress((void**)&cur_l, g_cur_l);
    cudaGetSymbolAddress((void**)&src_c, g_src_c);
    cudaGetSymbolAddress((void**)&src_l, g_src_l);

    uint32_t *whi, *wlo;
    cudaGetSymbolAddress((void**)&whi, g_whi);
    cudaGetSymbolAddress((void**)&wlo, g_wlo);

    cudaFuncSetAttribute(mlp2_multi, cudaFuncAttributeMaxDynamicSharedMemorySize,
                         MLP2_DSMEM);
    cudaFuncSetAttribute(gru_gemm_multi, cudaFuncAttributeMaxDynamicSharedMemorySize,
                         GRU_DSMEM);

    const int o_l2c0 = 0,      o_l2c1 = 8192,  o_c2l0 = 16384, o_c2l1 = 24576;
    const int o_l2l0 = 32768,  o_l2l1 = 40960;
    const int o_cih  = 49152,  o_chh  = 73728;
    const int o_lih  = 98304,  o_lhh  = 147456;

    // ---- pre-split weights into fragment-ordered bf16 hi/lo planes ----
    split_w<<<32, 256>>>(l2c_W0, whi + o_l2c0, wlo + o_l2c0, 8192, 64);
    split_w<<<32, 256>>>(l2c_W1, whi + o_l2c1, wlo + o_l2c1, 8192, 64);
    split_w<<<32, 256>>>(c2l_W0, whi + o_c2l0, wlo + o_c2l0, 8192, 64);
    split_w<<<32, 256>>>(c2l_W1, whi + o_c2l1, wlo + o_c2l1, 8192, 64);
    split_w<<<32, 256>>>(l2l_W0, whi + o_l2l0, wlo + o_l2l0, 8192, 64);
    split_w<<<32, 256>>>(l2l_W1, whi + o_l2l1, wlo + o_l2l1, 8192, 64);
    split_w<<<96, 256>>>(c_Wih,  whi + o_cih,  wlo + o_cih,  24576, 64);
    split_w<<<96, 256>>>(c_Whh,  whi + o_chh,  wlo + o_chh,  24576, 64);
    split_w<<<192, 256>>>(l_Wih, whi + o_lih,  wlo + o_lih,  49152, 128);
    split_w<<<96, 256>>>(l_Whh,  whi + o_lhh,  wlo + o_lhh,  24576, 64);

    // ---- CSR build (edge structure static across iterations) ----
    cudaMemsetAsync(cnt_c, 0, (size_t)C * sizeof(int));
    cudaMemsetAsync(cnt_l, 0, (size_t)L * sizeof(int));
    hist2<<<(E + 255) / 256, 256>>>(l_edge, c_edge, cnt_l, cnt_c, E);
    exscan<<<1, 1024>>>(cnt_c, off_c, C);
    exscan<<<1, 1024>>>(cnt_l, off_l, L);
    cudaMemcpyAsync(cur_c, off_c, (size_t)C * sizeof(int), cudaMemcpyDeviceToDevice);
    cudaMemcpyAsync(cur_l, off_l, (size_t)L * sizeof(int), cudaMemcpyDeviceToDevice);
    fill2<<<(E + 255) / 256, 256>>>(l_edge, c_edge, cur_l, cur_c, src_l, src_c, E);

    // iteration-0 slices = inputs
    cudaMemcpyAsync(louts, l_emb0, (size_t)L * D * sizeof(float), cudaMemcpyDeviceToDevice);
    cudaMemcpyAsync(couts, c_emb0, (size_t)C * D * sizeof(float), cudaMemcpyDeviceToDevice);

    const int gLx = (L + 127) / 128;
    const int gCx = (C + 127) / 128;
    const int total_nodes = C + L;
    const dim3 gGemm(gCx + gLx, 4);

    for (int it = 0; it < NITER; it++) {
        const float* l_prev = louts + (size_t)it * L * D;
        const float* c_prev = couts + (size_t)it * C * D;
        float* l_next = louts + (size_t)(it + 1) * L * D;
        float* c_next = couts + (size_t)(it + 1) * C * D;

        // phase 1: all three message MLPs in one launch
        MlpP p0 = {l_prev, whi + o_l2c0, wlo + o_l2c0, l2c_b0,
                   whi + o_l2c1, wlo + o_l2c1, l2c_b1, l2c_msg, L, 0, gLx};
        MlpP p1 = {c_prev, whi + o_c2l0, wlo + o_c2l0, c2l_b0,
                   whi + o_c2l1, wlo + o_c2l1, c2l_b1, c2l_msg, C, 0, gCx};
        MlpP p2 = {l_prev, whi + o_l2l0, wlo + o_l2l0, l2l_b0,
                   whi + o_l2l1, wlo + o_l2l1, l2l_b1, l2l_msg, L, 1, gLx};
        mlp2_multi<<<gLx + gCx + gLx, 256, MLP2_DSMEM>>>(p0, p1, p2);

        // phase 2: both gathers in one launch
        gather2<<<(total_nodes + 7) / 8, 256>>>(l2c_msg, off_c, src_c, aggr_c, C,
                                                c2l_msg, off_l, src_l, aggr_l, L);

        // phase 3: all GRU gate GEMMs in one launch
        GruP pc = {aggr_c, nullptr, 8, 0,
                   whi + o_cih, wlo + o_cih, whi + o_chh, wlo + o_chh,
                   c_bih, c_bhh, c_prev, rz_c, n_c, C, gCx};
        GruP pl = {aggr_l, l2l_msg, 8, 8,
                   whi + o_lih, wlo + o_lih, whi + o_lhh, wlo + o_lhh,
                   l_bih, l_bhh, l_prev, rz_l, n_l, L, gLx};
        gru_gemm_multi<<<gGemm, 256, GRU_DSMEM>>>(pc, pl);

        // phase 4: both elementwise GRU updates in one launch
        gru_elem2x2<<<(total_nodes * 32 + 255) / 256, 256>>>(
            rz_c, n_c, c_prev, c_next, C,
            rz_l, n_l, l_prev, l_next, L);
    }
}

// round 13
// speedup vs baseline: 1.3190x; 1.0706x over previous
#include <cuda_runtime.h>
#include <cuda_bf16.h>
#include <cstdint>

// Problem constants (fixed by setup_inputs)
#define DIM   128
#define LMAX  60000
#define CMAX  30000
#define EMAX  360000
#define NITER 8

#define CBLK ((CMAX + 127) / 128)           // 235
#define LBLK ((LMAX + 127) / 128)           // 469
#define CPLANE ((size_t)CBLK * 8192)        // u32 per clause plane
#define LPLANE ((size_t)LBLK * 8192)        // u32 per literal plane

// ---------------- scratch (device globals; no allocations allowed) ----------
__device__ float g_l2c_msg[(size_t)LMAX * DIM];
__device__ float g_c2l_msg[(size_t)CMAX * DIM];
__device__ float g_rz_c   [(size_t)CMAX * 2 * DIM];
__device__ float g_n_c    [(size_t)CMAX * 2 * DIM];
__device__ float g_rz_l   [(size_t)LMAX * 2 * DIM];
__device__ float g_n_l    [(size_t)LMAX * 2 * DIM];
// fragment-ordered bf16 activation planes (u32 = 2 bf16)
__device__ uint32_t g_ac_hi[CPLANE],  g_ac_lo[CPLANE];    // clause aggr
__device__ uint32_t g_al_hi[LPLANE],  g_al_lo[LPLANE];    // literal aggr
__device__ uint32_t g_m_hi [LPLANE],  g_m_lo [LPLANE];    // l2l message
__device__ uint32_t g_hc_hi[CPLANE],  g_hc_lo[CPLANE];    // clause state
__device__ uint32_t g_hl_hi[LPLANE],  g_hl_lo[LPLANE];    // literal state
// CSR scratch
__device__ int g_cnt_c[CMAX];
__device__ int g_cnt_l[LMAX];
__device__ int g_off_c[CMAX + 1];
__device__ int g_off_l[LMAX + 1];
__device__ int g_cur_c[CMAX];
__device__ int g_cur_l[LMAX];
__device__ int g_src_c[EMAX];
__device__ int g_src_l[EMAX];
// pre-split bf16 weight planes
#define WSPLIT_TOTAL 172032
__device__ uint32_t g_whi[WSPLIT_TOTAL];
__device__ uint32_t g_wlo[WSPLIT_TOTAL];

// ======================= helpers =============================================
__device__ __forceinline__ uint32_t smem_u32(const void* p) {
    uint32_t a;
    asm("{ .reg .u64 t; cvta.to.shared.u64 t, %1; cvt.u32.u64 %0, t; }"
        : "=r"(a) : "l"(p));
    return a;
}

__device__ __forceinline__ uint32_t pack_bf16(float lo, float hi) {
    uint32_t r;
    asm("cvt.rn.bf16x2.f32 %0, %1, %2;" : "=r"(r) : "f"(hi), "f"(lo));
    return r;
}

__device__ __forceinline__ void split2(float x, float y, uint32_t& hi, uint32_t& lo) {
    uint32_t h = pack_bf16(x, y);
    float hx = __uint_as_float(h << 16);
    float hy = __uint_as_float(h & 0xffff0000u);
    hi = h;
    lo = pack_bf16(x - hx, y - hy);
}

__device__ __forceinline__ void cp16(uint32_t dst, const void* src) {
    asm volatile("cp.async.ca.shared.global [%0], [%1], 16;"
                 :: "r"(dst), "l"(src) : "memory");
}
#define CP_COMMIT() asm volatile("cp.async.commit_group;" ::: "memory")
#define CP_WAIT0()  asm volatile("cp.async.wait_group 0;" ::: "memory")
#define CP_WAIT1()  asm volatile("cp.async.wait_group 1;" ::: "memory")

__device__ __forceinline__ void mma_bf16(float* d, const uint32_t* a,
                                         uint32_t b0, uint32_t b1) {
    asm volatile(
        "mma.sync.aligned.m16n8k16.row.col.f32.bf16.bf16.f32 "
        "{%0,%1,%2,%3}, {%4,%5,%6,%7}, {%8,%9}, {%0,%1,%2,%3};"
        : "+f"(d[0]), "+f"(d[1]), "+f"(d[2]), "+f"(d[3])
        : "r"(a[0]), "r"(a[1]), "r"(a[2]), "r"(a[3]), "r"(b0), "r"(b1));
}

#define IDX(r, q) ((((r) << 3)) | ((q) ^ ((r) & 7)))

__device__ __forceinline__ float fsigmoid(float x) { return 1.f / (1.f + __expf(-x)); }
__device__ __forceinline__ float ftanh(float x) {
    float t = __expf(2.f * fabsf(x));
    float r = 1.f - 2.f / (t + 1.f);
    return copysignf(r, x);
}

// ======================= weight pre-split (fragment-ordered) =================
__global__ void split_w(const float* __restrict__ W, uint32_t* __restrict__ hi,
                        uint32_t* __restrict__ lo, int total_pairs, int kp)
{
    int i = blockIdx.x * 256 + threadIdx.x;
    if (i >= total_pairs) return;
    int R = i / kp, p = i - R * kp;
    float2 f = ((const float2*)W)[i];
    uint32_t h, l;
    split2(f.x, f.y, h, l);
    int ngroup = R >> 7, n = R & 127;
    int ch = p >> 3, q = p & 7;
    int nt = n >> 3, l4 = n & 7;
    int region = l4 * 4 + (q & 3);
    int idx = region * 32 + (((nt >> 1) ^ (region & 7)) << 2) + ((nt & 1) << 1) + (q >> 2);
    size_t base = ((size_t)(ngroup * (kp >> 3) + ch)) << 10;
    hi[base + idx] = h;
    lo[base + idx] = l;
}

// ======================= activation pre-split (row-fragment planes) ==========
// X [N,128] fp32 -> hi/lo planes: per 128-row block, per K16 chunk, 1024 u32
// at [blk*8 + chunk] << 10, index IDX(row&127, q).
__global__ void split_act(const float* __restrict__ X, uint32_t* __restrict__ hi,
                          uint32_t* __restrict__ lo, int N)
{
    int i = blockIdx.x * 256 + threadIdx.x;
    if (i >= N * 64) return;
    int row = i >> 6, pp = i & 63;
    float2 f = ((const float2*)X)[i];
    uint32_t h, l;
    split2(f.x, f.y, h, l);
    int chunk = pp >> 3, q = pp & 7, rl = row & 127;
    size_t base = ((size_t)((row >> 7) * 8 + chunk)) << 10;
    hi[base + IDX(rl, q)] = h;
    lo[base + IDX(rl, q)] = l;
}

// ======================= MMA K16 sub-chunk ===================================
__device__ __forceinline__ void mma_chunk(const uint32_t* __restrict__ A,
                                          const uint32_t* __restrict__ B,
                                          float (&acc)[16][4], int lane, int wid)
{
    const uint32_t* Ah = A;
    const uint32_t* Al = A + 1024;
    const int r = wid * 16 + (lane >> 2);
    const int q = lane & 3;
    uint32_t ah[4], al[4];
    ah[0] = Ah[IDX(r, q)];     ah[1] = Ah[IDX(r + 8, q)];
    ah[2] = Ah[IDX(r, q + 4)]; ah[3] = Ah[IDX(r + 8, q + 4)];
    al[0] = Al[IDX(r, q)];     al[1] = Al[IDX(r + 8, q)];
    al[2] = Al[IDX(r, q + 4)]; al[3] = Al[IDX(r + 8, q + 4)];
    const uint32_t* Bh = B + lane * 32;
    const uint32_t* Bl = Bh + 1024;
#pragma unroll
    for (int c = 0; c < 8; c++) {
        const int sw = ((c ^ (lane & 7)) << 2);
        uint4 vh = *(const uint4*)(Bh + sw);
        uint4 vl = *(const uint4*)(Bl + sw);
        mma_bf16(acc[2 * c],     ah, vh.x, vh.y);
        mma_bf16(acc[2 * c + 1], ah, vh.z, vh.w);
        mma_bf16(acc[2 * c],     al, vh.x, vh.y);
        mma_bf16(acc[2 * c + 1], al, vh.z, vh.w);
        mma_bf16(acc[2 * c],     ah, vl.x, vl.y);
        mma_bf16(acc[2 * c + 1], ah, vl.z, vl.w);
    }
}

// ======================= param structs =======================================
struct MlpP {
    const float* A0;
    const uint32_t *W0h, *W0l;
    const float* b0;
    const uint32_t *W1h, *W1l;
    const float* b1;
    float* out;                 // fp32 output (may be null)
    uint32_t *ohi, *olo;        // plane output (may be null)
    int N, perm, gx;
};

struct GruP {
    const uint32_t *S0h, *S0l, *S1h, *S1l, *Hh, *Hl;
    int n0, n1;                 // K16 units of S0, S1
    const uint32_t *Wih_h, *Wih_l, *Whh_h, *Whh_l;
    const float *bih, *bhh;
    float *rz, *nbuf;
    int N, gx;
};

// K32 A-store for the MLP (stage-1 only): row = t>>1, 16-float half sub = t&1.
#define STA_K32(Sbase) do { \
        uint32_t* Ah = (Sbase); \
        uint32_t* Al = Ah + 1024; \
        uint32_t h0, l0; \
        split2(ra0.x, ra0.y, h0, l0); Ah[IDX(row, 0)] = h0; Al[IDX(row, 0)] = l0; \
        split2(ra0.z, ra0.w, h0, l0); Ah[IDX(row, 1)] = h0; Al[IDX(row, 1)] = l0; \
        split2(ra1.x, ra1.y, h0, l0); Ah[IDX(row, 2)] = h0; Al[IDX(row, 2)] = l0; \
        split2(ra1.z, ra1.w, h0, l0); Ah[IDX(row, 3)] = h0; Al[IDX(row, 3)] = l0; \
        split2(ra2.x, ra2.y, h0, l0); Ah[IDX(row, 4)] = h0; Al[IDX(row, 4)] = l0; \
        split2(ra2.z, ra2.w, h0, l0); Ah[IDX(row, 5)] = h0; Al[IDX(row, 5)] = l0; \
        split2(ra3.x, ra3.y, h0, l0); Ah[IDX(row, 6)] = h0; Al[IDX(row, 6)] = l0; \
        split2(ra3.z, ra3.w, h0, l0); Ah[IDX(row, 7)] = h0; Al[IDX(row, 7)] = l0; \
    } while (0)

// ======================= combined fused 2-layer MLP (occ 2, K32 chunks) ======
#define MLP2_DSMEM (24576 * 4)

__global__ __launch_bounds__(256, 2)
void mlp2_multi(MlpP p0, MlpP p1, MlpP p2)
{
    extern __shared__ __align__(16) uint32_t sm[];
    __shared__ float sb0[128];

    int bx = blockIdx.x;
    MlpP p;
    if (bx < p0.gx) { p = p0; }
    else if (bx < p0.gx + p1.gx) { p = p1; bx -= p0.gx; }
    else { p = p2; bx -= p0.gx + p1.gx; }

    const int t = threadIdx.x, lane = t & 31, wid = t >> 5;
    const int m0 = bx * 128;

    if (t < 128) sb0[t] = p.b0[t];

    float acc1[16][4];
#pragma unroll
    for (int i = 0; i < 16; i++)
#pragma unroll
        for (int j = 0; j < 4; j++) acc1[i][j] = 0.f;

    const int row = t >> 1;
    const int sub = t & 1;
    const int grow = m0 + row;
    int arow = (p.perm ? (grow ^ 1) : grow);
    if (grow >= p.N) arow = 0;
    float4 ra0, ra1, ra2, ra3;

    const int wrow = t & 127;
    const int wpl = t >> 7;
    const uint32_t* w0p = wpl ? p.W0l : p.W0h;
    const uint32_t* w1p = wpl ? p.W1l : p.W1h;

#define LDA1(ch) do { \
        const float* pp = p.A0 + (size_t)arow * 128 + ((ch) << 5) + sub * 16; \
        ra0 = *(const float4*)pp;       ra1 = *(const float4*)(pp + 4); \
        ra2 = *(const float4*)(pp + 8); ra3 = *(const float4*)(pp + 12); \
    } while (0)
#define CPW1(wb, ch, buf) do { \
        _Pragma("unroll") \
        for (int si = 0; si < 2; si++) { \
            const uint32_t* gp = (wb) + ((size_t)(2 * (ch) + si) << 10) + wrow * 8; \
            uint32_t daddr = smem_u32(sm + (buf) * 8192 + si * 4096 + 2048 + wpl * 1024 + wrow * 8); \
            cp16(daddr, gp); cp16(daddr + 16, gp + 4); \
        } \
    } while (0)
#define CPW2(ch, buf) do { \
        _Pragma("unroll") \
        for (int si = 0; si < 2; si++) { \
            const uint32_t* gp = w1p + ((size_t)(2 * (ch) + si) << 10) + wrow * 8; \
            uint32_t daddr = smem_u32(sm + 16384 + (buf) * 4096 + si * 2048 + wpl * 1024 + wrow * 8); \
            cp16(daddr, gp); cp16(daddr + 16, gp + 4); \
        } \
    } while (0)

    // ---- stage 1: 4 K32 chunks, 2-deep ring ----
    LDA1(0); CPW1(w0p, 0, 0); CP_COMMIT();
    STA_K32(sm + 0 * 8192 + sub * 4096);
    LDA1(1);
    CP_WAIT0(); __syncthreads();
    for (int ch = 0; ch < 4; ch++) {
        if (ch + 1 < 4) {
            const int nb = (ch + 1) & 1;
            CPW1(w0p, ch + 1, nb); CP_COMMIT();
            STA_K32(sm + nb * 8192 + sub * 4096);
        }
        if (ch + 2 < 4) LDA1(ch + 2);
        const uint32_t* S = sm + (ch & 1) * 8192;
        mma_chunk(S,        S + 2048, acc1, lane, wid);
        mma_chunk(S + 4096, S + 6144, acc1, lane, wid);
        if (ch + 1 < 4) { CP_WAIT0(); __syncthreads(); }
    }
    __syncthreads();

    // ---- bias + relu, spill stage-1 result into A region (pre-split) ----
    {
        const int rlo = wid * 16 + (lane >> 2);
        const int rhi = rlo + 8;
#pragma unroll
        for (int nt = 0; nt < 16; nt++) {
            const int col = nt * 8 + 2 * (lane & 3);
            float bx2 = sb0[col], by = sb0[col + 1];
            float v0 = fmaxf(acc1[nt][0] + bx2, 0.f);
            float v1 = fmaxf(acc1[nt][1] + by, 0.f);
            float v2 = fmaxf(acc1[nt][2] + bx2, 0.f);
            float v3 = fmaxf(acc1[nt][3] + by, 0.f);
            const int ch16 = nt >> 1;
            const int q = (nt & 1) * 4 + (lane & 3);
            uint32_t h, l;
            split2(v0, v1, h, l);
            sm[ch16 * 2048 + IDX(rlo, q)] = h;
            sm[ch16 * 2048 + 1024 + IDX(rlo, q)] = l;
            split2(v2, v3, h, l);
            sm[ch16 * 2048 + IDX(rhi, q)] = h;
            sm[ch16 * 2048 + 1024 + IDX(rhi, q)] = l;
        }
    }

    float acc2[16][4];
#pragma unroll
    for (int i = 0; i < 16; i++)
#pragma unroll
        for (int j = 0; j < 4; j++) acc2[i][j] = 0.f;

    // ---- stage 2: A from smem region, W1 streamed, 4 K32 chunks ----
    CPW2(0, 0); CP_COMMIT();
    CP_WAIT0(); __syncthreads();   // also publishes the spill
    for (int ch = 0; ch < 4; ch++) {
        if (ch + 1 < 4) { CPW2(ch + 1, (ch + 1) & 1); CP_COMMIT(); }
        const uint32_t* B = sm + 16384 + (ch & 1) * 4096;
        mma_chunk(sm + (2 * ch) * 2048,     B,        acc2, lane, wid);
        mma_chunk(sm + (2 * ch + 1) * 2048, B + 2048, acc2, lane, wid);
        if (ch + 1 < 4) { CP_WAIT0(); __syncthreads(); }
    }

    // ---- epilogue: fp32 or fragment-plane output ----
    const int rl0 = wid * 16 + (lane >> 2);
    const int rl1 = rl0 + 8;
    if (p.ohi) {
#pragma unroll
        for (int nt = 0; nt < 16; nt++) {
            const int col = nt * 8 + 2 * (lane & 3);
            float bx2 = p.b1[col], by = p.b1[col + 1];
            float v0 = acc2[nt][0] + bx2, v1 = acc2[nt][1] + by;
            float v2 = acc2[nt][2] + bx2, v3 = acc2[nt][3] + by;
            const int pq = nt * 4 + (lane & 3);
            const int chunk = pq >> 3, q = pq & 7;
            const size_t base = ((size_t)(bx * 8 + chunk)) << 10;
            uint32_t h, l;
            split2(v0, v1, h, l);
            p.ohi[base + IDX(rl0, q)] = h;
            p.olo[base + IDX(rl0, q)] = l;
            split2(v2, v3, h, l);
            p.ohi[base + IDX(rl1, q)] = h;
            p.olo[base + IDX(rl1, q)] = l;
        }
    } else {
        const int r0 = m0 + rl0;
#pragma unroll
        for (int nt = 0; nt < 16; nt++) {
            const int col = nt * 8 + 2 * (lane & 3);
            float bx2 = p.b1[col], by = p.b1[col + 1];
            if (r0 < p.N)
                *(float2*)(p.out + (size_t)r0 * 128 + col) =
                    make_float2(acc2[nt][0] + bx2, acc2[nt][1] + by);
            if (r0 + 8 < p.N)
                *(float2*)(p.out + (size_t)(r0 + 8) * 128 + col) =
                    make_float2(acc2[nt][2] + bx2, acc2[nt][3] + by);
        }
    }
#undef LDA1
#undef CPW1
#undef CPW2
}

// ======================= combined GRU gate GEMM (all-async A+B) ==============
// grid (pc.gx + pl.gx, 4). y: 0=r, 1=z (sigmoid -> rz), 2=n_input, 3=n_hidden (-> nbuf)
#define GRU_DSMEM (3 * 8192 * 4)

__global__ __launch_bounds__(256, 2)
void gru_gemm_multi(GruP pc, GruP pl)
{
    extern __shared__ __align__(16) uint32_t sm[];

    int bx = blockIdx.x;
    GruP p;
    if (bx < pc.gx) { p = pc; }
    else { p = pl; bx -= pc.gx; }

    const int t = threadIdx.x, lane = t & 31, wid = t >> 5;
    const int m0 = bx * 128;
    const int g  = blockIdx.y;
    const int nchi = p.n0 + p.n1;
    const int nch32 = (g < 2) ? (nchi + 8) >> 1 : (g == 2 ? nchi >> 1 : 4);
    const int blk8 = bx * 8;

    float acc[16][4];
#pragma unroll
    for (int i = 0; i < 16; i++)
#pragma unroll
        for (int j = 0; j < 4; j++) acc[i][j] = 0.f;

    const int wrow = t & 127;
    const int wpl = t >> 7;
    const uint32_t* pih = wpl ? p.Wih_l : p.Wih_h;
    const uint32_t* phh = wpl ? p.Whh_l : p.Whh_h;

#define CPA(ch, buf) do { \
        _Pragma("unroll") \
        for (int si = 0; si < 2; si++) { \
            const int c16 = 2 * (ch) + si; \
            const uint32_t* sp; int cl; \
            if (g == 3)            { sp = wpl ? p.Hl  : p.Hh;  cl = c16; } \
            else if (c16 < p.n0)   { sp = wpl ? p.S0l : p.S0h; cl = c16; } \
            else if (c16 < nchi)   { sp = wpl ? p.S1l : p.S1h; cl = c16 - p.n0; } \
            else                   { sp = wpl ? p.Hl  : p.Hh;  cl = c16 - nchi; } \
            const uint32_t* gp = sp + ((size_t)(blk8 + cl) << 10) + wrow * 8; \
            uint32_t daddr = smem_u32(sm + (buf) * 8192 + si * 4096 + wpl * 1024 + wrow * 8); \
            cp16(daddr, gp); cp16(daddr + 16, gp + 4); \
        } \
    } while (0)
#define CPW(ch, buf) do { \
        _Pragma("unroll") \
        for (int si = 0; si < 2; si++) { \
            const int c16 = 2 * (ch) + si; \
            const uint32_t* gp; \
            if (g < 2) gp = (c16 < nchi) \
                ? pih + (((size_t)(g * nchi + c16)) << 10) + wrow * 8 \
                : phh + (((size_t)(g * 8 + c16 - nchi)) << 10) + wrow * 8; \
            else if (g == 2) gp = pih + (((size_t)(2 * nchi + c16)) << 10) + wrow * 8; \
            else gp = phh + (((size_t)(16 + c16)) << 10) + wrow * 8; \
            uint32_t daddr = smem_u32(sm + (buf) * 8192 + si * 4096 + 2048 + wpl * 1024 + wrow * 8); \
            cp16(daddr, gp); cp16(daddr + 16, gp + 4); \
        } \
    } while (0)

    CPA(0, 0); CPW(0, 0); CP_COMMIT();
    if (nch32 > 1) { CPA(1, 1); CPW(1, 1); CP_COMMIT(); CP_WAIT1(); }
    else CP_WAIT0();
    __syncthreads();
    for (int ch = 0; ch < nch32; ch++) {
        if (ch + 2 < nch32) { CPA(ch + 2, (ch + 2) % 3); CPW(ch + 2, (ch + 2) % 3); CP_COMMIT(); }
        const uint32_t* S = sm + (ch % 3) * 8192;
        mma_chunk(S,        S + 2048, acc, lane, wid);
        mma_chunk(S + 4096, S + 6144, acc, lane, wid);
        if (ch + 1 < nch32) {
            if (ch + 2 < nch32) CP_WAIT1(); else CP_WAIT0();
            __syncthreads();
        }
    }

    const int r0 = m0 + wid * 16 + (lane >> 2);
    if (g < 2) {
#pragma unroll
        for (int nt = 0; nt < 16; nt++) {
            const int col = nt * 8 + 2 * (lane & 3);
            float bx2 = p.bih[g * 128 + col]     + p.bhh[g * 128 + col];
            float by  = p.bih[g * 128 + col + 1] + p.bhh[g * 128 + col + 1];
            if (r0 < p.N)
                *(float2*)(p.rz + (size_t)r0 * 256 + g * 128 + col) =
                    make_float2(fsigmoid(acc[nt][0] + bx2), fsigmoid(acc[nt][1] + by));
            if (r0 + 8 < p.N)
                *(float2*)(p.rz + (size_t)(r0 + 8) * 256 + g * 128 + col) =
                    make_float2(fsigmoid(acc[nt][2] + bx2), fsigmoid(acc[nt][3] + by));
        }
    } else {
        const float* bs = (g == 2) ? p.bih : p.bhh;
        const int go = (g - 2) * 128;
#pragma unroll
        for (int nt = 0; nt < 16; nt++) {
            const int col = nt * 8 + 2 * (lane & 3);
            float bx2 = bs[256 + col], by = bs[256 + col + 1];
            if (r0 < p.N)
                *(float2*)(p.nbuf + (size_t)r0 * 256 + go + col) =
                    make_float2(acc[nt][0] + bx2, acc[nt][1] + by);
            if (r0 + 8 < p.N)
                *(float2*)(p.nbuf + (size_t)(r0 + 8) * 256 + go + col) =
                    make_float2(acc[nt][2] + bx2, acc[nt][3] + by);
        }
    }
#undef CPA
#undef CPW
}

// ======================= CSR build ===========================================
__global__ void hist2(const int* __restrict__ l_e, const int* __restrict__ c_e,
                      int* __restrict__ cnt_l, int* __restrict__ cnt_c, int E)
{
    int i = blockIdx.x * blockDim.x + threadIdx.x;
    if (i < E) {
        atomicAdd(&cnt_l[l_e[i]], 1);
        atomicAdd(&cnt_c[c_e[i]], 1);
    }
}

__global__ void exscan(const int* __restrict__ cnt, int* __restrict__ off, int n)
{
    __shared__ int part[1024];
    const int t = threadIdx.x;
    const int chunk = (n + 1023) >> 10;
    const int b = t * chunk;
    const int e = min(b + chunk, n);
    int s = 0;
    for (int i = b; i < e; i++) s += cnt[i];
    part[t] = s;
    __syncthreads();
    for (int d = 1; d < 1024; d <<= 1) {
        int v = (t >= d) ? part[t - d] : 0;
        __syncthreads();
        if (t >= d) part[t] += v;
        __syncthreads();
    }
    int run = (t == 0) ? 0 : part[t - 1];
    for (int i = b; i < e; i++) { off[i] = run; run += cnt[i]; }
    if (t == 0) off[n] = part[1023];
}

__global__ void fill2(const int* __restrict__ l_e, const int* __restrict__ c_e,
                      int* __restrict__ cur_l, int* __restrict__ cur_c,
                      int* __restrict__ src_l, int* __restrict__ src_c, int E)
{
    int i = blockIdx.x * blockDim.x + threadIdx.x;
    if (i < E) {
        int l = l_e[i], c = c_e[i];
        src_c[atomicAdd(&cur_c[c], 1)] = l;
        src_l[atomicAdd(&cur_l[l], 1)] = c;
    }
}

// ======================= combined gather-sum (writes planes) =================
__global__ __launch_bounds__(256)
void gather2(const float* __restrict__ msgA, const int* __restrict__ offA,
             const int* __restrict__ srcA,
             uint32_t* __restrict__ aHiA, uint32_t* __restrict__ aLoA, int nA,
             const float* __restrict__ msgB, const int* __restrict__ offB,
             const int* __restrict__ srcB,
             uint32_t* __restrict__ aHiB, uint32_t* __restrict__ aLoB, int nB)
{
    int node = blockIdx.x * 8 + (threadIdx.x >> 5);
    int lane = threadIdx.x & 31;
    const float* msg;
    const int *off, *srcs;
    uint32_t *aHi, *aLo;
    if (node < nA) { msg = msgA; off = offA; srcs = srcA; aHi = aHiA; aLo = aLoA; }
    else {
        node -= nA;
        if (node >= nB) return;
        msg = msgB; off = offB; srcs = srcB; aHi = aHiB; aLo = aLoB;
    }
    int b = off[node], e = off[node + 1];
    float4 acc = {0.f, 0.f, 0.f, 0.f};
    for (int i = b; i < e; i++) {
        const float4 v = *((const float4*)(msg + (size_t)srcs[i] * DIM) + lane);
        acc.x += v.x; acc.y += v.y; acc.z += v.z; acc.w += v.w;
    }
    const int rl = node & 127;
    const int chunk = lane >> 2;
    const int q0 = (2 * lane) & 7;
    const size_t base = ((size_t)((node >> 7) * 8 + chunk)) << 10;
    uint32_t h, l;
    split2(acc.x, acc.y, h, l);
    aHi[base + IDX(rl, q0)] = h;
    aLo[base + IDX(rl, q0)] = l;
    split2(acc.z, acc.w, h, l);
    aHi[base + IDX(rl, q0 + 1)] = h;
    aLo[base + IDX(rl, q0 + 1)] = l;
}

// ---------------- combined GRU elementwise (writes fp32 + planes) ------------
__global__ void gru_elem2x2(const float* __restrict__ rzA, const float* __restrict__ nA,
                            const float* __restrict__ hA, float* __restrict__ hnA,
                            uint32_t* __restrict__ hiA, uint32_t* __restrict__ loA, int NA,
                            const float* __restrict__ rzB, const float* __restrict__ nB,
                            const float* __restrict__ hB, float* __restrict__ hnB,
                            uint32_t* __restrict__ hiB, uint32_t* __restrict__ loB, int NB)
{
    int idx = blockIdx.x * blockDim.x + threadIdx.x;
    int row = idx >> 5, c4 = (idx & 31) * 4;
    const float *rz, *nbuf, *h;
    float* hnew;
    uint32_t *phi, *plo;
    if (row < NA) { rz = rzA; nbuf = nA; h = hA; hnew = hnA; phi = hiA; plo = loA; }
    else {
        row -= NA;
        if (row >= NB) return;
        rz = rzB; nbuf = nB; h = hB; hnew = hnB; phi = hiB; plo = loB;
    }
    const float4 r4 = *(const float4*)(rz + (size_t)row * 256 + c4);
    const float4 z4 = *(const float4*)(rz + (size_t)row * 256 + 128 + c4);
    const float4 ni = *(const float4*)(nbuf + (size_t)row * 256 + c4);
    const float4 nh = *(const float4*)(nbuf + (size_t)row * 256 + 128 + c4);
    const float4 h4 = *(const float4*)(h + (size_t)row * 128 + c4);
    float4 o;
    o.x = (1.f - z4.x) * ftanh(ni.x + r4.x * nh.x) + z4.x * h4.x;
    o.y = (1.f - z4.y) * ftanh(ni.y + r4.y * nh.y) + z4.y * h4.y;
    o.z = (1.f - z4.z) * ftanh(ni.z + r4.z * nh.z) + z4.z * h4.z;
    o.w = (1.f - z4.w) * ftanh(ni.w + r4.w * nh.w) + z4.w * h4.w;
    *(float4*)(hnew + (size_t)row * 128 + c4) = o;
    // plane write
    const int rl = row & 127;
    const int pq = c4 >> 1;                 // even
    const int q0 = pq & 7;
    const size_t base = ((size_t)((row >> 7) * 8 + (c4 >> 4))) << 10;
    uint32_t hh, ll;
    split2(o.x, o.y, hh, ll);
    phi[base + IDX(rl, q0)] = hh;
    plo[base + IDX(rl, q0)] = ll;
    split2(o.z, o.w, hh, ll);
    phi[base + IDX(rl, q0 + 1)] = hh;
    plo[base + IDX(rl, q0 + 1)] = ll;
}

// ---------------- launch ------------------------------------------------------
extern "C" void kernel_launch(void* const* d_in, const int* in_sizes, int n_in,
                              void* d_out, int out_size)
{
    const int D = DIM;
    const int E = in_sizes[2];
    const int L = in_sizes[4] / D;
    const int C = in_sizes[5] / D;

    const int*   l_edge = (const int*)d_in[2];
    const int*   c_edge = (const int*)d_in[3];
    const float* l_emb0 = (const float*)d_in[4];
    const float* c_emb0 = (const float*)d_in[5];

    const float* l2c_W0 = (const float*)d_in[6];
    const float* l2c_b0 = (const float*)d_in[7];
    const float* l2c_W1 = (const float*)d_in[8];
    const float* l2c_b1 = (const float*)d_in[9];
    const float* c2l_W0 = (const float*)d_in[10];
    const float* c2l_b0 = (const float*)d_in[11];
    const float* c2l_W1 = (const float*)d_in[12];
    const float* c2l_b1 = (const float*)d_in[13];
    const float* l2l_W0 = (const float*)d_in[14];
    const float* l2l_b0 = (const float*)d_in[15];
    const float* l2l_W1 = (const float*)d_in[16];
    const float* l2l_b1 = (const float*)d_in[17];
    const float* c_Wih  = (const float*)d_in[18];
    const float* c_Whh  = (const float*)d_in[19];
    const float* c_bih  = (const float*)d_in[20];
    const float* c_bhh  = (const float*)d_in[21];
    const float* l_Wih  = (const float*)d_in[22];
    const float* l_Whh  = (const float*)d_in[23];
    const float* l_bih  = (const float*)d_in[24];
    const float* l_bhh  = (const float*)d_in[25];

    float* out   = (float*)d_out;
    float* louts = out;                                // [9, L, D]
    float* couts = out + (size_t)(NITER + 1) * L * D;  // [9, C, D]

    float *l2c_msg, *c2l_msg, *rz_c, *n_c, *rz_l, *n_l;
    cudaGetSymbolAddress((void**)&l2c_msg, g_l2c_msg);
    cudaGetSymbolAddress((void**)&c2l_msg, g_c2l_msg);
    cudaGetSymbolAddress((void**)&rz_c,    g_rz_c);
    cudaGetSymbolAddress((void**)&n_c,     g_n_c);
    cudaGetSymbolAddress((void**)&rz_l,    g_rz_l);
    cudaGetSymbolAddress((void**)&n_l,     g_n_l);

    uint32_t *ac_hi, *ac_lo, *al_hi, *al_lo, *m_hi, *m_lo, *hc_hi, *hc_lo, *hl_hi, *hl_lo;
    cudaGetSymbolAddress((void**)&ac_hi, g_ac_hi);
    cudaGetSymbolAddress((void**)&ac_lo, g_ac_lo);
    cudaGetSymbolAddress((void**)&al_hi, g_al_hi);
    cudaGetSymbolAddress((void**)&al_lo, g_al_lo);
    cudaGetSymbolAddress((void**)&m_hi,  g_m_hi);
    cudaGetSymbolAddress((void**)&m_lo,  g_m_lo);
    cudaGetSymbolAddress((void**)&hc_hi, g_hc_hi);
    cudaGetSymbolAddress((void**)&hc_lo, g_hc_lo);
    cudaGetSymbolAddress((void**)&hl_hi, g_hl_hi);
    cudaGetSymbolAddress((void**)&hl_lo, g_hl_lo);

    int *cnt_c, *cnt_l, *off_c, *off_l, *cur_c, *cur_l, *src_c, *src_l;
    cudaGetSymbolAddress((void**)&cnt_c, g_cnt_c);
    cudaGetSymbolAddress((void**)&cnt_l, g_cnt_l);
    cudaGetSymbolAddress((void**)&off_c, g_off_c);
    cudaGetSymbolAddress((void**)&off_l, g_off_l);
    cudaGetSymbolAddress((void**)&cur_c, g_cur_c);
    cudaGetSymbolAddress((void**)&cur_l, g_cur_l);
    cudaGetSymbolAddress((void**)&src_c, g_src_c);
    cudaGetSymbolAddress((void**)&src_l, g_src_l);

    uint32_t *whi, *wlo;
    cudaGetSymbolAddress((void**)&whi, g_whi);
    cudaGetSymbolAddress((void**)&wlo, g_wlo);

    cudaFuncSetAttribute(mlp2_multi, cudaFuncAttributeMaxDynamicSharedMemorySize,
                         MLP2_DSMEM);
    cudaFuncSetAttribute(gru_gemm_multi, cudaFuncAttributeMaxDynamicSharedMemorySize,
                         GRU_DSMEM);

    const int o_l2c0 = 0,      o_l2c1 = 8192,  o_c2l0 = 16384, o_c2l1 = 24576;
    const int o_l2l0 = 32768,  o_l2l1 = 40960;
    const int o_cih  = 49152,  o_chh  = 73728;
    const int o_lih  = 98304,  o_lhh  = 147456;

    // ---- pre-split weights ----
    split_w<<<32, 256>>>(l2c_W0, whi + o_l2c0, wlo + o_l2c0, 8192, 64);
    split_w<<<32, 256>>>(l2c_W1, whi + o_l2c1, wlo + o_l2c1, 8192, 64);
    split_w<<<32, 256>>>(c2l_W0, whi + o_c2l0, wlo + o_c2l0, 8192, 64);
    split_w<<<32, 256>>>(c2l_W1, whi + o_c2l1, wlo + o_c2l1, 8192, 64);
    split_w<<<32, 256>>>(l2l_W0, whi + o_l2l0, wlo + o_l2l0, 8192, 64);
    split_w<<<32, 256>>>(l2l_W1, whi + o_l2l1, wlo + o_l2l1, 8192, 64);
    split_w<<<96, 256>>>(c_Wih,  whi + o_cih,  wlo + o_cih,  24576, 64);
    split_w<<<96, 256>>>(c_Whh,  whi + o_chh,  wlo + o_chh,  24576, 64);
    split_w<<<192, 256>>>(l_Wih, whi + o_lih,  wlo + o_lih,  49152, 128);
    split_w<<<96, 256>>>(l_Whh,  whi + o_lhh,  wlo + o_lhh,  24576, 64);

    // ---- CSR build ----
    cudaMemsetAsync(cnt_c, 0, (size_t)C * sizeof(int));
    cudaMemsetAsync(cnt_l, 0, (size_t)L * sizeof(int));
    hist2<<<(E + 255) / 256, 256>>>(l_edge, c_edge, cnt_l, cnt_c, E);
    exscan<<<1, 1024>>>(cnt_c, off_c, C);
    exscan<<<1, 1024>>>(cnt_l, off_l, L);
    cudaMemcpyAsync(cur_c, off_c, (size_t)C * sizeof(int), cudaMemcpyDeviceToDevice);
    cudaMemcpyAsync(cur_l, off_l, (size_t)L * sizeof(int), cudaMemcpyDeviceToDevice);
    fill2<<<(E + 255) / 256, 256>>>(l_edge, c_edge, cur_l, cur_c, src_l, src_c, E);

    // iteration-0 slices = inputs; seed state planes
    cudaMemcpyAsync(louts, l_emb0, (size_t)L * D * sizeof(float), cudaMemcpyDeviceToDevice);
    cudaMemcpyAsync(couts, c_emb0, (size_t)C * D * sizeof(float), cudaMemcpyDeviceToDevice);
    split_act<<<(L * 64 + 255) / 256, 256>>>(l_emb0, hl_hi, hl_lo, L);
    split_act<<<(C * 64 + 255) / 256, 256>>>(c_emb0, hc_hi, hc_lo, C);

    const int gLx = (L + 127) / 128;
    const int gCx = (C + 127) / 128;
    const int total_nodes = C + L;
    const dim3 gGemm(gCx + gLx, 4);

    for (int it = 0; it < NITER; it++) {
        const float* l_prev = louts + (size_t)it * L * D;
        const float* c_prev = couts + (size_t)it * C * D;
        float* l_next = louts + (size_t)(it + 1) * L * D;
        float* c_next = couts + (size_t)(it + 1) * C * D;

        // phase 1: all three message MLPs in one launch
        MlpP p0 = {l_prev, whi + o_l2c0, wlo + o_l2c0, l2c_b0,
                   whi + o_l2c1, wlo + o_l2c1, l2c_b1, l2c_msg, nullptr, nullptr, L, 0, gLx};
        MlpP p1 = {c_prev, whi + o_c2l0, wlo + o_c2l0, c2l_b0,
                   whi + o_c2l1, wlo + o_c2l1, c2l_b1, c2l_msg, nullptr, nullptr, C, 0, gCx};
        MlpP p2 = {l_prev, whi + o_l2l0, wlo + o_l2l0, l2l_b0,
                   whi + o_l2l1, wlo + o_l2l1, l2l_b1, nullptr, m_hi, m_lo, L, 1, gLx};
        mlp2_multi<<<gLx + gCx + gLx, 256, MLP2_DSMEM>>>(p0, p1, p2);

        // phase 2: both gathers in one launch (write planes)
        gather2<<<(total_nodes + 7) / 8, 256>>>(l2c_msg, off_c, src_c, ac_hi, ac_lo, C,
                                                c2l_msg, off_l, src_l, al_hi, al_lo, L);

        // phase 3: all GRU gate GEMMs in one launch (all-async)
        GruP pc = {ac_hi, ac_lo, nullptr, nullptr, hc_hi, hc_lo, 8, 0,
                   whi + o_cih, wlo + o_cih, whi + o_chh, wlo + o_chh,
                   c_bih, c_bhh, rz_c, n_c, C, gCx};
        GruP pl = {al_hi, al_lo, m_hi, m_lo, hl_hi, hl_lo, 8, 8,
                   whi + o_lih, wlo + o_lih, whi + o_lhh, wlo + o_lhh,
                   l_bih, l_bhh, rz_l, n_l, L, gLx};
        gru_gemm_multi<<<gGemm, 256, GRU_DSMEM>>>(pc, pl);

        // phase 4: both elementwise GRU updates (fp32 + next-state planes)
        gru_elem2x2<<<(total_nodes * 32 + 255) / 256, 256>>>(
            rz_c, n_c, c_prev, c_next, hc_hi, hc_lo, C,
            rz_l, n_l, l_prev, l_next, hl_hi, hl_lo, L);
    }
}

// round 14
// speedup vs baseline: 1.5630x; 1.1850x over previous
#include <cuda_runtime.h>
#include <cuda_fp16.h>
#include <cstdint>

// Problem constants (fixed by setup_inputs)
#define DIM   128
#define LMAX  60000
#define CMAX  30000
#define EMAX  360000
#define NITER 8

#define CBLK ((CMAX + 127) / 128)
#define LBLK ((LMAX + 127) / 128)
#define CPLANE ((size_t)CBLK * 8192)
#define LPLANE ((size_t)LBLK * 8192)

// ---------------- scratch (device globals; no allocations allowed) ----------
__device__ float g_l2c_msg[(size_t)LMAX * DIM];
__device__ float g_c2l_msg[(size_t)CMAX * DIM];
__device__ float g_rz_c   [(size_t)CMAX * 2 * DIM];
__device__ float g_n_c    [(size_t)CMAX * 2 * DIM];
__device__ float g_rz_l   [(size_t)LMAX * 2 * DIM];
__device__ float g_n_l    [(size_t)LMAX * 2 * DIM];
// fragment-ordered fp16 activation planes (u32 = 2 fp16), single (hi-only)
__device__ uint32_t g_ac[CPLANE];    // clause aggr
__device__ uint32_t g_al[LPLANE];    // literal aggr
__device__ uint32_t g_m [LPLANE];    // l2l message
__device__ uint32_t g_hc[CPLANE];    // clause state
__device__ uint32_t g_hl[LPLANE];    // literal state
// CSR scratch
__device__ int g_cnt_c[CMAX];
__device__ int g_cnt_l[LMAX];
__device__ int g_off_c[CMAX + 1];
__device__ int g_off_l[LMAX + 1];
__device__ int g_cur_c[CMAX];
__device__ int g_cur_l[LMAX];
__device__ int g_src_c[EMAX];
__device__ int g_src_l[EMAX];
// pre-split fp16 weight planes
#define WSPLIT_TOTAL 172032
__device__ uint32_t g_whi[WSPLIT_TOTAL];
__device__ uint32_t g_wlo[WSPLIT_TOTAL];

// ======================= helpers =============================================
__device__ __forceinline__ uint32_t smem_u32(const void* p) {
    uint32_t a;
    asm("{ .reg .u64 t; cvta.to.shared.u64 t, %1; cvt.u32.u64 %0, t; }"
        : "=r"(a) : "l"(p));
    return a;
}

__device__ __forceinline__ uint32_t packh(float x, float y) {
    __half2 h = __floats2half2_rn(x, y);
    return *reinterpret_cast<uint32_t*>(&h);
}

__device__ __forceinline__ void split2h(float x, float y, uint32_t& hi, uint32_t& lo) {
    __half hx = __float2half_rn(x), hy = __float2half_rn(y);
    __half lx = __float2half_rn(x - __half2float(hx));
    __half ly = __float2half_rn(y - __half2float(hy));
    __half2 H = __halves2half2(hx, hy);
    __half2 Lo = __halves2half2(lx, ly);
    hi = *reinterpret_cast<uint32_t*>(&H);
    lo = *reinterpret_cast<uint32_t*>(&Lo);
}

__device__ __forceinline__ void cp16(uint32_t dst, const void* src) {
    asm volatile("cp.async.ca.shared.global [%0], [%1], 16;"
                 :: "r"(dst), "l"(src) : "memory");
}
#define CP_COMMIT() asm volatile("cp.async.commit_group;" ::: "memory")
#define CP_WAIT0()  asm volatile("cp.async.wait_group 0;" ::: "memory")
#define CP_WAIT1()  asm volatile("cp.async.wait_group 1;" ::: "memory")

__device__ __forceinline__ void mma_f16(float* d, const uint32_t* a,
                                        uint32_t b0, uint32_t b1) {
    asm volatile(
        "mma.sync.aligned.m16n8k16.row.col.f32.f16.f16.f32 "
        "{%0,%1,%2,%3}, {%4,%5,%6,%7}, {%8,%9}, {%0,%1,%2,%3};"
        : "+f"(d[0]), "+f"(d[1]), "+f"(d[2]), "+f"(d[3])
        : "r"(a[0]), "r"(a[1]), "r"(a[2]), "r"(a[3]), "r"(b0), "r"(b1));
}

#define IDX(r, q) ((((r) << 3)) | ((q) ^ ((r) & 7)))

__device__ __forceinline__ float fsigmoid(float x) { return 1.f / (1.f + __expf(-x)); }
__device__ __forceinline__ float ftanh(float x) {
    float t = __expf(2.f * fabsf(x));
    float r = 1.f - 2.f / (t + 1.f);
    return copysignf(r, x);
}

// ======================= weight pre-split (fp16 hi/lo, fragment-ordered) =====
__global__ void split_w(const float* __restrict__ W, uint32_t* __restrict__ hi,
                        uint32_t* __restrict__ lo, int total_pairs, int kp)
{
    int i = blockIdx.x * 256 + threadIdx.x;
    if (i >= total_pairs) return;
    int R = i / kp, p = i - R * kp;
    float2 f = ((const float2*)W)[i];
    uint32_t h, l;
    split2h(f.x, f.y, h, l);
    int ngroup = R >> 7, n = R & 127;
    int ch = p >> 3, q = p & 7;
    int nt = n >> 3, l4 = n & 7;
    int region = l4 * 4 + (q & 3);
    int idx = region * 32 + (((nt >> 1) ^ (region & 7)) << 2) + ((nt & 1) << 1) + (q >> 2);
    size_t base = ((size_t)(ngroup * (kp >> 3) + ch)) << 10;
    hi[base + idx] = h;
    lo[base + idx] = l;
}

// ======================= activation pre-split (single fp16 plane) ============
__global__ void split_act(const float* __restrict__ X, uint32_t* __restrict__ pl, int N)
{
    int i = blockIdx.x * 256 + threadIdx.x;
    if (i >= N * 64) return;
    int row = i >> 6, pp = i & 63;
    float2 f = ((const float2*)X)[i];
    int chunk = pp >> 3, q = pp & 7, rl = row & 127;
    size_t base = ((size_t)((row >> 7) * 8 + chunk)) << 10;
    pl[base + IDX(rl, q)] = packh(f.x, f.y);
}

// ======================= MMA K16 sub-chunk (2 MMAs per acc-pair) =============
// A: single plane 1024 u32; B: [Bh 1024][Bl 1024].
__device__ __forceinline__ void mma_chunk(const uint32_t* __restrict__ A,
                                          const uint32_t* __restrict__ B,
                                          float (&acc)[16][4], int lane, int wid)
{
    const int r = wid * 16 + (lane >> 2);
    const int q = lane & 3;
    uint32_t ah[4];
    ah[0] = A[IDX(r, q)];     ah[1] = A[IDX(r + 8, q)];
    ah[2] = A[IDX(r, q + 4)]; ah[3] = A[IDX(r + 8, q + 4)];
    const uint32_t* Bh = B + lane * 32;
    const uint32_t* Bl = Bh + 1024;
#pragma unroll
    for (int c = 0; c < 8; c++) {
        const int sw = ((c ^ (lane & 7)) << 2);
        uint4 vh = *(const uint4*)(Bh + sw);
        uint4 vl = *(const uint4*)(Bl + sw);
        mma_f16(acc[2 * c],     ah, vh.x, vh.y);
        mma_f16(acc[2 * c + 1], ah, vh.z, vh.w);
        mma_f16(acc[2 * c],     ah, vl.x, vl.y);
        mma_f16(acc[2 * c + 1], ah, vl.z, vl.w);
    }
}

// ======================= param structs =======================================
struct MlpP {
    const float* A0;
    const uint32_t *W0h, *W0l;
    const float* b0;
    const uint32_t *W1h, *W1l;
    const float* b1;
    float* out;                 // fp32 output (may be null)
    uint32_t* opl;              // plane output (may be null)
    int N, perm, gx;
};

struct GruP {
    const uint32_t *S0, *S1, *H;    // single fp16 planes
    int n0, n1;                     // K16 units
    const uint32_t *Wih_h, *Wih_l, *Whh_h, *Whh_l;
    const float *bih, *bhh;
    float *rz, *nbuf;
    int N, gx;
};

// K32 A-store (single fp16 plane): row = t>>1, K16-select sub = t&1.
#define STA_K32S(Sbase) do { \
        uint32_t* Ap = (Sbase) + sub * 1024; \
        Ap[IDX(row, 0)] = packh(ra0.x, ra0.y); \
        Ap[IDX(row, 1)] = packh(ra0.z, ra0.w); \
        Ap[IDX(row, 2)] = packh(ra1.x, ra1.y); \
        Ap[IDX(row, 3)] = packh(ra1.z, ra1.w); \
        Ap[IDX(row, 4)] = packh(ra2.x, ra2.y); \
        Ap[IDX(row, 5)] = packh(ra2.z, ra2.w); \
        Ap[IDX(row, 6)] = packh(ra3.x, ra3.y); \
        Ap[IDX(row, 7)] = packh(ra3.z, ra3.w); \
    } while (0)

// chunk32 buffer layout (u32, 6144): [A0 1024][A1 1024][Bh0 1024][Bl0 1024][Bh1 1024][Bl1 1024]

// ======================= combined fused 2-layer MLP (occ 2) ==================
// dyn smem (u32): stage1 ring 2 x 6144 = [0,12288); stage2 A region [0,8192),
// stage2 B ring 2 x 4096 at [8192,16384).
#define MLP2_DSMEM (16384 * 4)

__global__ __launch_bounds__(256, 2)
void mlp2_multi(MlpP p0, MlpP p1, MlpP p2)
{
    extern __shared__ __align__(16) uint32_t sm[];
    __shared__ float sb0[128];

    int bx = blockIdx.x;
    MlpP p;
    if (bx < p0.gx) { p = p0; }
    else if (bx < p0.gx + p1.gx) { p = p1; bx -= p0.gx; }
    else { p = p2; bx -= p0.gx + p1.gx; }

    const int t = threadIdx.x, lane = t & 31, wid = t >> 5;
    const int m0 = bx * 128;

    if (t < 128) sb0[t] = p.b0[t];

    float acc1[16][4];
#pragma unroll
    for (int i = 0; i < 16; i++)
#pragma unroll
        for (int j = 0; j < 4; j++) acc1[i][j] = 0.f;

    const int row = t >> 1;
    const int sub = t & 1;
    const int grow = m0 + row;
    int arow = (p.perm ? (grow ^ 1) : grow);
    if (grow >= p.N) arow = 0;
    float4 ra0, ra1, ra2, ra3;

    const int wrow = t & 127;
    const int wpl = t >> 7;
    const uint32_t* w0p = wpl ? p.W0l : p.W0h;
    const uint32_t* w1p = wpl ? p.W1l : p.W1h;

#define LDA1(ch) do { \
        const float* pp = p.A0 + (size_t)arow * 128 + ((ch) << 5) + sub * 16; \
        ra0 = *(const float4*)pp;       ra1 = *(const float4*)(pp + 4); \
        ra2 = *(const float4*)(pp + 8); ra3 = *(const float4*)(pp + 12); \
    } while (0)
#define CPW1(wb, ch, buf) do { \
        _Pragma("unroll") \
        for (int si = 0; si < 2; si++) { \
            const uint32_t* gp = (wb) + ((size_t)(2 * (ch) + si) << 10) + wrow * 8; \
            uint32_t daddr = smem_u32(sm + (buf) * 6144 + 2048 + si * 2048 + wpl * 1024 + wrow * 8); \
            cp16(daddr, gp); cp16(daddr + 16, gp + 4); \
        } \
    } while (0)
#define CPW2(ch, buf) do { \
        _Pragma("unroll") \
        for (int si = 0; si < 2; si++) { \
            const uint32_t* gp = w1p + ((size_t)(2 * (ch) + si) << 10) + wrow * 8; \
            uint32_t daddr = smem_u32(sm + 8192 + (buf) * 4096 + si * 2048 + wpl * 1024 + wrow * 8); \
            cp16(daddr, gp); cp16(daddr + 16, gp + 4); \
        } \
    } while (0)

    // ---- stage 1: 4 K32 chunks, 2-deep ring ----
    LDA1(0); CPW1(w0p, 0, 0); CP_COMMIT();
    STA_K32S(sm + 0 * 6144);
    LDA1(1);
    CP_WAIT0(); __syncthreads();
    for (int ch = 0; ch < 4; ch++) {
        if (ch + 1 < 4) {
            const int nb = (ch + 1) & 1;
            CPW1(w0p, ch + 1, nb); CP_COMMIT();
            STA_K32S(sm + nb * 6144);
        }
        if (ch + 2 < 4) LDA1(ch + 2);
        const uint32_t* S = sm + (ch & 1) * 6144;
        mma_chunk(S,        S + 2048, acc1, lane, wid);
        mma_chunk(S + 1024, S + 4096, acc1, lane, wid);
        if (ch + 1 < 4) { CP_WAIT0(); __syncthreads(); }
    }
    __syncthreads();

    // ---- bias + relu, spill stage-1 result into A region (fp16 planes) ----
    {
        const int rlo = wid * 16 + (lane >> 2);
        const int rhi = rlo + 8;
#pragma unroll
        for (int nt = 0; nt < 16; nt++) {
            const int col = nt * 8 + 2 * (lane & 3);
            float bx2 = sb0[col], by = sb0[col + 1];
            float v0 = fmaxf(acc1[nt][0] + bx2, 0.f);
            float v1 = fmaxf(acc1[nt][1] + by, 0.f);
            float v2 = fmaxf(acc1[nt][2] + bx2, 0.f);
            float v3 = fmaxf(acc1[nt][3] + by, 0.f);
            const int ch16 = nt >> 1;
            const int q = (nt & 1) * 4 + (lane & 3);
            sm[ch16 * 1024 + IDX(rlo, q)] = packh(v0, v1);
            sm[ch16 * 1024 + IDX(rhi, q)] = packh(v2, v3);
        }
    }

    float acc2[16][4];
#pragma unroll
    for (int i = 0; i < 16; i++)
#pragma unroll
        for (int j = 0; j < 4; j++) acc2[i][j] = 0.f;

    // ---- stage 2: A from smem region, W1 streamed, 4 K32 chunks ----
    CPW2(0, 0); CP_COMMIT();
    CP_WAIT0(); __syncthreads();   // also publishes the spill
    for (int ch = 0; ch < 4; ch++) {
        if (ch + 1 < 4) { CPW2(ch + 1, (ch + 1) & 1); CP_COMMIT(); }
        const uint32_t* B = sm + 8192 + (ch & 1) * 4096;
        mma_chunk(sm + (2 * ch) * 1024,     B,        acc2, lane, wid);
        mma_chunk(sm + (2 * ch + 1) * 1024, B + 2048, acc2, lane, wid);
        if (ch + 1 < 4) { CP_WAIT0(); __syncthreads(); }
    }

    // ---- epilogue: fp32 or fragment-plane output ----
    const int rl0 = wid * 16 + (lane >> 2);
    const int rl1 = rl0 + 8;
    if (p.opl) {
#pragma unroll
        for (int nt = 0; nt < 16; nt++) {
            const int col = nt * 8 + 2 * (lane & 3);
            float bx2 = p.b1[col], by = p.b1[col + 1];
            float v0 = acc2[nt][0] + bx2, v1 = acc2[nt][1] + by;
            float v2 = acc2[nt][2] + bx2, v3 = acc2[nt][3] + by;
            const int pq = nt * 4 + (lane & 3);
            const int chunk = pq >> 3, q = pq & 7;
            const size_t base = ((size_t)(bx * 8 + chunk)) << 10;
            p.opl[base + IDX(rl0, q)] = packh(v0, v1);
            p.opl[base + IDX(rl1, q)] = packh(v2, v3);
        }
    } else {
        const int r0 = m0 + rl0;
#pragma unroll
        for (int nt = 0; nt < 16; nt++) {
            const int col = nt * 8 + 2 * (lane & 3);
            float bx2 = p.b1[col], by = p.b1[col + 1];
            if (r0 < p.N)
                *(float2*)(p.out + (size_t)r0 * 128 + col) =
                    make_float2(acc2[nt][0] + bx2, acc2[nt][1] + by);
            if (r0 + 8 < p.N)
                *(float2*)(p.out + (size_t)(r0 + 8) * 128 + col) =
                    make_float2(acc2[nt][2] + bx2, acc2[nt][3] + by);
        }
    }
#undef LDA1
#undef CPW1
#undef CPW2
}

// ======================= combined GRU gate GEMM (all-async A+B) ==============
// grid (pc.gx + pl.gx, 4). y: 0=r, 1=z (sigmoid -> rz), 2=n_input, 3=n_hidden (-> nbuf)
#define GRU_DSMEM (3 * 6144 * 4)

__global__ __launch_bounds__(256, 2)
void gru_gemm_multi(GruP pc, GruP pl)
{
    extern __shared__ __align__(16) uint32_t sm[];

    int bx = blockIdx.x;
    GruP p;
    if (bx < pc.gx) { p = pc; }
    else { p = pl; bx -= pc.gx; }

    const int t = threadIdx.x, lane = t & 31, wid = t >> 5;
    const int m0 = bx * 128;
    const int g  = blockIdx.y;
    const int nchi = p.n0 + p.n1;
    const int nch32 = (g < 2) ? (nchi + 8) >> 1 : (g == 2 ? nchi >> 1 : 4);
    const int blk8 = bx * 8;

    float acc[16][4];
#pragma unroll
    for (int i = 0; i < 16; i++)
#pragma unroll
        for (int j = 0; j < 4; j++) acc[i][j] = 0.f;

    const int wrow = t & 127;
    const int wpl = t >> 7;
    const uint32_t* pih = wpl ? p.Wih_l : p.Wih_h;
    const uint32_t* phh = wpl ? p.Whh_l : p.Whh_h;

#define CPA(ch, buf) do { \
        _Pragma("unroll") \
        for (int si = 0; si < 2; si++) { \
            const int c16 = 2 * (ch) + si; \
            const uint32_t* sp; int cl; \
            if (g == 3)            { sp = p.H;  cl = c16; } \
            else if (c16 < p.n0)   { sp = p.S0; cl = c16; } \
            else if (c16 < nchi)   { sp = p.S1; cl = c16 - p.n0; } \
            else                   { sp = p.H;  cl = c16 - nchi; } \
            const uint32_t* gp = sp + ((size_t)(blk8 + cl) << 10) + t * 4; \
            cp16(smem_u32(sm + (buf) * 6144 + si * 1024 + t * 4), gp); \
        } \
    } while (0)
#define CPW(ch, buf) do { \
        _Pragma("unroll") \
        for (int si = 0; si < 2; si++) { \
            const int c16 = 2 * (ch) + si; \
            const uint32_t* gp; \
            if (g < 2) gp = (c16 < nchi) \
                ? pih + (((size_t)(g * nchi + c16)) << 10) + wrow * 8 \
                : phh + (((size_t)(g * 8 + c16 - nchi)) << 10) + wrow * 8; \
            else if (g == 2) gp = pih + (((size_t)(2 * nchi + c16)) << 10) + wrow * 8; \
            else gp = phh + (((size_t)(16 + c16)) << 10) + wrow * 8; \
            uint32_t daddr = smem_u32(sm + (buf) * 6144 + 2048 + si * 2048 + wpl * 1024 + wrow * 8); \
            cp16(daddr, gp); cp16(daddr + 16, gp + 4); \
        } \
    } while (0)

    CPA(0, 0); CPW(0, 0); CP_COMMIT();
    if (nch32 > 1) { CPA(1, 1); CPW(1, 1); CP_COMMIT(); CP_WAIT1(); }
    else CP_WAIT0();
    __syncthreads();
    for (int ch = 0; ch < nch32; ch++) {
        if (ch + 2 < nch32) { CPA(ch + 2, (ch + 2) % 3); CPW(ch + 2, (ch + 2) % 3); CP_COMMIT(); }
        const uint32_t* S = sm + (ch % 3) * 6144;
        mma_chunk(S,        S + 2048, acc, lane, wid);
        mma_chunk(S + 1024, S + 4096, acc, lane, wid);
        if (ch + 1 < nch32) {
            if (ch + 2 < nch32) CP_WAIT1(); else CP_WAIT0();
            __syncthreads();
        }
    }

    const int r0 = m0 + wid * 16 + (lane >> 2);
    if (g < 2) {
#pragma unroll
        for (int nt = 0; nt < 16; nt++) {
            const int col = nt * 8 + 2 * (lane & 3);
            float bx2 = p.bih[g * 128 + col]     + p.bhh[g * 128 + col];
            float by  = p.bih[g * 128 + col + 1] + p.bhh[g * 128 + col + 1];
            if (r0 < p.N)
                *(float2*)(p.rz + (size_t)r0 * 256 + g * 128 + col) =
                    make_float2(fsigmoid(acc[nt][0] + bx2), fsigmoid(acc[nt][1] + by));
            if (r0 + 8 < p.N)
                *(float2*)(p.rz + (size_t)(r0 + 8) * 256 + g * 128 + col) =
                    make_float2(fsigmoid(acc[nt][2] + bx2), fsigmoid(acc[nt][3] + by));
        }
    } else {
        const float* bs = (g == 2) ? p.bih : p.bhh;
        const int go = (g - 2) * 128;
#pragma unroll
        for (int nt = 0; nt < 16; nt++) {
            const int col = nt * 8 + 2 * (lane & 3);
            float bx2 = bs[256 + col], by = bs[256 + col + 1];
            if (r0 < p.N)
                *(float2*)(p.nbuf + (size_t)r0 * 256 + go + col) =
                    make_float2(acc[nt][0] + bx2, acc[nt][1] + by);
            if (r0 + 8 < p.N)
                *(float2*)(p.nbuf + (size_t)(r0 + 8) * 256 + go + col) =
                    make_float2(acc[nt][2] + bx2, acc[nt][3] + by);
        }
    }
#undef CPA
#undef CPW
}

// ======================= CSR build ===========================================
__global__ void hist2(const int* __restrict__ l_e, const int* __restrict__ c_e,
                      int* __restrict__ cnt_l, int* __restrict__ cnt_c, int E)
{
    int i = blockIdx.x * blockDim.x + threadIdx.x;
    if (i < E) {
        atomicAdd(&cnt_l[l_e[i]], 1);
        atomicAdd(&cnt_c[c_e[i]], 1);
    }
}

__global__ void exscan(const int* __restrict__ cnt, int* __restrict__ off, int n)
{
    __shared__ int part[1024];
    const int t = threadIdx.x;
    const int chunk = (n + 1023) >> 10;
    const int b = t * chunk;
    const int e = min(b + chunk, n);
    int s = 0;
    for (int i = b; i < e; i++) s += cnt[i];
    part[t] = s;
    __syncthreads();
    for (int d = 1; d < 1024; d <<= 1) {
        int v = (t >= d) ? part[t - d] : 0;
        __syncthreads();
        if (t >= d) part[t] += v;
        __syncthreads();
    }
    int run = (t == 0) ? 0 : part[t - 1];
    for (int i = b; i < e; i++) { off[i] = run; run += cnt[i]; }
    if (t == 0) off[n] = part[1023];
}

__global__ void fill2(const int* __restrict__ l_e, const int* __restrict__ c_e,
                      int* __restrict__ cur_l, int* __restrict__ cur_c,
                      int* __restrict__ src_l, int* __restrict__ src_c, int E)
{
    int i = blockIdx.x * blockDim.x + threadIdx.x;
    if (i < E) {
        int l = l_e[i], c = c_e[i];
        src_c[atomicAdd(&cur_c[c], 1)] = l;
        src_l[atomicAdd(&cur_l[l], 1)] = c;
    }
}

// ======================= combined gather-sum (writes fp16 planes) ============
__global__ __launch_bounds__(256)
void gather2(const float* __restrict__ msgA, const int* __restrict__ offA,
             const int* __restrict__ srcA, uint32_t* __restrict__ aplA, int nA,
             const float* __restrict__ msgB, const int* __restrict__ offB,
             const int* __restrict__ srcB, uint32_t* __restrict__ aplB, int nB)
{
    int node = blockIdx.x * 8 + (threadIdx.x >> 5);
    int lane = threadIdx.x & 31;
    const float* msg;
    const int *off, *srcs;
    uint32_t* apl;
    if (node < nA) { msg = msgA; off = offA; srcs = srcA; apl = aplA; }
    else {
        node -= nA;
        if (node >= nB) return;
        msg = msgB; off = offB; srcs = srcB; apl = aplB;
    }
    int b = off[node], e = off[node + 1];
    float4 acc = {0.f, 0.f, 0.f, 0.f};
    for (int i = b; i < e; i++) {
        const float4 v = *((const float4*)(msg + (size_t)srcs[i] * DIM) + lane);
        acc.x += v.x; acc.y += v.y; acc.z += v.z; acc.w += v.w;
    }
    const int rl = node & 127;
    const int chunk = lane >> 2;
    const int q0 = (2 * lane) & 7;
    const size_t base = ((size_t)((node >> 7) * 8 + chunk)) << 10;
    apl[base + IDX(rl, q0)]     = packh(acc.x, acc.y);
    apl[base + IDX(rl, q0 + 1)] = packh(acc.z, acc.w);
}

// ---------------- combined GRU elementwise (writes fp32 + fp16 planes) -------
__global__ void gru_elem2x2(const float* __restrict__ rzA, const float* __restrict__ nA,
                            const float* __restrict__ hA, float* __restrict__ hnA,
                            uint32_t* __restrict__ plA, int NA,
                            const float* __restrict__ rzB, const float* __restrict__ nB,
                            const float* __restrict__ hB, float* __restrict__ hnB,
                            uint32_t* __restrict__ plB, int NB)
{
    int idx = blockIdx.x * blockDim.x + threadIdx.x;
    int row = idx >> 5, c4 = (idx & 31) * 4;
    const float *rz, *nbuf, *h;
    float* hnew;
    uint32_t* pl;
    if (row < NA) { rz = rzA; nbuf = nA; h = hA; hnew = hnA; pl = plA; }
    else {
        row -= NA;
        if (row >= NB) return;
        rz = rzB; nbuf = nB; h = hB; hnew = hnB; pl = plB;
    }
    const float4 r4 = *(const float4*)(rz + (size_t)row * 256 + c4);
    const float4 z4 = *(const float4*)(rz + (size_t)row * 256 + 128 + c4);
    const float4 ni = *(const float4*)(nbuf + (size_t)row * 256 + c4);
    const float4 nh = *(const float4*)(nbuf + (size_t)row * 256 + 128 + c4);
    const float4 h4 = *(const float4*)(h + (size_t)row * 128 + c4);
    float4 o;
    o.x = (1.f - z4.x) * ftanh(ni.x + r4.x * nh.x) + z4.x * h4.x;
    o.y = (1.f - z4.y) * ftanh(ni.y + r4.y * nh.y) + z4.y * h4.y;
    o.z = (1.f - z4.z) * ftanh(ni.z + r4.z * nh.z) + z4.z * h4.z;
    o.w = (1.f - z4.w) * ftanh(ni.w + r4.w * nh.w) + z4.w * h4.w;
    *(float4*)(hnew + (size_t)row * 128 + c4) = o;
    const int rl = row & 127;
    const int q0 = (c4 >> 1) & 7;
    const size_t base = ((size_t)((row >> 7) * 8 + (c4 >> 4))) << 10;
    pl[base + IDX(rl, q0)]     = packh(o.x, o.y);
    pl[base + IDX(rl, q0 + 1)] = packh(o.z, o.w);
}

// ---------------- launch ------------------------------------------------------
extern "C" void kernel_launch(void* const* d_in, const int* in_sizes, int n_in,
                              void* d_out, int out_size)
{
    const int D = DIM;
    const int E = in_sizes[2];
    const int L = in_sizes[4] / D;
    const int C = in_sizes[5] / D;

    const int*   l_edge = (const int*)d_in[2];
    const int*   c_edge = (const int*)d_in[3];
    const float* l_emb0 = (const float*)d_in[4];
    const float* c_emb0 = (const float*)d_in[5];

    const float* l2c_W0 = (const float*)d_in[6];
    const float* l2c_b0 = (const float*)d_in[7];
    const float* l2c_W1 = (const float*)d_in[8];
    const float* l2c_b1 = (const float*)d_in[9];
    const float* c2l_W0 = (const float*)d_in[10];
    const float* c2l_b0 = (const float*)d_in[11];
    const float* c2l_W1 = (const float*)d_in[12];
    const float* c2l_b1 = (const float*)d_in[13];
    const float* l2l_W0 = (const float*)d_in[14];
    const float* l2l_b0 = (const float*)d_in[15];
    const float* l2l_W1 = (const float*)d_in[16];
    const float* l2l_b1 = (const float*)d_in[17];
    const float* c_Wih  = (const float*)d_in[18];
    const float* c_Whh  = (const float*)d_in[19];
    const float* c_bih  = (const float*)d_in[20];
    const float* c_bhh  = (const float*)d_in[21];
    const float* l_Wih  = (const float*)d_in[22];
    const float* l_Whh  = (const float*)d_in[23];
    const float* l_bih  = (const float*)d_in[24];
    const float* l_bhh  = (const float*)d_in[25];

    float* out   = (float*)d_out;
    float* louts = out;                                // [9, L, D]
    float* couts = out + (size_t)(NITER + 1) * L * D;  // [9, C, D]

    float *l2c_msg, *c2l_msg, *rz_c, *n_c, *rz_l, *n_l;
    cudaGetSymbolAddress((void**)&l2c_msg, g_l2c_msg);
    cudaGetSymbolAddress((void**)&c2l_msg, g_c2l_msg);
    cudaGetSymbolAddress((void**)&rz_c,    g_rz_c);
    cudaGetSymbolAddress((void**)&n_c,     g_n_c);
    cudaGetSymbolAddress((void**)&rz_l,    g_rz_l);
    cudaGetSymbolAddress((void**)&n_l,     g_n_l);

    uint32_t *ac, *al, *mpl, *hc, *hl;
    cudaGetSymbolAddress((void**)&ac,  g_ac);
    cudaGetSymbolAddress((void**)&al,  g_al);
    cudaGetSymbolAddress((void**)&mpl, g_m);
    cudaGetSymbolAddress((void**)&hc,  g_hc);
    cudaGetSymbolAddress((void**)&hl,  g_hl);

    int *cnt_c, *cnt_l, *off_c, *off_l, *cur_c, *cur_l, *src_c, *src_l;
    cudaGetSymbolAddress((void**)&cnt_c, g_cnt_c);
    cudaGetSymbolAddress((void**)&cnt_l, g_cnt_l);
    cudaGetSymbolAddress((void**)&off_c, g_off_c);
    cudaGetSymbolAddress((void**)&off_l, g_off_l);
    cudaGetSymbolAddress((void**)&cur_c, g_cur_c);
    cudaGetSymbolAddress((void**)&cur_l, g_cur_l);
    cudaGetSymbolAddress((void**)&src_c, g_src_c);
    cudaGetSymbolAddress((void**)&src_l, g_src_l);

    uint32_t *whi, *wlo;
    cudaGetSymbolAddress((void**)&whi, g_whi);
    cudaGetSymbolAddress((void**)&wlo, g_wlo);

    cudaFuncSetAttribute(mlp2_multi, cudaFuncAttributeMaxDynamicSharedMemorySize,
                         MLP2_DSMEM);
    cudaFuncSetAttribute(gru_gemm_multi, cudaFuncAttributeMaxDynamicSharedMemorySize,
                         GRU_DSMEM);

    const int o_l2c0 = 0,      o_l2c1 = 8192,  o_c2l0 = 16384, o_c2l1 = 24576;
    const int o_l2l0 = 32768,  o_l2l1 = 40960;
    const int o_cih  = 49152,  o_chh  = 73728;
    const int o_lih  = 98304,  o_lhh  = 147456;

    // ---- pre-split weights (fp16 hi/lo) ----
    split_w<<<32, 256>>>(l2c_W0, whi + o_l2c0, wlo + o_l2c0, 8192, 64);
    split_w<<<32, 256>>>(l2c_W1, whi + o_l2c1, wlo + o_l2c1, 8192, 64);
    split_w<<<32, 256>>>(c2l_W0, whi + o_c2l0, wlo + o_c2l0, 8192, 64);
    split_w<<<32, 256>>>(c2l_W1, whi + o_c2l1, wlo + o_c2l1, 8192, 64);
    split_w<<<32, 256>>>(l2l_W0, whi + o_l2l0, wlo + o_l2l0, 8192, 64);
    split_w<<<32, 256>>>(l2l_W1, whi + o_l2l1, wlo + o_l2l1, 8192, 64);
    split_w<<<96, 256>>>(c_Wih,  whi + o_cih,  wlo + o_cih,  24576, 64);
    split_w<<<96, 256>>>(c_Whh,  whi + o_chh,  wlo + o_chh,  24576, 64);
    split_w<<<192, 256>>>(l_Wih, whi + o_lih,  wlo + o_lih,  49152, 128);
    split_w<<<96, 256>>>(l_Whh,  whi + o_lhh,  wlo + o_lhh,  24576, 64);

    // ---- CSR build ----
    cudaMemsetAsync(cnt_c, 0, (size_t)C * sizeof(int));
    cudaMemsetAsync(cnt_l, 0, (size_t)L * sizeof(int));
    hist2<<<(E + 255) / 256, 256>>>(l_edge, c_edge, cnt_l, cnt_c, E);
    exscan<<<1, 1024>>>(cnt_c, off_c, C);
    exscan<<<1, 1024>>>(cnt_l, off_l, L);
    cudaMemcpyAsync(cur_c, off_c, (size_t)C * sizeof(int), cudaMemcpyDeviceToDevice);
    cudaMemcpyAsync(cur_l, off_l, (size_t)L * sizeof(int), cudaMemcpyDeviceToDevice);
    fill2<<<(E + 255) / 256, 256>>>(l_edge, c_edge, cur_l, cur_c, src_l, src_c, E);

    // iteration-0 slices = inputs; seed state planes
    cudaMemcpyAsync(louts, l_emb0, (size_t)L * D * sizeof(float), cudaMemcpyDeviceToDevice);
    cudaMemcpyAsync(couts, c_emb0, (size_t)C * D * sizeof(float), cudaMemcpyDeviceToDevice);
    split_act<<<(L * 64 + 255) / 256, 256>>>(l_emb0, hl, L);
    split_act<<<(C * 64 + 255) / 256, 256>>>(c_emb0, hc, C);

    const int gLx = (L + 127) / 128;
    const int gCx = (C + 127) / 128;
    const int total_nodes = C + L;
    const dim3 gGemm(gCx + gLx, 4);

    for (int it = 0; it < NITER; it++) {
        const float* l_prev = louts + (size_t)it * L * D;
        const float* c_prev = couts + (size_t)it * C * D;
        float* l_next = louts + (size_t)(it + 1) * L * D;
        float* c_next = couts + (size_t)(it + 1) * C * D;

        // phase 1: all three message MLPs in one launch
        MlpP p0 = {l_prev, whi + o_l2c0, wlo + o_l2c0, l2c_b0,
                   whi + o_l2c1, wlo + o_l2c1, l2c_b1, l2c_msg, nullptr, L, 0, gLx};
        MlpP p1 = {c_prev, whi + o_c2l0, wlo + o_c2l0, c2l_b0,
                   whi + o_c2l1, wlo + o_c2l1, c2l_b1, c2l_msg, nullptr, C, 0, gCx};
        MlpP p2 = {l_prev, whi + o_l2l0, wlo + o_l2l0, l2l_b0,
                   whi + o_l2l1, wlo + o_l2l1, l2l_b1, nullptr, mpl, L, 1, gLx};
        mlp2_multi<<<gLx + gCx + gLx, 256, MLP2_DSMEM>>>(p0, p1, p2);

        // phase 2: both gathers in one launch (write fp16 planes)
        gather2<<<(total_nodes + 7) / 8, 256>>>(l2c_msg, off_c, src_c, ac, C,
                                                c2l_msg, off_l, src_l, al, L);

        // phase 3: all GRU gate GEMMs in one launch (all-async)
        GruP pc = {ac, nullptr, hc, 8, 0,
                   whi + o_cih, wlo + o_cih, whi + o_chh, wlo + o_chh,
                   c_bih, c_bhh, rz_c, n_c, C, gCx};
        GruP pl = {al, mpl, hl, 8, 8,
                   whi + o_lih, wlo + o_lih, whi + o_lhh, wlo + o_lhh,
                   l_bih, l_bhh, rz_l, n_l, L, gLx};
        gru_gemm_multi<<<gGemm, 256, GRU_DSMEM>>>(pc, pl);

        // phase 4: both elementwise GRU updates (fp32 + next-state planes)
        gru_elem2x2<<<(total_nodes * 32 + 255) / 256, 256>>>(
            rz_c, n_c, c_prev, c_next, hc, C,
            rz_l, n_l, l_prev, l_next, hl, L);
    }
}

// round 15
// speedup vs baseline: 2.0249x; 1.2955x over previous
#include <cuda_runtime.h>
#include <cuda_fp16.h>
#include <cstdint>

// Problem constants (fixed by setup_inputs)
#define DIM   128
#define LMAX  60000
#define CMAX  30000
#define EMAX  360000
#define NITER 8

#define CBLK ((CMAX + 127) / 128)
#define LBLK ((LMAX + 127) / 128)
#define CPLANE ((size_t)CBLK * 8192)
#define LPLANE ((size_t)LBLK * 8192)

// ---------------- scratch (device globals; no allocations allowed) ----------
__device__ float g_l2c_msg[(size_t)LMAX * DIM];
__device__ float g_c2l_msg[(size_t)CMAX * DIM];
__device__ float g_rz_c   [(size_t)CMAX * 2 * DIM];
__device__ float g_n_c    [(size_t)CMAX * 2 * DIM];
__device__ float g_rz_l   [(size_t)LMAX * 2 * DIM];
__device__ float g_n_l    [(size_t)LMAX * 2 * DIM];
// fragment-ordered fp16 activation planes (u32 = 2 fp16)
__device__ uint32_t g_ac[CPLANE];    // clause aggr
__device__ uint32_t g_al[LPLANE];    // literal aggr
__device__ uint32_t g_m [LPLANE];    // l2l message
__device__ uint32_t g_hc[CPLANE];    // clause state
__device__ uint32_t g_hl[LPLANE];    // literal state
// CSR scratch
__device__ int g_cnt_c[CMAX];
__device__ int g_cnt_l[LMAX];
__device__ int g_off_c[CMAX + 1];
__device__ int g_off_l[LMAX + 1];
__device__ int g_cur_c[CMAX];
__device__ int g_cur_l[LMAX];
__device__ int g_src_c[EMAX];
__device__ int g_src_l[EMAX];
// pre-converted fp16 weight planes (single plane)
#define WSPLIT_TOTAL 172032
__device__ uint32_t g_whi[WSPLIT_TOTAL];

// ======================= helpers =============================================
__device__ __forceinline__ uint32_t smem_u32(const void* p) {
    uint32_t a;
    asm("{ .reg .u64 t; cvta.to.shared.u64 t, %1; cvt.u32.u64 %0, t; }"
        : "=r"(a) : "l"(p));
    return a;
}

__device__ __forceinline__ uint32_t packh(float x, float y) {
    __half2 h = __floats2half2_rn(x, y);
    return *reinterpret_cast<uint32_t*>(&h);
}

__device__ __forceinline__ void cp16(uint32_t dst, const void* src) {
    asm volatile("cp.async.ca.shared.global [%0], [%1], 16;"
                 :: "r"(dst), "l"(src) : "memory");
}
#define CP_COMMIT() asm volatile("cp.async.commit_group;" ::: "memory")
#define CP_WAIT0()  asm volatile("cp.async.wait_group 0;" ::: "memory")
#define CP_WAIT1()  asm volatile("cp.async.wait_group 1;" ::: "memory")

__device__ __forceinline__ void mma_f16(float* d, const uint32_t* a,
                                        uint32_t b0, uint32_t b1) {
    asm volatile(
        "mma.sync.aligned.m16n8k16.row.col.f32.f16.f16.f32 "
        "{%0,%1,%2,%3}, {%4,%5,%6,%7}, {%8,%9}, {%0,%1,%2,%3};"
        : "+f"(d[0]), "+f"(d[1]), "+f"(d[2]), "+f"(d[3])
        : "r"(a[0]), "r"(a[1]), "r"(a[2]), "r"(a[3]), "r"(b0), "r"(b1));
}

#define IDX(r, q) ((((r) << 3)) | ((q) ^ ((r) & 7)))

__device__ __forceinline__ float fsigmoid(float x) { return 1.f / (1.f + __expf(-x)); }
__device__ __forceinline__ float ftanh(float x) {
    float t = __expf(2.f * fabsf(x));
    float r = 1.f - 2.f / (t + 1.f);
    return copysignf(r, x);
}

// ======================= weight pre-convert (fp16 single plane) ==============
__global__ void split_w(const float* __restrict__ W, uint32_t* __restrict__ hi,
                        int total_pairs, int kp)
{
    int i = blockIdx.x * 256 + threadIdx.x;
    if (i >= total_pairs) return;
    int R = i / kp, p = i - R * kp;
    float2 f = ((const float2*)W)[i];
    uint32_t h = packh(f.x, f.y);
    int ngroup = R >> 7, n = R & 127;
    int ch = p >> 3, q = p & 7;
    int nt = n >> 3, l4 = n & 7;
    int region = l4 * 4 + (q & 3);
    int idx = region * 32 + (((nt >> 1) ^ (region & 7)) << 2) + ((nt & 1) << 1) + (q >> 2);
    size_t base = ((size_t)(ngroup * (kp >> 3) + ch)) << 10;
    hi[base + idx] = h;
}

// ======================= activation pre-split (single fp16 plane) ============
__global__ void split_act(const float* __restrict__ X, uint32_t* __restrict__ pl, int N)
{
    int i = blockIdx.x * 256 + threadIdx.x;
    if (i >= N * 64) return;
    int row = i >> 6, pp = i & 63;
    float2 f = ((const float2*)X)[i];
    int chunk = pp >> 3, q = pp & 7, rl = row & 127;
    size_t base = ((size_t)((row >> 7) * 8 + chunk)) << 10;
    pl[base + IDX(rl, q)] = packh(f.x, f.y);
}

// ======================= MMA K16 sub-chunk (1 MMA per acc) ===================
// A: single plane 1024 u32; B: single plane 1024 u32.
__device__ __forceinline__ void mma_chunk(const uint32_t* __restrict__ A,
                                          const uint32_t* __restrict__ B,
                                          float (&acc)[16][4], int lane, int wid)
{
    const int r = wid * 16 + (lane >> 2);
    const int q = lane & 3;
    uint32_t ah[4];
    ah[0] = A[IDX(r, q)];     ah[1] = A[IDX(r + 8, q)];
    ah[2] = A[IDX(r, q + 4)]; ah[3] = A[IDX(r + 8, q + 4)];
    const uint32_t* Bp = B + lane * 32;
#pragma unroll
    for (int c = 0; c < 8; c++) {
        const int sw = ((c ^ (lane & 7)) << 2);
        uint4 v = *(const uint4*)(Bp + sw);
        mma_f16(acc[2 * c],     ah, v.x, v.y);
        mma_f16(acc[2 * c + 1], ah, v.z, v.w);
    }
}

// ======================= param structs =======================================
struct MlpP {
    const float* A0;
    const uint32_t* W0;
    const float* b0;
    const uint32_t* W1;
    const float* b1;
    float* out;                 // fp32 output (may be null)
    uint32_t* opl;              // plane output (may be null)
    int N, perm, gx;
};

struct GruP {
    const uint32_t *S0, *S1, *H;    // single fp16 planes
    int n0, n1;                     // K16 units
    const uint32_t *Wih, *Whh;
    const float *bih, *bhh;
    float *rz, *nbuf;
    int N, gx;
};

// K32 A-store (single fp16 plane): row = t>>1, K16-select sub = t&1.
#define STA_K32S(Sbase) do { \
        uint32_t* Ap = (Sbase) + sub * 1024; \
        Ap[IDX(row, 0)] = packh(ra0.x, ra0.y); \
        Ap[IDX(row, 1)] = packh(ra0.z, ra0.w); \
        Ap[IDX(row, 2)] = packh(ra1.x, ra1.y); \
        Ap[IDX(row, 3)] = packh(ra1.z, ra1.w); \
        Ap[IDX(row, 4)] = packh(ra2.x, ra2.y); \
        Ap[IDX(row, 5)] = packh(ra2.z, ra2.w); \
        Ap[IDX(row, 6)] = packh(ra3.x, ra3.y); \
        Ap[IDX(row, 7)] = packh(ra3.z, ra3.w); \
    } while (0)

// chunk32 buffer (u32, 4096): [A0 1024][A1 1024][B0 1024][B1 1024]

// ======================= combined fused 2-layer MLP (occ 2) ==================
// dyn smem (u32): stage1 ring 2 x 4096 = [0,8192); stage2 A region [0,8192),
// stage2 B ring 2 x 2048 at [8192,12288).
#define MLP2_DSMEM (12288 * 4)

__global__ __launch_bounds__(256, 2)
void mlp2_multi(MlpP p0, MlpP p1, MlpP p2)
{
    extern __shared__ __align__(16) uint32_t sm[];
    __shared__ float sb0[128];

    int bx = blockIdx.x;
    MlpP p;
    if (bx < p0.gx) { p = p0; }
    else if (bx < p0.gx + p1.gx) { p = p1; bx -= p0.gx; }
    else { p = p2; bx -= p0.gx + p1.gx; }

    const int t = threadIdx.x, lane = t & 31, wid = t >> 5;
    const int m0 = bx * 128;

    if (t < 128) sb0[t] = p.b0[t];

    float acc1[16][4];
#pragma unroll
    for (int i = 0; i < 16; i++)
#pragma unroll
        for (int j = 0; j < 4; j++) acc1[i][j] = 0.f;

    const int row = t >> 1;
    const int sub = t & 1;
    const int grow = m0 + row;
    int arow = (p.perm ? (grow ^ 1) : grow);
    if (grow >= p.N) arow = 0;
    float4 ra0, ra1, ra2, ra3;

#define LDA1(ch) do { \
        const float* pp = p.A0 + (size_t)arow * 128 + ((ch) << 5) + sub * 16; \
        ra0 = *(const float4*)pp;       ra1 = *(const float4*)(pp + 4); \
        ra2 = *(const float4*)(pp + 8); ra3 = *(const float4*)(pp + 12); \
    } while (0)
#define CPW1(wb, ch, buf) do { \
        _Pragma("unroll") \
        for (int si = 0; si < 2; si++) { \
            const uint32_t* gp = (wb) + ((size_t)(2 * (ch) + si) << 10) + t * 4; \
            cp16(smem_u32(sm + (buf) * 4096 + 2048 + si * 1024 + t * 4), gp); \
        } \
    } while (0)
#define CPW2(ch, buf) do { \
        _Pragma("unroll") \
        for (int si = 0; si < 2; si++) { \
            const uint32_t* gp = p.W1 + ((size_t)(2 * (ch) + si) << 10) + t * 4; \
            cp16(smem_u32(sm + 8192 + (buf) * 2048 + si * 1024 + t * 4), gp); \
        } \
    } while (0)

    // ---- stage 1: 4 K32 chunks, 2-deep ring ----
    LDA1(0); CPW1(p.W0, 0, 0); CP_COMMIT();
    STA_K32S(sm + 0 * 4096);
    LDA1(1);
    CP_WAIT0(); __syncthreads();
    for (int ch = 0; ch < 4; ch++) {
        if (ch + 1 < 4) {
            const int nb = (ch + 1) & 1;
            CPW1(p.W0, ch + 1, nb); CP_COMMIT();
            STA_K32S(sm + nb * 4096);
        }
        if (ch + 2 < 4) LDA1(ch + 2);
        const uint32_t* S = sm + (ch & 1) * 4096;
        mma_chunk(S,        S + 2048, acc1, lane, wid);
        mma_chunk(S + 1024, S + 3072, acc1, lane, wid);
        if (ch + 1 < 4) { CP_WAIT0(); __syncthreads(); }
    }
    __syncthreads();

    // ---- bias + relu, spill stage-1 result into A region (fp16 planes) ----
    {
        const int rlo = wid * 16 + (lane >> 2);
        const int rhi = rlo + 8;
#pragma unroll
        for (int nt = 0; nt < 16; nt++) {
            const int col = nt * 8 + 2 * (lane & 3);
            float bx2 = sb0[col], by = sb0[col + 1];
            float v0 = fmaxf(acc1[nt][0] + bx2, 0.f);
            float v1 = fmaxf(acc1[nt][1] + by, 0.f);
            float v2 = fmaxf(acc1[nt][2] + bx2, 0.f);
            float v3 = fmaxf(acc1[nt][3] + by, 0.f);
            const int ch16 = nt >> 1;
            const int q = (nt & 1) * 4 + (lane & 3);
            sm[ch16 * 1024 + IDX(rlo, q)] = packh(v0, v1);
            sm[ch16 * 1024 + IDX(rhi, q)] = packh(v2, v3);
        }
    }

    float acc2[16][4];
#pragma unroll
    for (int i = 0; i < 16; i++)
#pragma unroll
        for (int j = 0; j < 4; j++) acc2[i][j] = 0.f;

    // ---- stage 2: A from smem region, W1 streamed, 4 K32 chunks ----
    CPW2(0, 0); CP_COMMIT();
    CP_WAIT0(); __syncthreads();   // also publishes the spill
    for (int ch = 0; ch < 4; ch++) {
        if (ch + 1 < 4) { CPW2(ch + 1, (ch + 1) & 1); CP_COMMIT(); }
        const uint32_t* B = sm + 8192 + (ch & 1) * 2048;
        mma_chunk(sm + (2 * ch) * 1024,     B,        acc2, lane, wid);
        mma_chunk(sm + (2 * ch + 1) * 1024, B + 1024, acc2, lane, wid);
        if (ch + 1 < 4) { CP_WAIT0(); __syncthreads(); }
    }

    // ---- epilogue: fp32 or fragment-plane output ----
    const int rl0 = wid * 16 + (lane >> 2);
    const int rl1 = rl0 + 8;
    if (p.opl) {
#pragma unroll
        for (int nt = 0; nt < 16; nt++) {
            const int col = nt * 8 + 2 * (lane & 3);
            float bx2 = p.b1[col], by = p.b1[col + 1];
            float v0 = acc2[nt][0] + bx2, v1 = acc2[nt][1] + by;
            float v2 = acc2[nt][2] + bx2, v3 = acc2[nt][3] + by;
            const int pq = nt * 4 + (lane & 3);
            const int chunk = pq >> 3, q = pq & 7;
            const size_t base = ((size_t)(bx * 8 + chunk)) << 10;
            p.opl[base + IDX(rl0, q)] = packh(v0, v1);
            p.opl[base + IDX(rl1, q)] = packh(v2, v3);
        }
    } else {
        const int r0 = m0 + rl0;
#pragma unroll
        for (int nt = 0; nt < 16; nt++) {
            const int col = nt * 8 + 2 * (lane & 3);
            float bx2 = p.b1[col], by = p.b1[col + 1];
            if (r0 < p.N)
                *(float2*)(p.out + (size_t)r0 * 128 + col) =
                    make_float2(acc2[nt][0] + bx2, acc2[nt][1] + by);
            if (r0 + 8 < p.N)
                *(float2*)(p.out + (size_t)(r0 + 8) * 128 + col) =
                    make_float2(acc2[nt][2] + bx2, acc2[nt][3] + by);
        }
    }
#undef LDA1
#undef CPW1
#undef CPW2
}

// ======================= combined GRU gate GEMM (all-async A+B) ==============
// grid (pc.gx + pl.gx, 4). y: 0=r, 1=z (sigmoid -> rz), 2=n_input, 3=n_hidden (-> nbuf)
#define GRU_DSMEM (3 * 4096 * 4)

__global__ __launch_bounds__(256, 2)
void gru_gemm_multi(GruP pc, GruP pl)
{
    extern __shared__ __align__(16) uint32_t sm[];

    int bx = blockIdx.x;
    GruP p;
    if (bx < pc.gx) { p = pc; }
    else { p = pl; bx -= pc.gx; }

    const int t = threadIdx.x, lane = t & 31, wid = t >> 5;
    const int m0 = bx * 128;
    const int g  = blockIdx.y;
    const int nchi = p.n0 + p.n1;
    const int nch32 = (g < 2) ? (nchi + 8) >> 1 : (g == 2 ? nchi >> 1 : 4);
    const int blk8 = bx * 8;

    float acc[16][4];
#pragma unroll
    for (int i = 0; i < 16; i++)
#pragma unroll
        for (int j = 0; j < 4; j++) acc[i][j] = 0.f;

#define CPA(ch, buf) do { \
        _Pragma("unroll") \
        for (int si = 0; si < 2; si++) { \
            const int c16 = 2 * (ch) + si; \
            const uint32_t* sp; int cl; \
            if (g == 3)            { sp = p.H;  cl = c16; } \
            else if (c16 < p.n0)   { sp = p.S0; cl = c16; } \
            else if (c16 < nchi)   { sp = p.S1; cl = c16 - p.n0; } \
            else                   { sp = p.H;  cl = c16 - nchi; } \
            const uint32_t* gp = sp + ((size_t)(blk8 + cl) << 10) + t * 4; \
            cp16(smem_u32(sm + (buf) * 4096 + si * 1024 + t * 4), gp); \
        } \
    } while (0)
#define CPW(ch, buf) do { \
        _Pragma("unroll") \
        for (int si = 0; si < 2; si++) { \
            const int c16 = 2 * (ch) + si; \
            const uint32_t* gp; \
            if (g < 2) gp = (c16 < nchi) \
                ? p.Wih + (((size_t)(g * nchi + c16)) << 10) + t * 4 \
                : p.Whh + (((size_t)(g * 8 + c16 - nchi)) << 10) + t * 4; \
            else if (g == 2) gp = p.Wih + (((size_t)(2 * nchi + c16)) << 10) + t * 4; \
            else gp = p.Whh + (((size_t)(16 + c16)) << 10) + t * 4; \
            cp16(smem_u32(sm + (buf) * 4096 + 2048 + si * 1024 + t * 4), gp); \
        } \
    } while (0)

    CPA(0, 0); CPW(0, 0); CP_COMMIT();
    if (nch32 > 1) { CPA(1, 1); CPW(1, 1); CP_COMMIT(); CP_WAIT1(); }
    else CP_WAIT0();
    __syncthreads();
    for (int ch = 0; ch < nch32; ch++) {
        if (ch + 2 < nch32) { CPA(ch + 2, (ch + 2) % 3); CPW(ch + 2, (ch + 2) % 3); CP_COMMIT(); }
        const uint32_t* S = sm + (ch % 3) * 4096;
        mma_chunk(S,        S + 2048, acc, lane, wid);
        mma_chunk(S + 1024, S + 3072, acc, lane, wid);
        if (ch + 1 < nch32) {
            if (ch + 2 < nch32) CP_WAIT1(); else CP_WAIT0();
            __syncthreads();
        }
    }

    const int r0 = m0 + wid * 16 + (lane >> 2);
    if (g < 2) {
#pragma unroll
        for (int nt = 0; nt < 16; nt++) {
            const int col = nt * 8 + 2 * (lane & 3);
            float bx2 = p.bih[g * 128 + col]     + p.bhh[g * 128 + col];
            float by  = p.bih[g * 128 + col + 1] + p.bhh[g * 128 + col + 1];
            if (r0 < p.N)
                *(float2*)(p.rz + (size_t)r0 * 256 + g * 128 + col) =
                    make_float2(fsigmoid(acc[nt][0] + bx2), fsigmoid(acc[nt][1] + by));
            if (r0 + 8 < p.N)
                *(float2*)(p.rz + (size_t)(r0 + 8) * 256 + g * 128 + col) =
                    make_float2(fsigmoid(acc[nt][2] + bx2), fsigmoid(acc[nt][3] + by));
        }
    } else {
        const float* bs = (g == 2) ? p.bih : p.bhh;
        const int go = (g - 2) * 128;
#pragma unroll
        for (int nt = 0; nt < 16; nt++) {
            const int col = nt * 8 + 2 * (lane & 3);
            float bx2 = bs[256 + col], by = bs[256 + col + 1];
            if (r0 < p.N)
                *(float2*)(p.nbuf + (size_t)r0 * 256 + go + col) =
                    make_float2(acc[nt][0] + bx2, acc[nt][1] + by);
            if (r0 + 8 < p.N)
                *(float2*)(p.nbuf + (size_t)(r0 + 8) * 256 + go + col) =
                    make_float2(acc[nt][2] + bx2, acc[nt][3] + by);
        }
    }
#undef CPA
#undef CPW
}

// ======================= CSR build ===========================================
__global__ void hist2(const int* __restrict__ l_e, const int* __restrict__ c_e,
                      int* __restrict__ cnt_l, int* __restrict__ cnt_c, int E)
{
    int i = blockIdx.x * blockDim.x + threadIdx.x;
    if (i < E) {
        atomicAdd(&cnt_l[l_e[i]], 1);
        atomicAdd(&cnt_c[c_e[i]], 1);
    }
}

__global__ void exscan(const int* __restrict__ cnt, int* __restrict__ off, int n)
{
    __shared__ int part[1024];
    const int t = threadIdx.x;
    const int chunk = (n + 1023) >> 10;
    const int b = t * chunk;
    const int e = min(b + chunk, n);
    int s = 0;
    for (int i = b; i < e; i++) s += cnt[i];
    part[t] = s;
    __syncthreads();
    for (int d = 1; d < 1024; d <<= 1) {
        int v = (t >= d) ? part[t - d] : 0;
        __syncthreads();
        if (t >= d) part[t] += v;
        __syncthreads();
    }
    int run = (t == 0) ? 0 : part[t - 1];
    for (int i = b; i < e; i++) { off[i] = run; run += cnt[i]; }
    if (t == 0) off[n] = part[1023];
}

__global__ void fill2(const int* __restrict__ l_e, const int* __restrict__ c_e,
                      int* __restrict__ cur_l, int* __restrict__ cur_c,
                      int* __restrict__ src_l, int* __restrict__ src_c, int E)
{
    int i = blockIdx.x * blockDim.x + threadIdx.x;
    if (i < E) {
        int l = l_e[i], c = c_e[i];
        src_c[atomicAdd(&cur_c[c], 1)] = l;
        src_l[atomicAdd(&cur_l[l], 1)] = c;
    }
}

// ======================= combined gather-sum (writes fp16 planes) ============
__global__ __launch_bounds__(256)
void gather2(const float* __restrict__ msgA, const int* __restrict__ offA,
             const int* __restrict__ srcA, uint32_t* __restrict__ aplA, int nA,
             const float* __restrict__ msgB, const int* __restrict__ offB,
             const int* __restrict__ srcB, uint32_t* __restrict__ aplB, int nB)
{
    int node = blockIdx.x * 8 + (threadIdx.x >> 5);
    int lane = threadIdx.x & 31;
    const float* msg;
    const int *off, *srcs;
    uint32_t* apl;
    if (node < nA) { msg = msgA; off = offA; srcs = srcA; apl = aplA; }
    else {
        node -= nA;
        if (node >= nB) return;
        msg = msgB; off = offB; srcs = srcB; apl = aplB;
    }
    int b = off[node], e = off[node + 1];
    float4 acc = {0.f, 0.f, 0.f, 0.f};
    for (int i = b; i < e; i++) {
        const float4 v = *((const float4*)(msg + (size_t)srcs[i] * DIM) + lane);
        acc.x += v.x; acc.y += v.y; acc.z += v.z; acc.w += v.w;
    }
    const int rl = node & 127;
    const int chunk = lane >> 2;
    const int q0 = (2 * lane) & 7;
    const size_t base = ((size_t)((node >> 7) * 8 + chunk)) << 10;
    apl[base + IDX(rl, q0)]     = packh(acc.x, acc.y);
    apl[base + IDX(rl, q0 + 1)] = packh(acc.z, acc.w);
}

// ---------------- combined GRU elementwise (writes fp32 + fp16 planes) -------
__global__ void gru_elem2x2(const float* __restrict__ rzA, const float* __restrict__ nA,
                            const float* __restrict__ hA, float* __restrict__ hnA,
                            uint32_t* __restrict__ plA, int NA,
                            const float* __restrict__ rzB, const float* __restrict__ nB,
                            const float* __restrict__ hB, float* __restrict__ hnB,
                            uint32_t* __restrict__ plB, int NB)
{
    int idx = blockIdx.x * blockDim.x + threadIdx.x;
    int row = idx >> 5, c4 = (idx & 31) * 4;
    const float *rz, *nbuf, *h;
    float* hnew;
    uint32_t* pl;
    if (row < NA) { rz = rzA; nbuf = nA; h = hA; hnew = hnA; pl = plA; }
    else {
        row -= NA;
        if (row >= NB) return;
        rz = rzB; nbuf = nB; h = hB; hnew = hnB; pl = plB;
    }
    const float4 r4 = *(const float4*)(rz + (size_t)row * 256 + c4);
    const float4 z4 = *(const float4*)(rz + (size_t)row * 256 + 128 + c4);
    const float4 ni = *(const float4*)(nbuf + (size_t)row * 256 + c4);
    const float4 nh = *(const float4*)(nbuf + (size_t)row * 256 + 128 + c4);
    const float4 h4 = *(const float4*)(h + (size_t)row * 128 + c4);
    float4 o;
    o.x = (1.f - z4.x) * ftanh(ni.x + r4.x * nh.x) + z4.x * h4.x;
    o.y = (1.f - z4.y) * ftanh(ni.y + r4.y * nh.y) + z4.y * h4.y;
    o.z = (1.f - z4.z) * ftanh(ni.z + r4.z * nh.z) + z4.z * h4.z;
    o.w = (1.f - z4.w) * ftanh(ni.w + r4.w * nh.w) + z4.w * h4.w;
    *(float4*)(hnew + (size_t)row * 128 + c4) = o;
    const int rl = row & 127;
    const int q0 = (c4 >> 1) & 7;
    const size_t base = ((size_t)((row >> 7) * 8 + (c4 >> 4))) << 10;
    pl[base + IDX(rl, q0)]     = packh(o.x, o.y);
    pl[base + IDX(rl, q0 + 1)] = packh(o.z, o.w);
}

// ---------------- launch ------------------------------------------------------
extern "C" void kernel_launch(void* const* d_in, const int* in_sizes, int n_in,
                              void* d_out, int out_size)
{
    const int D = DIM;
    const int E = in_sizes[2];
    const int L = in_sizes[4] / D;
    const int C = in_sizes[5] / D;

    const int*   l_edge = (const int*)d_in[2];
    const int*   c_edge = (const int*)d_in[3];
    const float* l_emb0 = (const float*)d_in[4];
    const float* c_emb0 = (const float*)d_in[5];

    const float* l2c_W0 = (const float*)d_in[6];
    const float* l2c_b0 = (const float*)d_in[7];
    const float* l2c_W1 = (const float*)d_in[8];
    const float* l2c_b1 = (const float*)d_in[9];
    const float* c2l_W0 = (const float*)d_in[10];
    const float* c2l_b0 = (const float*)d_in[11];
    const float* c2l_W1 = (const float*)d_in[12];
    const float* c2l_b1 = (const float*)d_in[13];
    const float* l2l_W0 = (const float*)d_in[14];
    const float* l2l_b0 = (const float*)d_in[15];
    const float* l2l_W1 = (const float*)d_in[16];
    const float* l2l_b1 = (const float*)d_in[17];
    const float* c_Wih  = (const float*)d_in[18];
    const float* c_Whh  = (const float*)d_in[19];
    const float* c_bih  = (const float*)d_in[20];
    const float* c_bhh  = (const float*)d_in[21];
    const float* l_Wih  = (const float*)d_in[22];
    const float* l_Whh  = (const float*)d_in[23];
    const float* l_bih  = (const float*)d_in[24];
    const float* l_bhh  = (const float*)d_in[25];

    float* out   = (float*)d_out;
    float* louts = out;                                // [9, L, D]
    float* couts = out + (size_t)(NITER + 1) * L * D;  // [9, C, D]

    float *l2c_msg, *c2l_msg, *rz_c, *n_c, *rz_l, *n_l;
    cudaGetSymbolAddress((void**)&l2c_msg, g_l2c_msg);
    cudaGetSymbolAddress((void**)&c2l_msg, g_c2l_msg);
    cudaGetSymbolAddress((void**)&rz_c,    g_rz_c);
    cudaGetSymbolAddress((void**)&n_c,     g_n_c);
    cudaGetSymbolAddress((void**)&rz_l,    g_rz_l);
    cudaGetSymbolAddress((void**)&n_l,     g_n_l);

    uint32_t *ac, *al, *mpl, *hc, *hl;
    cudaGetSymbolAddress((void**)&ac,  g_ac);
    cudaGetSymbolAddress((void**)&al,  g_al);
    cudaGetSymbolAddress((void**)&mpl, g_m);
    cudaGetSymbolAddress((void**)&hc,  g_hc);
    cudaGetSymbolAddress((void**)&hl,  g_hl);

    int *cnt_c, *cnt_l, *off_c, *off_l, *cur_c, *cur_l, *src_c, *src_l;
    cudaGetSymbolAddress((void**)&cnt_c, g_cnt_c);
    cudaGetSymbolAddress((void**)&cnt_l, g_cnt_l);
    cudaGetSymbolAddress((void**)&off_c, g_off_c);
    cudaGetSymbolAddress((void**)&off_l, g_off_l);
    cudaGetSymbolAddress((void**)&cur_c, g_cur_c);
    cudaGetSymbolAddress((void**)&cur_l, g_cur_l);
    cudaGetSymbolAddress((void**)&src_c, g_src_c);
    cudaGetSymbolAddress((void**)&src_l, g_src_l);

    uint32_t* whi;
    cudaGetSymbolAddress((void**)&whi, g_whi);

    cudaFuncSetAttribute(mlp2_multi, cudaFuncAttributeMaxDynamicSharedMemorySize,
                         MLP2_DSMEM);
    cudaFuncSetAttribute(gru_gemm_multi, cudaFuncAttributeMaxDynamicSharedMemorySize,
                         GRU_DSMEM);

    const int o_l2c0 = 0,      o_l2c1 = 8192,  o_c2l0 = 16384, o_c2l1 = 24576;
    const int o_l2l0 = 32768,  o_l2l1 = 40960;
    const int o_cih  = 49152,  o_chh  = 73728;
    const int o_lih  = 98304,  o_lhh  = 147456;

    // ---- pre-convert weights (fp16 single plane) ----
    split_w<<<32, 256>>>(l2c_W0, whi + o_l2c0, 8192, 64);
    split_w<<<32, 256>>>(l2c_W1, whi + o_l2c1, 8192, 64);
    split_w<<<32, 256>>>(c2l_W0, whi + o_c2l0, 8192, 64);
    split_w<<<32, 256>>>(c2l_W1, whi + o_c2l1, 8192, 64);
    split_w<<<32, 256>>>(l2l_W0, whi + o_l2l0, 8192, 64);
    split_w<<<32, 256>>>(l2l_W1, whi + o_l2l1, 8192, 64);
    split_w<<<96, 256>>>(c_Wih,  whi + o_cih,  24576, 64);
    split_w<<<96, 256>>>(c_Whh,  whi + o_chh,  24576, 64);
    split_w<<<192, 256>>>(l_Wih, whi + o_lih,  49152, 128);
    split_w<<<96, 256>>>(l_Whh,  whi + o_lhh,  24576, 64);

    // ---- CSR build ----
    cudaMemsetAsync(cnt_c, 0, (size_t)C * sizeof(int));
    cudaMemsetAsync(cnt_l, 0, (size_t)L * sizeof(int));
    hist2<<<(E + 255) / 256, 256>>>(l_edge, c_edge, cnt_l, cnt_c, E);
    exscan<<<1, 1024>>>(cnt_c, off_c, C);
    exscan<<<1, 1024>>>(cnt_l, off_l, L);
    cudaMemcpyAsync(cur_c, off_c, (size_t)C * sizeof(int), cudaMemcpyDeviceToDevice);
    cudaMemcpyAsync(cur_l, off_l, (size_t)L * sizeof(int), cudaMemcpyDeviceToDevice);
    fill2<<<(E + 255) / 256, 256>>>(l_edge, c_edge, cur_l, cur_c, src_l, src_c, E);

    // iteration-0 slices = inputs; seed state planes
    cudaMemcpyAsync(louts, l_emb0, (size_t)L * D * sizeof(float), cudaMemcpyDeviceToDevice);
    cudaMemcpyAsync(couts, c_emb0, (size_t)C * D * sizeof(float), cudaMemcpyDeviceToDevice);
    split_act<<<(L * 64 + 255) / 256, 256>>>(l_emb0, hl, L);
    split_act<<<(C * 64 + 255) / 256, 256>>>(c_emb0, hc, C);

    const int gLx = (L + 127) / 128;
    const int gCx = (C + 127) / 128;
    const int total_nodes = C + L;
    const dim3 gGemm(gCx + gLx, 4);

    for (int it = 0; it < NITER; it++) {
        const float* l_prev = louts + (size_t)it * L * D;
        const float* c_prev = couts + (size_t)it * C * D;
        float* l_next = louts + (size_t)(it + 1) * L * D;
        float* c_next = couts + (size_t)(it + 1) * C * D;

        // phase 1: all three message MLPs in one launch
        MlpP p0 = {l_prev, whi + o_l2c0, l2c_b0, whi + o_l2c1, l2c_b1,
                   l2c_msg, nullptr, L, 0, gLx};
        MlpP p1 = {c_prev, whi + o_c2l0, c2l_b0, whi + o_c2l1, c2l_b1,
                   c2l_msg, nullptr, C, 0, gCx};
        MlpP p2 = {l_prev, whi + o_l2l0, l2l_b0, whi + o_l2l1, l2l_b1,
                   nullptr, mpl, L, 1, gLx};
        mlp2_multi<<<gLx + gCx + gLx, 256, MLP2_DSMEM>>>(p0, p1, p2);

        // phase 2: both gathers in one launch (write fp16 planes)
        gather2<<<(total_nodes + 7) / 8, 256>>>(l2c_msg, off_c, src_c, ac, C,
                                                c2l_msg, off_l, src_l, al, L);

        // phase 3: all GRU gate GEMMs in one launch (all-async)
        GruP pc = {ac, nullptr, hc, 8, 0,
                   whi + o_cih, whi + o_chh, c_bih, c_bhh, rz_c, n_c, C, gCx};
        GruP pl = {al, mpl, hl, 8, 8,
                   whi + o_lih, whi + o_lhh, l_bih, l_bhh, rz_l, n_l, L, gLx};
        gru_gemm_multi<<<gGemm, 256, GRU_DSMEM>>>(pc, pl);

        // phase 4: both elementwise GRU updates (fp32 + next-state planes)
        gru_elem2x2<<<(total_nodes * 32 + 255) / 256, 256>>>(
            rz_c, n_c, c_prev, c_next, hc, C,
            rz_l, n_l, l_prev, l_next, hl, L);
    }
}

// round 16
// speedup vs baseline: 2.1376x; 1.0556x over previous
#include <cuda_runtime.h>
#include <cuda_fp16.h>
#include <cstdint>

// Problem constants (fixed by setup_inputs)
#define DIM   128
#define LMAX  60000
#define CMAX  30000
#define EMAX  360000
#define NITER 8

#define CBLK ((CMAX + 127) / 128)
#define LBLK ((LMAX + 127) / 128)
#define CPLANE ((size_t)CBLK * 8192)
#define LPLANE ((size_t)LBLK * 8192)

// ---------------- scratch (device globals; no allocations allowed) ----------
__device__ uint32_t g_l2c_msg[(size_t)LMAX * 64];   // half2 row-major
__device__ uint32_t g_c2l_msg[(size_t)CMAX * 64];
__device__ float g_rz_c[(size_t)CMAX * 2 * DIM];
__device__ float g_n_c [(size_t)CMAX * 2 * DIM];
__device__ float g_rz_l[(size_t)LMAX * 2 * DIM];
__device__ float g_n_l [(size_t)LMAX * 2 * DIM];
// fragment-ordered fp16 activation planes (u32 = 2 fp16)
__device__ uint32_t g_ac[CPLANE];    // clause aggr
__device__ uint32_t g_al[LPLANE];    // literal aggr
__device__ uint32_t g_m [LPLANE];    // l2l message
__device__ uint32_t g_hc[CPLANE];    // clause state
__device__ uint32_t g_hl[LPLANE];    // literal state
__device__ uint32_t g_hlp[LPLANE];   // literal state, row^1-permuted
// CSR scratch
__device__ int g_cnt_c[CMAX];
__device__ int g_cnt_l[LMAX];
__device__ int g_off_c[CMAX + 1];
__device__ int g_off_l[LMAX + 1];
__device__ int g_cur_c[CMAX];
__device__ int g_cur_l[LMAX];
__device__ int g_src_c[EMAX];
__device__ int g_src_l[EMAX];
// pre-converted fp16 weight planes
#define WSPLIT_TOTAL 172032
__device__ uint32_t g_whi[WSPLIT_TOTAL];

// ======================= helpers =============================================
__device__ __forceinline__ uint32_t smem_u32(const void* p) {
    uint32_t a;
    asm("{ .reg .u64 t; cvta.to.shared.u64 t, %1; cvt.u32.u64 %0, t; }"
        : "=r"(a) : "l"(p));
    return a;
}

__device__ __forceinline__ uint32_t packh(float x, float y) {
    __half2 h = __floats2half2_rn(x, y);
    return *reinterpret_cast<uint32_t*>(&h);
}

__device__ __forceinline__ float2 unpackh(uint32_t u) {
    __half2 h = *reinterpret_cast<__half2*>(&u);
    return __half22float2(h);
}

__device__ __forceinline__ void cp16(uint32_t dst, const void* src) {
    asm volatile("cp.async.ca.shared.global [%0], [%1], 16;"
                 :: "r"(dst), "l"(src) : "memory");
}
#define CP_COMMIT() asm volatile("cp.async.commit_group;" ::: "memory")
#define CP_WAIT0()  asm volatile("cp.async.wait_group 0;" ::: "memory")
#define CP_WAIT1()  asm volatile("cp.async.wait_group 1;" ::: "memory")

__device__ __forceinline__ void mma_f16(float* d, const uint32_t* a,
                                        uint32_t b0, uint32_t b1) {
    asm volatile(
        "mma.sync.aligned.m16n8k16.row.col.f32.f16.f16.f32 "
        "{%0,%1,%2,%3}, {%4,%5,%6,%7}, {%8,%9}, {%0,%1,%2,%3};"
        : "+f"(d[0]), "+f"(d[1]), "+f"(d[2]), "+f"(d[3])
        : "r"(a[0]), "r"(a[1]), "r"(a[2]), "r"(a[3]), "r"(b0), "r"(b1));
}

#define IDX(r, q) ((((r) << 3)) | ((q) ^ ((r) & 7)))

__device__ __forceinline__ float fsigmoid(float x) { return 1.f / (1.f + __expf(-x)); }
__device__ __forceinline__ float ftanh(float x) {
    float t = __expf(2.f * fabsf(x));
    float r = 1.f - 2.f / (t + 1.f);
    return copysignf(r, x);
}

// ======================= weight pre-convert (fp16 single plane) ==============
__global__ void split_w(const float* __restrict__ W, uint32_t* __restrict__ hi,
                        int total_pairs, int kp)
{
    int i = blockIdx.x * 256 + threadIdx.x;
    if (i >= total_pairs) return;
    int R = i / kp, p = i - R * kp;
    float2 f = ((const float2*)W)[i];
    uint32_t h = packh(f.x, f.y);
    int ngroup = R >> 7, n = R & 127;
    int ch = p >> 3, q = p & 7;
    int nt = n >> 3, l4 = n & 7;
    int region = l4 * 4 + (q & 3);
    int idx = region * 32 + (((nt >> 1) ^ (region & 7)) << 2) + ((nt & 1) << 1) + (q >> 2);
    size_t base = ((size_t)(ngroup * (kp >> 3) + ch)) << 10;
    hi[base + idx] = h;
}

// ======================= activation pre-split ================================
// X [N,128] fp32 -> plane; value of row `row` stored at plane position row^perm
__global__ void split_act(const float* __restrict__ X, uint32_t* __restrict__ pl,
                          int N, int perm)
{
    int i = blockIdx.x * 256 + threadIdx.x;
    if (i >= N * 64) return;
    int row = i >> 6, pp = i & 63;
    float2 f = ((const float2*)X)[i];
    int rowp = row ^ perm;
    int chunk = pp >> 3, q = pp & 7, rl = rowp & 127;
    size_t base = ((size_t)((rowp >> 7) * 8 + chunk)) << 10;
    pl[base + IDX(rl, q)] = packh(f.x, f.y);
}

// ======================= MMA K16 sub-chunk ===================================
__device__ __forceinline__ void mma_chunk(const uint32_t* __restrict__ A,
                                          const uint32_t* __restrict__ B,
                                          float (&acc)[16][4], int lane, int wid)
{
    const int r = wid * 16 + (lane >> 2);
    const int q = lane & 3;
    uint32_t ah[4];
    ah[0] = A[IDX(r, q)];     ah[1] = A[IDX(r + 8, q)];
    ah[2] = A[IDX(r, q + 4)]; ah[3] = A[IDX(r + 8, q + 4)];
    const uint32_t* Bp = B + lane * 32;
#pragma unroll
    for (int c = 0; c < 8; c++) {
        const int sw = ((c ^ (lane & 7)) << 2);
        uint4 v = *(const uint4*)(Bp + sw);
        mma_f16(acc[2 * c],     ah, v.x, v.y);
        mma_f16(acc[2 * c + 1], ah, v.z, v.w);
    }
}

// ======================= param structs =======================================
struct MlpP {
    const uint32_t* Apl;        // fp16 A plane (fragment-ordered)
    const uint32_t* W0;
    const float* b0;
    const uint32_t* W1;
    const float* b1;
    uint32_t* omsg;             // half2 row-major msg output (may be null)
    uint32_t* opl;              // plane output (may be null)
    int N, gx;
};

struct GruP {
    const uint32_t *S0, *S1, *H;
    int n0, n1;
    const uint32_t *Wih, *Whh;
    const float *bih, *bhh;
    float *rz, *nbuf;
    int N, gx;
};

// chunk32 buffer (u32, 4096): [A0 1024][A1 1024][B0 1024][B1 1024]

// ======================= combined fused 2-layer MLP (occ 2, all-async) =======
// dyn smem (u32): stage1 ring 3 x 4096 = [0,12288);
// stage2: A region [0,8192) (spill), B ring 2 x 2048 at [8192,12288).
#define MLP2_DSMEM (12288 * 4)

__global__ __launch_bounds__(256, 2)
void mlp2_multi(MlpP p0, MlpP p1, MlpP p2)
{
    extern __shared__ __align__(16) uint32_t sm[];
    __shared__ float sb0[128];

    int bx = blockIdx.x;
    MlpP p;
    if (bx < p0.gx) { p = p0; }
    else if (bx < p0.gx + p1.gx) { p = p1; bx -= p0.gx; }
    else { p = p2; bx -= p0.gx + p1.gx; }

    const int t = threadIdx.x, lane = t & 31, wid = t >> 5;
    const int m0 = bx * 128;
    const int blk8 = bx * 8;

    if (t < 128) sb0[t] = p.b0[t];

    float acc1[16][4];
#pragma unroll
    for (int i = 0; i < 16; i++)
#pragma unroll
        for (int j = 0; j < 4; j++) acc1[i][j] = 0.f;

#define CPA1(ch, buf) do { \
        _Pragma("unroll") \
        for (int si = 0; si < 2; si++) { \
            const uint32_t* gp = p.Apl + ((size_t)(blk8 + 2 * (ch) + si) << 10) + t * 4; \
            cp16(smem_u32(sm + (buf) * 4096 + si * 1024 + t * 4), gp); \
        } \
    } while (0)
#define CPW1(ch, buf) do { \
        _Pragma("unroll") \
        for (int si = 0; si < 2; si++) { \
            const uint32_t* gp = p.W0 + ((size_t)(2 * (ch) + si) << 10) + t * 4; \
            cp16(smem_u32(sm + (buf) * 4096 + 2048 + si * 1024 + t * 4), gp); \
        } \
    } while (0)
#define CPW2(ch, buf) do { \
        _Pragma("unroll") \
        for (int si = 0; si < 2; si++) { \
            const uint32_t* gp = p.W1 + ((size_t)(2 * (ch) + si) << 10) + t * 4; \
            cp16(smem_u32(sm + 8192 + (buf) * 2048 + si * 1024 + t * 4), gp); \
        } \
    } while (0)

    // ---- stage 1: 4 K32 chunks, 3-buffer ring, all-async ----
    CPA1(0, 0); CPW1(0, 0); CP_COMMIT();
    CPA1(1, 1); CPW1(1, 1); CP_COMMIT(); CP_WAIT1();
    __syncthreads();
    for (int ch = 0; ch < 4; ch++) {
        if (ch + 2 < 4) { CPA1(ch + 2, (ch + 2) % 3); CPW1(ch + 2, (ch + 2) % 3); CP_COMMIT(); }
        const uint32_t* S = sm + (ch % 3) * 4096;
        mma_chunk(S,        S + 2048, acc1, lane, wid);
        mma_chunk(S + 1024, S + 3072, acc1, lane, wid);
        if (ch + 1 < 4) {
            if (ch + 2 < 4) CP_WAIT1(); else CP_WAIT0();
            __syncthreads();
        }
    }
    __syncthreads();

    // ---- bias + relu, spill stage-1 result into A region (fp16 planes) ----
    {
        const int rlo = wid * 16 + (lane >> 2);
        const int rhi = rlo + 8;
#pragma unroll
        for (int nt = 0; nt < 16; nt++) {
            const int col = nt * 8 + 2 * (lane & 3);
            float bx2 = sb0[col], by = sb0[col + 1];
            float v0 = fmaxf(acc1[nt][0] + bx2, 0.f);
            float v1 = fmaxf(acc1[nt][1] + by, 0.f);
            float v2 = fmaxf(acc1[nt][2] + bx2, 0.f);
            float v3 = fmaxf(acc1[nt][3] + by, 0.f);
            const int ch16 = nt >> 1;
            const int q = (nt & 1) * 4 + (lane & 3);
            sm[ch16 * 1024 + IDX(rlo, q)] = packh(v0, v1);
            sm[ch16 * 1024 + IDX(rhi, q)] = packh(v2, v3);
        }
    }

    float acc2[16][4];
#pragma unroll
    for (int i = 0; i < 16; i++)
#pragma unroll
        for (int j = 0; j < 4; j++) acc2[i][j] = 0.f;

    // ---- stage 2: A from smem region, W1 streamed, 4 K32 chunks ----
    CPW2(0, 0); CP_COMMIT();
    CP_WAIT0(); __syncthreads();   // also publishes the spill
    for (int ch = 0; ch < 4; ch++) {
        if (ch + 1 < 4) { CPW2(ch + 1, (ch + 1) & 1); CP_COMMIT(); }
        const uint32_t* B = sm + 8192 + (ch & 1) * 2048;
        mma_chunk(sm + (2 * ch) * 1024,     B,        acc2, lane, wid);
        mma_chunk(sm + (2 * ch + 1) * 1024, B + 1024, acc2, lane, wid);
        if (ch + 1 < 4) { CP_WAIT0(); __syncthreads(); }
    }

    // ---- epilogue: half2 msg or fragment-plane output ----
    const int rl0 = wid * 16 + (lane >> 2);
    const int rl1 = rl0 + 8;
    if (p.opl) {
#pragma unroll
        for (int nt = 0; nt < 16; nt++) {
            const int col = nt * 8 + 2 * (lane & 3);
            float bx2 = p.b1[col], by = p.b1[col + 1];
            float v0 = acc2[nt][0] + bx2, v1 = acc2[nt][1] + by;
            float v2 = acc2[nt][2] + bx2, v3 = acc2[nt][3] + by;
            const int pq = nt * 4 + (lane & 3);
            const int chunk = pq >> 3, q = pq & 7;
            const size_t base = ((size_t)(bx * 8 + chunk)) << 10;
            p.opl[base + IDX(rl0, q)] = packh(v0, v1);
            p.opl[base + IDX(rl1, q)] = packh(v2, v3);
        }
    } else {
        const int r0 = m0 + rl0;
#pragma unroll
        for (int nt = 0; nt < 16; nt++) {
            const int col = nt * 8 + 2 * (lane & 3);
            float bx2 = p.b1[col], by = p.b1[col + 1];
            if (r0 < p.N)
                p.omsg[(size_t)r0 * 64 + (col >> 1)] =
                    packh(acc2[nt][0] + bx2, acc2[nt][1] + by);
            if (r0 + 8 < p.N)
                p.omsg[(size_t)(r0 + 8) * 64 + (col >> 1)] =
                    packh(acc2[nt][2] + bx2, acc2[nt][3] + by);
        }
    }
#undef CPA1
#undef CPW1
#undef CPW2
}

// ======================= combined GRU gate GEMM (all-async A+B) ==============
#define GRU_DSMEM (3 * 4096 * 4)

__global__ __launch_bounds__(256, 2)
void gru_gemm_multi(GruP pc, GruP pl)
{
    extern __shared__ __align__(16) uint32_t sm[];

    int bx = blockIdx.x;
    GruP p;
    if (bx < pc.gx) { p = pc; }
    else { p = pl; bx -= pc.gx; }

    const int t = threadIdx.x, lane = t & 31, wid = t >> 5;
    const int m0 = bx * 128;
    const int g  = blockIdx.y;
    const int nchi = p.n0 + p.n1;
    const int nch32 = (g < 2) ? (nchi + 8) >> 1 : (g == 2 ? nchi >> 1 : 4);
    const int blk8 = bx * 8;

    float acc[16][4];
#pragma unroll
    for (int i = 0; i < 16; i++)
#pragma unroll
        for (int j = 0; j < 4; j++) acc[i][j] = 0.f;

#define CPA(ch, buf) do { \
        _Pragma("unroll") \
        for (int si = 0; si < 2; si++) { \
            const int c16 = 2 * (ch) + si; \
            const uint32_t* sp; int cl; \
            if (g == 3)            { sp = p.H;  cl = c16; } \
            else if (c16 < p.n0)   { sp = p.S0; cl = c16; } \
            else if (c16 < nchi)   { sp = p.S1; cl = c16 - p.n0; } \
            else                   { sp = p.H;  cl = c16 - nchi; } \
            const uint32_t* gp = sp + ((size_t)(blk8 + cl) << 10) + t * 4; \
            cp16(smem_u32(sm + (buf) * 4096 + si * 1024 + t * 4), gp); \
        } \
    } while (0)
#define CPW(ch, buf) do { \
        _Pragma("unroll") \
        for (int si = 0; si < 2; si++) { \
            const int c16 = 2 * (ch) + si; \
            const uint32_t* gp; \
            if (g < 2) gp = (c16 < nchi) \
                ? p.Wih + (((size_t)(g * nchi + c16)) << 10) + t * 4 \
                : p.Whh + (((size_t)(g * 8 + c16 - nchi)) << 10) + t * 4; \
            else if (g == 2) gp = p.Wih + (((size_t)(2 * nchi + c16)) << 10) + t * 4; \
            else gp = p.Whh + (((size_t)(16 + c16)) << 10) + t * 4; \
            cp16(smem_u32(sm + (buf) * 4096 + 2048 + si * 1024 + t * 4), gp); \
        } \
    } while (0)

    CPA(0, 0); CPW(0, 0); CP_COMMIT();
    if (nch32 > 1) { CPA(1, 1); CPW(1, 1); CP_COMMIT(); CP_WAIT1(); }
    else CP_WAIT0();
    __syncthreads();
    for (int ch = 0; ch < nch32; ch++) {
        if (ch + 2 < nch32) { CPA(ch + 2, (ch + 2) % 3); CPW(ch + 2, (ch + 2) % 3); CP_COMMIT(); }
        const uint32_t* S = sm + (ch % 3) * 4096;
        mma_chunk(S,        S + 2048, acc, lane, wid);
        mma_chunk(S + 1024, S + 3072, acc, lane, wid);
        if (ch + 1 < nch32) {
            if (ch + 2 < nch32) CP_WAIT1(); else CP_WAIT0();
            __syncthreads();
        }
    }

    const int r0 = m0 + wid * 16 + (lane >> 2);
    if (g < 2) {
#pragma unroll
        for (int nt = 0; nt < 16; nt++) {
            const int col = nt * 8 + 2 * (lane & 3);
            float bx2 = p.bih[g * 128 + col]     + p.bhh[g * 128 + col];
            float by  = p.bih[g * 128 + col + 1] + p.bhh[g * 128 + col + 1];
            if (r0 < p.N)
                *(float2*)(p.rz + (size_t)r0 * 256 + g * 128 + col) =
                    make_float2(fsigmoid(acc[nt][0] + bx2), fsigmoid(acc[nt][1] + by));
            if (r0 + 8 < p.N)
                *(float2*)(p.rz + (size_t)(r0 + 8) * 256 + g * 128 + col) =
                    make_float2(fsigmoid(acc[nt][2] + bx2), fsigmoid(acc[nt][3] + by));
        }
    } else {
        const float* bs = (g == 2) ? p.bih : p.bhh;
        const int go = (g - 2) * 128;
#pragma unroll
        for (int nt = 0; nt < 16; nt++) {
            const int col = nt * 8 + 2 * (lane & 3);
            float bx2 = bs[256 + col], by = bs[256 + col + 1];
            if (r0 < p.N)
                *(float2*)(p.nbuf + (size_t)r0 * 256 + go + col) =
                    make_float2(acc[nt][0] + bx2, acc[nt][1] + by);
            if (r0 + 8 < p.N)
                *(float2*)(p.nbuf + (size_t)(r0 + 8) * 256 + go + col) =
                    make_float2(acc[nt][2] + bx2, acc[nt][3] + by);
        }
    }
#undef CPA
#undef CPW
}

// ======================= CSR build ===========================================
__global__ void hist2(const int* __restrict__ l_e, const int* __restrict__ c_e,
                      int* __restrict__ cnt_l, int* __restrict__ cnt_c, int E)
{
    int i = blockIdx.x * blockDim.x + threadIdx.x;
    if (i < E) {
        atomicAdd(&cnt_l[l_e[i]], 1);
        atomicAdd(&cnt_c[c_e[i]], 1);
    }
}

__global__ void exscan(const int* __restrict__ cnt, int* __restrict__ off, int n)
{
    __shared__ int part[1024];
    const int t = threadIdx.x;
    const int chunk = (n + 1023) >> 10;
    const int b = t * chunk;
    const int e = min(b + chunk, n);
    int s = 0;
    for (int i = b; i < e; i++) s += cnt[i];
    part[t] = s;
    __syncthreads();
    for (int d = 1; d < 1024; d <<= 1) {
        int v = (t >= d) ? part[t - d] : 0;
        __syncthreads();
        if (t >= d) part[t] += v;
        __syncthreads();
    }
    int run = (t == 0) ? 0 : part[t - 1];
    for (int i = b; i < e; i++) { off[i] = run; run += cnt[i]; }
    if (t == 0) off[n] = part[1023];
}

__global__ void fill2(const int* __restrict__ l_e, const int* __restrict__ c_e,
                      int* __restrict__ cur_l, int* __restrict__ cur_c,
                      int* __restrict__ src_l, int* __restrict__ src_c, int E)
{
    int i = blockIdx.x * blockDim.x + threadIdx.x;
    if (i < E) {
        int l = l_e[i], c = c_e[i];
        src_c[atomicAdd(&cur_c[c], 1)] = l;
        src_l[atomicAdd(&cur_l[l], 1)] = c;
    }
}

// ======================= combined gather-sum (fp16 msgs -> planes) ===========
__global__ __launch_bounds__(256)
void gather2(const uint32_t* __restrict__ msgA, const int* __restrict__ offA,
             const int* __restrict__ srcA, uint32_t* __restrict__ aplA, int nA,
             const uint32_t* __restrict__ msgB, const int* __restrict__ offB,
             const int* __restrict__ srcB, uint32_t* __restrict__ aplB, int nB)
{
    int node = blockIdx.x * 8 + (threadIdx.x >> 5);
    int lane = threadIdx.x & 31;
    const uint32_t* msg;
    const int *off, *srcs;
    uint32_t* apl;
    if (node < nA) { msg = msgA; off = offA; srcs = srcA; apl = aplA; }
    else {
        node -= nA;
        if (node >= nB) return;
        msg = msgB; off = offB; srcs = srcB; apl = aplB;
    }
    int b = off[node], e = off[node + 1];
    float4 acc = {0.f, 0.f, 0.f, 0.f};
    for (int i = b; i < e; i++) {
        const uint2 u = *(const uint2*)(msg + (size_t)srcs[i] * 64 + lane * 2);
        float2 a = unpackh(u.x), c = unpackh(u.y);
        acc.x += a.x; acc.y += a.y; acc.z += c.x; acc.w += c.y;
    }
    const int rl = node & 127;
    const int chunk = lane >> 2;
    const int q0 = (2 * lane) & 7;
    const size_t base = ((size_t)((node >> 7) * 8 + chunk)) << 10;
    apl[base + IDX(rl, q0)]     = packh(acc.x, acc.y);
    apl[base + IDX(rl, q0 + 1)] = packh(acc.z, acc.w);
}

// ---------------- combined GRU elementwise (fp32 out + planes [+perm]) -------
__global__ void gru_elem2x2(const float* __restrict__ rzA, const float* __restrict__ nA,
                            const float* __restrict__ hA, float* __restrict__ hnA,
                            uint32_t* __restrict__ plA, int NA,
                            const float* __restrict__ rzB, const float* __restrict__ nB,
                            const float* __restrict__ hB, float* __restrict__ hnB,
                            uint32_t* __restrict__ plB, uint32_t* __restrict__ plBp, int NB)
{
    int idx = blockIdx.x * blockDim.x + threadIdx.x;
    int row = idx >> 5, c4 = (idx & 31) * 4;
    const float *rz, *nbuf, *h;
    float* hnew;
    uint32_t *pl, *plp;
    if (row < NA) { rz = rzA; nbuf = nA; h = hA; hnew = hnA; pl = plA; plp = nullptr; }
    else {
        row -= NA;
        if (row >= NB) return;
        rz = rzB; nbuf = nB; h = hB; hnew = hnB; pl = plB; plp = plBp;
    }
    const float4 r4 = *(const float4*)(rz + (size_t)row * 256 + c4);
    const float4 z4 = *(const float4*)(rz + (size_t)row * 256 + 128 + c4);
    const float4 ni = *(const float4*)(nbuf + (size_t)row * 256 + c4);
    const float4 nh = *(const float4*)(nbuf + (size_t)row * 256 + 128 + c4);
    const float4 h4 = *(const float4*)(h + (size_t)row * 128 + c4);
    float4 o;
    o.x = (1.f - z4.x) * ftanh(ni.x + r4.x * nh.x) + z4.x * h4.x;
    o.y = (1.f - z4.y) * ftanh(ni.y + r4.y * nh.y) + z4.y * h4.y;
    o.z = (1.f - z4.z) * ftanh(ni.z + r4.z * nh.z) + z4.z * h4.z;
    o.w = (1.f - z4.w) * ftanh(ni.w + r4.w * nh.w) + z4.w * h4.w;
    *(float4*)(hnew + (size_t)row * 128 + c4) = o;
    const uint32_t u0 = packh(o.x, o.y), u1 = packh(o.z, o.w);
    const int q0 = (c4 >> 1) & 7;
    {
        const int rl = row & 127;
        const size_t base = ((size_t)((row >> 7) * 8 + (c4 >> 4))) << 10;
        pl[base + IDX(rl, q0)]     = u0;
        pl[base + IDX(rl, q0 + 1)] = u1;
    }
    if (plp) {
        const int rowp = row ^ 1;
        const int rl = rowp & 127;
        const size_t base = ((size_t)((rowp >> 7) * 8 + (c4 >> 4))) << 10;
        plp[base + IDX(rl, q0)]     = u0;
        plp[base + IDX(rl, q0 + 1)] = u1;
    }
}

// ---------------- launch ------------------------------------------------------
extern "C" void kernel_launch(void* const* d_in, const int* in_sizes, int n_in,
                              void* d_out, int out_size)
{
    const int D = DIM;
    const int E = in_sizes[2];
    const int L = in_sizes[4] / D;
    const int C = in_sizes[5] / D;

    const int*   l_edge = (const int*)d_in[2];
    const int*   c_edge = (const int*)d_in[3];
    const float* l_emb0 = (const float*)d_in[4];
    const float* c_emb0 = (const float*)d_in[5];

    const float* l2c_W0 = (const float*)d_in[6];
    const float* l2c_b0 = (const float*)d_in[7];
    const float* l2c_W1 = (const float*)d_in[8];
    const float* l2c_b1 = (const float*)d_in[9];
    const float* c2l_W0 = (const float*)d_in[10];
    const float* c2l_b0 = (const float*)d_in[11];
    const float* c2l_W1 = (const float*)d_in[12];
    const float* c2l_b1 = (const float*)d_in[13];
    const float* l2l_W0 = (const float*)d_in[14];
    const float* l2l_b0 = (const float*)d_in[15];
    const float* l2l_W1 = (const float*)d_in[16];
    const float* l2l_b1 = (const float*)d_in[17];
    const float* c_Wih  = (const float*)d_in[18];
    const float* c_Whh  = (const float*)d_in[19];
    const float* c_bih  = (const float*)d_in[20];
    const float* c_bhh  = (const float*)d_in[21];
    const float* l_Wih  = (const float*)d_in[22];
    const float* l_Whh  = (const float*)d_in[23];
    const float* l_bih  = (const float*)d_in[24];
    const float* l_bhh  = (const float*)d_in[25];

    float* out   = (float*)d_out;
    float* louts = out;                                // [9, L, D]
    float* couts = out + (size_t)(NITER + 1) * L * D;  // [9, C, D]

    uint32_t *l2c_msg, *c2l_msg;
    float *rz_c, *n_c, *rz_l, *n_l;
    cudaGetSymbolAddress((void**)&l2c_msg, g_l2c_msg);
    cudaGetSymbolAddress((void**)&c2l_msg, g_c2l_msg);
    cudaGetSymbolAddress((void**)&rz_c,    g_rz_c);
    cudaGetSymbolAddress((void**)&n_c,     g_n_c);
    cudaGetSymbolAddress((void**)&rz_l,    g_rz_l);
    cudaGetSymbolAddress((void**)&n_l,     g_n_l);

    uint32_t *ac, *al, *mpl, *hc, *hl, *hlp;
    cudaGetSymbolAddress((void**)&ac,  g_ac);
    cudaGetSymbolAddress((void**)&al,  g_al);
    cudaGetSymbolAddress((void**)&mpl, g_m);
    cudaGetSymbolAddress((void**)&hc,  g_hc);
    cudaGetSymbolAddress((void**)&hl,  g_hl);
    cudaGetSymbolAddress((void**)&hlp, g_hlp);

    int *cnt_c, *cnt_l, *off_c, *off_l, *cur_c, *cur_l, *src_c, *src_l;
    cudaGetSymbolAddress((void**)&cnt_c, g_cnt_c);
    cudaGetSymbolAddress((void**)&cnt_l, g_cnt_l);
    cudaGetSymbolAddress((void**)&off_c, g_off_c);
    cudaGetSymbolAddress((void**)&off_l, g_off_l);
    cudaGetSymbolAddress((void**)&cur_c, g_cur_c);
    cudaGetSymbolAddress((void**)&cur_l, g_cur_l);
    cudaGetSymbolAddress((void**)&src_c, g_src_c);
    cudaGetSymbolAddress((void**)&src_l, g_src_l);

    uint32_t* whi;
    cudaGetSymbolAddress((void**)&whi, g_whi);

    cudaFuncSetAttribute(mlp2_multi, cudaFuncAttributeMaxDynamicSharedMemorySize,
                         MLP2_DSMEM);
    cudaFuncSetAttribute(gru_gemm_multi, cudaFuncAttributeMaxDynamicSharedMemorySize,
                         GRU_DSMEM);

    const int o_l2c0 = 0,      o_l2c1 = 8192,  o_c2l0 = 16384, o_c2l1 = 24576;
    const int o_l2l0 = 32768,  o_l2l1 = 40960;
    const int o_cih  = 49152,  o_chh  = 73728;
    const int o_lih  = 98304,  o_lhh  = 147456;

    // ---- pre-convert weights (fp16 single plane) ----
    split_w<<<32, 256>>>(l2c_W0, whi + o_l2c0, 8192, 64);
    split_w<<<32, 256>>>(l2c_W1, whi + o_l2c1, 8192, 64);
    split_w<<<32, 256>>>(c2l_W0, whi + o_c2l0, 8192, 64);
    split_w<<<32, 256>>>(c2l_W1, whi + o_c2l1, 8192, 64);
    split_w<<<32, 256>>>(l2l_W0, whi + o_l2l0, 8192, 64);
    split_w<<<32, 256>>>(l2l_W1, whi + o_l2l1, 8192, 64);
    split_w<<<96, 256>>>(c_Wih,  whi + o_cih,  24576, 64);
    split_w<<<96, 256>>>(c_Whh,  whi + o_chh,  24576, 64);
    split_w<<<192, 256>>>(l_Wih, whi + o_lih,  49152, 128);
    split_w<<<96, 256>>>(l_Whh,  whi + o_lhh,  24576, 64);

    // ---- CSR build ----
    cudaMemsetAsync(cnt_c, 0, (size_t)C * sizeof(int));
    cudaMemsetAsync(cnt_l, 0, (size_t)L * sizeof(int));
    hist2<<<(E + 255) / 256, 256>>>(l_edge, c_edge, cnt_l, cnt_c, E);
    exscan<<<1, 1024>>>(cnt_c, off_c, C);
    exscan<<<1, 1024>>>(cnt_l, off_l, L);
    cudaMemcpyAsync(cur_c, off_c, (size_t)C * sizeof(int), cudaMemcpyDeviceToDevice);
    cudaMemcpyAsync(cur_l, off_l, (size_t)L * sizeof(int), cudaMemcpyDeviceToDevice);
    fill2<<<(E + 255) / 256, 256>>>(l_edge, c_edge, cur_l, cur_c, src_l, src_c, E);

    // iteration-0 slices = inputs; seed state planes (normal + perm)
    cudaMemcpyAsync(louts, l_emb0, (size_t)L * D * sizeof(float), cudaMemcpyDeviceToDevice);
    cudaMemcpyAsync(couts, c_emb0, (size_t)C * D * sizeof(float), cudaMemcpyDeviceToDevice);
    split_act<<<(L * 64 + 255) / 256, 256>>>(l_emb0, hl,  L, 0);
    split_act<<<(L * 64 + 255) / 256, 256>>>(l_emb0, hlp, L, 1);
    split_act<<<(C * 64 + 255) / 256, 256>>>(c_emb0, hc,  C, 0);

    const int gLx = (L + 127) / 128;
    const int gCx = (C + 127) / 128;
    const int total_nodes = C + L;
    const dim3 gGemm(gCx + gLx, 4);

    for (int it = 0; it < NITER; it++) {
        const float* l_prev = louts + (size_t)it * L * D;
        const float* c_prev = couts + (size_t)it * C * D;
        float* l_next = louts + (size_t)(it + 1) * L * D;
        float* c_next = couts + (size_t)(it + 1) * C * D;

        // phase 1: all three message MLPs in one launch (A from planes)
        MlpP p0 = {hl,  whi + o_l2c0, l2c_b0, whi + o_l2c1, l2c_b1,
                   l2c_msg, nullptr, L, gLx};
        MlpP p1 = {hc,  whi + o_c2l0, c2l_b0, whi + o_c2l1, c2l_b1,
                   c2l_msg, nullptr, C, gCx};
        MlpP p2 = {hlp, whi + o_l2l0, l2l_b0, whi + o_l2l1, l2l_b1,
                   nullptr, mpl, L, gLx};
        mlp2_multi<<<gLx + gCx + gLx, 256, MLP2_DSMEM>>>(p0, p1, p2);

        // phase 2: both gathers in one launch (fp16 msgs -> planes)
        gather2<<<(total_nodes + 7) / 8, 256>>>(l2c_msg, off_c, src_c, ac, C,
                                                c2l_msg, off_l, src_l, al, L);

        // phase 3: all GRU gate GEMMs in one launch (all-async)
        GruP pc = {ac, nullptr, hc, 8, 0,
                   whi + o_cih, whi + o_chh, c_bih, c_bhh, rz_c, n_c, C, gCx};
        GruP pl = {al, mpl, hl, 8, 8,
                   whi + o_lih, whi + o_lhh, l_bih, l_bhh, rz_l, n_l, L, gLx};
        gru_gemm_multi<<<gGemm, 256, GRU_DSMEM>>>(pc, pl);

        // phase 4: both elementwise GRU updates (fp32 + planes; literal also perm)
        gru_elem2x2<<<(total_nodes * 32 + 255) / 256, 256>>>(
            rz_c, n_c, c_prev, c_next, hc, C,
            rz_l, n_l, l_prev, l_next, hl, hlp, L);
    }
}

// round 17
// speedup vs baseline: 2.1512x; 1.0064x over previous
#include <cuda_runtime.h>
#include <cuda_fp16.h>
#include <cstdint>

// Problem constants (fixed by setup_inputs)
#define DIM   128
#define LMAX  60000
#define CMAX  30000
#define EMAX  360000
#define NITER 8

#define CBLK ((CMAX + 127) / 128)
#define LBLK ((LMAX + 127) / 128)
#define CPLANE ((size_t)CBLK * 8192)
#define LPLANE ((size_t)LBLK * 8192)

// ---------------- scratch (device globals; no allocations allowed) ----------
__device__ uint32_t g_l2c_msg[(size_t)LMAX * 64];   // half2 row-major
__device__ uint32_t g_c2l_msg[(size_t)CMAX * 64];
__device__ uint32_t g_rz_c[(size_t)CMAX * 128];     // half2: r[0:64), z[64:128)
__device__ uint32_t g_rz_l[(size_t)LMAX * 128];
__device__ float g_n_c [(size_t)CMAX * 2 * DIM];
__device__ float g_n_l [(size_t)LMAX * 2 * DIM];
// fragment-ordered fp16 activation planes (u32 = 2 fp16)
__device__ uint32_t g_ac[CPLANE];    // clause aggr
__device__ uint32_t g_al[LPLANE];    // literal aggr
__device__ uint32_t g_m [LPLANE];    // l2l message
__device__ uint32_t g_hc[CPLANE];    // clause state
__device__ uint32_t g_hl[LPLANE];    // literal state
__device__ uint32_t g_hlp[LPLANE];   // literal state, row^1-permuted
// CSR scratch
__device__ int g_cnt_c[CMAX];
__device__ int g_cnt_l[LMAX];
__device__ int g_off_c[CMAX + 1];
__device__ int g_off_l[LMAX + 1];
__device__ int g_cur_c[CMAX];
__device__ int g_cur_l[LMAX];
__device__ int g_src_c[EMAX];
__device__ int g_src_l[EMAX];
// pre-converted fp16 weight planes
#define WSPLIT_TOTAL 172032
__device__ uint32_t g_whi[WSPLIT_TOTAL];

// ======================= helpers =============================================
__device__ __forceinline__ uint32_t smem_u32(const void* p) {
    uint32_t a;
    asm("{ .reg .u64 t; cvta.to.shared.u64 t, %1; cvt.u32.u64 %0, t; }"
        : "=r"(a) : "l"(p));
    return a;
}

__device__ __forceinline__ uint32_t packh(float x, float y) {
    __half2 h = __floats2half2_rn(x, y);
    return *reinterpret_cast<uint32_t*>(&h);
}

__device__ __forceinline__ float2 unpackh(uint32_t u) {
    __half2 h = *reinterpret_cast<__half2*>(&u);
    return __half22float2(h);
}

__device__ __forceinline__ void cp16(uint32_t dst, const void* src) {
    asm volatile("cp.async.ca.shared.global [%0], [%1], 16;"
                 :: "r"(dst), "l"(src) : "memory");
}
#define CP_COMMIT() asm volatile("cp.async.commit_group;" ::: "memory")
#define CP_WAIT0()  asm volatile("cp.async.wait_group 0;" ::: "memory")
#define CP_WAIT1()  asm volatile("cp.async.wait_group 1;" ::: "memory")
#define CP_WAIT2()  asm volatile("cp.async.wait_group 2;" ::: "memory")
#define WAITN(w) do { \
        if ((w) >= 2) CP_WAIT2(); \
        else if ((w) == 1) CP_WAIT1(); \
        else CP_WAIT0(); \
    } while (0)

__device__ __forceinline__ void mma_f16(float* d, const uint32_t* a,
                                        uint32_t b0, uint32_t b1) {
    asm volatile(
        "mma.sync.aligned.m16n8k16.row.col.f32.f16.f16.f32 "
        "{%0,%1,%2,%3}, {%4,%5,%6,%7}, {%8,%9}, {%0,%1,%2,%3};"
        : "+f"(d[0]), "+f"(d[1]), "+f"(d[2]), "+f"(d[3])
        : "r"(a[0]), "r"(a[1]), "r"(a[2]), "r"(a[3]), "r"(b0), "r"(b1));
}

#define IDX(r, q) ((((r) << 3)) | ((q) ^ ((r) & 7)))

__device__ __forceinline__ float fsigmoid(float x) { return 1.f / (1.f + __expf(-x)); }
__device__ __forceinline__ float ftanh(float x) {
    float t = __expf(2.f * fabsf(x));
    float r = 1.f - 2.f / (t + 1.f);
    return copysignf(r, x);
}

// ======================= weight pre-convert (fp16 single plane) ==============
__global__ void split_w(const float* __restrict__ W, uint32_t* __restrict__ hi,
                        int total_pairs, int kp)
{
    int i = blockIdx.x * 256 + threadIdx.x;
    if (i >= total_pairs) return;
    int R = i / kp, p = i - R * kp;
    float2 f = ((const float2*)W)[i];
    uint32_t h = packh(f.x, f.y);
    int ngroup = R >> 7, n = R & 127;
    int ch = p >> 3, q = p & 7;
    int nt = n >> 3, l4 = n & 7;
    int region = l4 * 4 + (q & 3);
    int idx = region * 32 + (((nt >> 1) ^ (region & 7)) << 2) + ((nt & 1) << 1) + (q >> 2);
    size_t base = ((size_t)(ngroup * (kp >> 3) + ch)) << 10;
    hi[base + idx] = h;
}

// ======================= activation pre-split ================================
__global__ void split_act(const float* __restrict__ X, uint32_t* __restrict__ pl,
                          int N, int perm)
{
    int i = blockIdx.x * 256 + threadIdx.x;
    if (i >= N * 64) return;
    int row = i >> 6, pp = i & 63;
    float2 f = ((const float2*)X)[i];
    int rowp = row ^ perm;
    int chunk = pp >> 3, q = pp & 7, rl = rowp & 127;
    size_t base = ((size_t)((rowp >> 7) * 8 + chunk)) << 10;
    pl[base + IDX(rl, q)] = packh(f.x, f.y);
}

// ======================= MMA K16 sub-chunk ===================================
__device__ __forceinline__ void mma_chunk(const uint32_t* __restrict__ A,
                                          const uint32_t* __restrict__ B,
                                          float (&acc)[16][4], int lane, int wid)
{
    const int r = wid * 16 + (lane >> 2);
    const int q = lane & 3;
    uint32_t ah[4];
    ah[0] = A[IDX(r, q)];     ah[1] = A[IDX(r + 8, q)];
    ah[2] = A[IDX(r, q + 4)]; ah[3] = A[IDX(r + 8, q + 4)];
    const uint32_t* Bp = B + lane * 32;
#pragma unroll
    for (int c = 0; c < 8; c++) {
        const int sw = ((c ^ (lane & 7)) << 2);
        uint4 v = *(const uint4*)(Bp + sw);
        mma_f16(acc[2 * c],     ah, v.x, v.y);
        mma_f16(acc[2 * c + 1], ah, v.z, v.w);
    }
}

// ======================= param structs =======================================
struct MlpP {
    const uint32_t* Apl;
    const uint32_t* W0;
    const float* b0;
    const uint32_t* W1;
    const float* b1;
    uint32_t* omsg;             // half2 row-major msg output (may be null)
    uint32_t* opl;              // plane output (may be null)
    int N, gx;
};

struct GruP {
    const uint32_t *S0, *S1, *H;
    int n0, n1;
    const uint32_t *Wih, *Whh;
    const float *bih, *bhh;
    uint32_t* rz;               // half2 gate buffer
    float* nbuf;
    int N, gx;
};

// chunk32 buffer (u32, 4096): [A0 1024][A1 1024][B0 1024][B1 1024]

// ======================= combined fused 2-layer MLP (occ 2, depth-4 ring) ====
// dyn smem (u32): stage1 ring 4 x 4096 = [0,16384);
// stage2: A spill region [0,8192), B ring 4 x 2048 at [16384, 24576).
#define MLP2_DSMEM (24576 * 4)

__global__ __launch_bounds__(256, 2)
void mlp2_multi(MlpP p0, MlpP p1, MlpP p2)
{
    extern __shared__ __align__(16) uint32_t sm[];
    __shared__ float sb0[128];

    int bx = blockIdx.x;
    MlpP p;
    if (bx < p0.gx) { p = p0; }
    else if (bx < p0.gx + p1.gx) { p = p1; bx -= p0.gx; }
    else { p = p2; bx -= p0.gx + p1.gx; }

    const int t = threadIdx.x, lane = t & 31, wid = t >> 5;
    const int m0 = bx * 128;
    const int blk8 = bx * 8;

    if (t < 128) sb0[t] = p.b0[t];

    float acc1[16][4];
#pragma unroll
    for (int i = 0; i < 16; i++)
#pragma unroll
        for (int j = 0; j < 4; j++) acc1[i][j] = 0.f;

#define CPA1(ch, buf) do { \
        _Pragma("unroll") \
        for (int si = 0; si < 2; si++) { \
            const uint32_t* gp = p.Apl + ((size_t)(blk8 + 2 * (ch) + si) << 10) + t * 4; \
            cp16(smem_u32(sm + (buf) * 4096 + si * 1024 + t * 4), gp); \
        } \
    } while (0)
#define CPW1(ch, buf) do { \
        _Pragma("unroll") \
        for (int si = 0; si < 2; si++) { \
            const uint32_t* gp = p.W0 + ((size_t)(2 * (ch) + si) << 10) + t * 4; \
            cp16(smem_u32(sm + (buf) * 4096 + 2048 + si * 1024 + t * 4), gp); \
        } \
    } while (0)
#define CPW2(ch, buf) do { \
        _Pragma("unroll") \
        for (int si = 0; si < 2; si++) { \
            const uint32_t* gp = p.W1 + ((size_t)(2 * (ch) + si) << 10) + t * 4; \
            cp16(smem_u32(sm + 16384 + (buf) * 2048 + si * 1024 + t * 4), gp); \
        } \
    } while (0)

    // ---- stage 1: 4 K32 chunks, depth-4 ring ----
#pragma unroll
    for (int i = 0; i < 3; i++) {
        if (i < 4) { CPA1(i, i); CPW1(i, i); }
        CP_COMMIT();
    }
    CP_WAIT2(); __syncthreads();
    for (int ch = 0; ch < 4; ch++) {
        if (ch + 3 < 4) { CPA1(ch + 3, (ch + 3) & 3); CPW1(ch + 3, (ch + 3) & 3); }
        CP_COMMIT();
        const uint32_t* S = sm + (ch & 3) * 4096;
        mma_chunk(S,        S + 2048, acc1, lane, wid);
        mma_chunk(S + 1024, S + 3072, acc1, lane, wid);
        int w = 4 - ch - 2; if (w > 2) w = 2; if (w < 0) w = 0;
        WAITN(w);
        __syncthreads();
    }

    // ---- bias + relu, spill stage-1 result into A region (fp16 planes) ----
    {
        const int rlo = wid * 16 + (lane >> 2);
        const int rhi = rlo + 8;
#pragma unroll
        for (int nt = 0; nt < 16; nt++) {
            const int col = nt * 8 + 2 * (lane & 3);
            float bx2 = sb0[col], by = sb0[col + 1];
            float v0 = fmaxf(acc1[nt][0] + bx2, 0.f);
            float v1 = fmaxf(acc1[nt][1] + by, 0.f);
            float v2 = fmaxf(acc1[nt][2] + bx2, 0.f);
            float v3 = fmaxf(acc1[nt][3] + by, 0.f);
            const int ch16 = nt >> 1;
            const int q = (nt & 1) * 4 + (lane & 3);
            sm[ch16 * 1024 + IDX(rlo, q)] = packh(v0, v1);
            sm[ch16 * 1024 + IDX(rhi, q)] = packh(v2, v3);
        }
    }

    float acc2[16][4];
#pragma unroll
    for (int i = 0; i < 16; i++)
#pragma unroll
        for (int j = 0; j < 4; j++) acc2[i][j] = 0.f;

    // ---- stage 2: A from smem region, W1 streamed, depth-4 B ring ----
#pragma unroll
    for (int i = 0; i < 3; i++) {
        if (i < 4) CPW2(i, i);
        CP_COMMIT();
    }
    CP_WAIT2(); __syncthreads();   // also publishes the spill
    for (int ch = 0; ch < 4; ch++) {
        if (ch + 3 < 4) CPW2(ch + 3, (ch + 3) & 3);
        CP_COMMIT();
        const uint32_t* B = sm + 16384 + (ch & 3) * 2048;
        mma_chunk(sm + (2 * ch) * 1024,     B,        acc2, lane, wid);
        mma_chunk(sm + (2 * ch + 1) * 1024, B + 1024, acc2, lane, wid);
        if (ch + 1 < 4) {
            int w = 4 - ch - 2; if (w > 2) w = 2; if (w < 0) w = 0;
            WAITN(w);
            __syncthreads();
        }
    }

    // ---- epilogue: half2 msg or fragment-plane output ----
    const int rl0 = wid * 16 + (lane >> 2);
    const int rl1 = rl0 + 8;
    if (p.opl) {
#pragma unroll
        for (int nt = 0; nt < 16; nt++) {
            const int col = nt * 8 + 2 * (lane & 3);
            float bx2 = p.b1[col], by = p.b1[col + 1];
            float v0 = acc2[nt][0] + bx2, v1 = acc2[nt][1] + by;
            float v2 = acc2[nt][2] + bx2, v3 = acc2[nt][3] + by;
            const int pq = nt * 4 + (lane & 3);
            const int chunk = pq >> 3, q = pq & 7;
            const size_t base = ((size_t)(bx * 8 + chunk)) << 10;
            p.opl[base + IDX(rl0, q)] = packh(v0, v1);
            p.opl[base + IDX(rl1, q)] = packh(v2, v3);
        }
    } else {
        const int r0 = m0 + rl0;
#pragma unroll
        for (int nt = 0; nt < 16; nt++) {
            const int col = nt * 8 + 2 * (lane & 3);
            float bx2 = p.b1[col], by = p.b1[col + 1];
            if (r0 < p.N)
                p.omsg[(size_t)r0 * 64 + (col >> 1)] =
                    packh(acc2[nt][0] + bx2, acc2[nt][1] + by);
            if (r0 + 8 < p.N)
                p.omsg[(size_t)(r0 + 8) * 64 + (col >> 1)] =
                    packh(acc2[nt][2] + bx2, acc2[nt][3] + by);
        }
    }
#undef CPA1
#undef CPW1
#undef CPW2
}

// ======================= combined GRU gate GEMM (depth-4 ring) ===============
#define GRU_DSMEM (4 * 4096 * 4)

__global__ __launch_bounds__(256, 2)
void gru_gemm_multi(GruP pc, GruP pl)
{
    extern __shared__ __align__(16) uint32_t sm[];

    int bx = blockIdx.x;
    GruP p;
    if (bx < pc.gx) { p = pc; }
    else { p = pl; bx -= pc.gx; }

    const int t = threadIdx.x, lane = t & 31, wid = t >> 5;
    const int m0 = bx * 128;
    const int g  = blockIdx.y;
    const int nchi = p.n0 + p.n1;
    const int nch32 = (g < 2) ? (nchi + 8) >> 1 : (g == 2 ? nchi >> 1 : 4);
    const int blk8 = bx * 8;

    float acc[16][4];
#pragma unroll
    for (int i = 0; i < 16; i++)
#pragma unroll
        for (int j = 0; j < 4; j++) acc[i][j] = 0.f;

#define CPA(ch, buf) do { \
        _Pragma("unroll") \
        for (int si = 0; si < 2; si++) { \
            const int c16 = 2 * (ch) + si; \
            const uint32_t* sp; int cl; \
            if (g == 3)            { sp = p.H;  cl = c16; } \
            else if (c16 < p.n0)   { sp = p.S0; cl = c16; } \
            else if (c16 < nchi)   { sp = p.S1; cl = c16 - p.n0; } \
            else                   { sp = p.H;  cl = c16 - nchi; } \
            const uint32_t* gp = sp + ((size_t)(blk8 + cl) << 10) + t * 4; \
            cp16(smem_u32(sm + (buf) * 4096 + si * 1024 + t * 4), gp); \
        } \
    } while (0)
#define CPW(ch, buf) do { \
        _Pragma("unroll") \
        for (int si = 0; si < 2; si++) { \
            const int c16 = 2 * (ch) + si; \
            const uint32_t* gp; \
            if (g < 2) gp = (c16 < nchi) \
                ? p.Wih + (((size_t)(g * nchi + c16)) << 10) + t * 4 \
                : p.Whh + (((size_t)(g * 8 + c16 - nchi)) << 10) + t * 4; \
            else if (g == 2) gp = p.Wih + (((size_t)(2 * nchi + c16)) << 10) + t * 4; \
            else gp = p.Whh + (((size_t)(16 + c16)) << 10) + t * 4; \
            cp16(smem_u32(sm + (buf) * 4096 + 2048 + si * 1024 + t * 4), gp); \
        } \
    } while (0)

    const int n = nch32;
#pragma unroll
    for (int i = 0; i < 3; i++) {
        if (i < n) { CPA(i, i); CPW(i, i); }
        CP_COMMIT();
    }
    CP_WAIT2(); __syncthreads();
    for (int ch = 0; ch < n; ch++) {
        if (ch + 3 < n) { CPA(ch + 3, (ch + 3) & 3); CPW(ch + 3, (ch + 3) & 3); }
        CP_COMMIT();
        const uint32_t* S = sm + (ch & 3) * 4096;
        mma_chunk(S,        S + 2048, acc, lane, wid);
        mma_chunk(S + 1024, S + 3072, acc, lane, wid);
        if (ch + 1 < n) {
            int w = n - ch - 2; if (w > 2) w = 2; if (w < 0) w = 0;
            WAITN(w);
            __syncthreads();
        }
    }

    const int r0 = m0 + wid * 16 + (lane >> 2);
    if (g < 2) {
#pragma unroll
        for (int nt = 0; nt < 16; nt++) {
            const int col = nt * 8 + 2 * (lane & 3);
            float bx2 = p.bih[g * 128 + col]     + p.bhh[g * 128 + col];
            float by  = p.bih[g * 128 + col + 1] + p.bhh[g * 128 + col + 1];
            if (r0 < p.N)
                p.rz[(size_t)r0 * 128 + g * 64 + (col >> 1)] =
                    packh(fsigmoid(acc[nt][0] + bx2), fsigmoid(acc[nt][1] + by));
            if (r0 + 8 < p.N)
                p.rz[(size_t)(r0 + 8) * 128 + g * 64 + (col >> 1)] =
                    packh(fsigmoid(acc[nt][2] + bx2), fsigmoid(acc[nt][3] + by));
        }
    } else {
        const float* bs = (g == 2) ? p.bih : p.bhh;
        const int go = (g - 2) * 128;
#pragma unroll
        for (int nt = 0; nt < 16; nt++) {
            const int col = nt * 8 + 2 * (lane & 3);
            float bx2 = bs[256 + col], by = bs[256 + col + 1];
            if (r0 < p.N)
                *(float2*)(p.nbuf + (size_t)r0 * 256 + go + col) =
                    make_float2(acc[nt][0] + bx2, acc[nt][1] + by);
            if (r0 + 8 < p.N)
                *(float2*)(p.nbuf + (size_t)(r0 + 8) * 256 + go + col) =
                    make_float2(acc[nt][2] + bx2, acc[nt][3] + by);
        }
    }
#undef CPA
#undef CPW
}

// ======================= CSR build ===========================================
__global__ void hist2(const int* __restrict__ l_e, const int* __restrict__ c_e,
                      int* __restrict__ cnt_l, int* __restrict__ cnt_c, int E)
{
    int i = blockIdx.x * blockDim.x + threadIdx.x;
    if (i < E) {
        atomicAdd(&cnt_l[l_e[i]], 1);
        atomicAdd(&cnt_c[c_e[i]], 1);
    }
}

__global__ void exscan(const int* __restrict__ cnt, int* __restrict__ off, int n)
{
    __shared__ int part[1024];
    const int t = threadIdx.x;
    const int chunk = (n + 1023) >> 10;
    const int b = t * chunk;
    const int e = min(b + chunk, n);
    int s = 0;
    for (int i = b; i < e; i++) s += cnt[i];
    part[t] = s;
    __syncthreads();
    for (int d = 1; d < 1024; d <<= 1) {
        int v = (t >= d) ? part[t - d] : 0;
        __syncthreads();
        if (t >= d) part[t] += v;
        __syncthreads();
    }
    int run = (t == 0) ? 0 : part[t - 1];
    for (int i = b; i < e; i++) { off[i] = run; run += cnt[i]; }
    if (t == 0) off[n] = part[1023];
}

__global__ void fill2(const int* __restrict__ l_e, const int* __restrict__ c_e,
                      int* __restrict__ cur_l, int* __restrict__ cur_c,
                      int* __restrict__ src_l, int* __restrict__ src_c, int E)
{
    int i = blockIdx.x * blockDim.x + threadIdx.x;
    if (i < E) {
        int l = l_e[i], c = c_e[i];
        src_c[atomicAdd(&cur_c[c], 1)] = l;
        src_l[atomicAdd(&cur_l[l], 1)] = c;
    }
}

// ======================= combined gather-sum (fp16 msgs -> planes) ===========
__global__ __launch_bounds__(256)
void gather2(const uint32_t* __restrict__ msgA, const int* __restrict__ offA,
             const int* __restrict__ srcA, uint32_t* __restrict__ aplA, int nA,
             const uint32_t* __restrict__ msgB, const int* __restrict__ offB,
             const int* __restrict__ srcB, uint32_t* __restrict__ aplB, int nB)
{
    int node = blockIdx.x * 8 + (threadIdx.x >> 5);
    int lane = threadIdx.x & 31;
    const uint32_t* msg;
    const int *off, *srcs;
    uint32_t* apl;
    if (node < nA) { msg = msgA; off = offA; srcs = srcA; apl = aplA; }
    else {
        node -= nA;
        if (node >= nB) return;
        msg = msgB; off = offB; srcs = srcB; apl = aplB;
    }
    int b = off[node], e = off[node + 1];
    float4 acc = {0.f, 0.f, 0.f, 0.f};
    for (int i = b; i < e; i++) {
        const uint2 u = *(const uint2*)(msg + (size_t)srcs[i] * 64 + lane * 2);
        float2 a = unpackh(u.x), c = unpackh(u.y);
        acc.x += a.x; acc.y += a.y; acc.z += c.x; acc.w += c.y;
    }
    const int rl = node & 127;
    const int chunk = lane >> 2;
    const int q0 = (2 * lane) & 7;
    const size_t base = ((size_t)((node >> 7) * 8 + chunk)) << 10;
    apl[base + IDX(rl, q0)]     = packh(acc.x, acc.y);
    apl[base + IDX(rl, q0 + 1)] = packh(acc.z, acc.w);
}

// ---------------- combined GRU elementwise (half2 rz; fp32 nbuf) -------------
__global__ void gru_elem2x2(const uint32_t* __restrict__ rzA, const float* __restrict__ nA,
                            const float* __restrict__ hA, float* __restrict__ hnA,
                            uint32_t* __restrict__ plA, int NA,
                            const uint32_t* __restrict__ rzB, const float* __restrict__ nB,
                            const float* __restrict__ hB, float* __restrict__ hnB,
                            uint32_t* __restrict__ plB, uint32_t* __restrict__ plBp, int NB)
{
    int idx = blockIdx.x * blockDim.x + threadIdx.x;
    int row = idx >> 5, c4 = (idx & 31) * 4;
    const uint32_t* rz;
    const float *nbuf, *h;
    float* hnew;
    uint32_t *pl, *plp;
    if (row < NA) { rz = rzA; nbuf = nA; h = hA; hnew = hnA; pl = plA; plp = nullptr; }
    else {
        row -= NA;
        if (row >= NB) return;
        rz = rzB; nbuf = nB; h = hB; hnew = hnB; pl = plB; plp = plBp;
    }
    const uint2 ru = *(const uint2*)(rz + (size_t)row * 128 + (c4 >> 1));
    const uint2 zu = *(const uint2*)(rz + (size_t)row * 128 + 64 + (c4 >> 1));
    const float2 r01 = unpackh(ru.x), r23 = unpackh(ru.y);
    const float2 z01 = unpackh(zu.x), z23 = unpackh(zu.y);
    const float4 ni = *(const float4*)(nbuf + (size_t)row * 256 + c4);
    const float4 nh = *(const float4*)(nbuf + (size_t)row * 256 + 128 + c4);
    const float4 h4 = *(const float4*)(h + (size_t)row * 128 + c4);
    float4 o;
    o.x = (1.f - z01.x) * ftanh(ni.x + r01.x * nh.x) + z01.x * h4.x;
    o.y = (1.f - z01.y) * ftanh(ni.y + r01.y * nh.y) + z01.y * h4.y;
    o.z = (1.f - z23.x) * ftanh(ni.z + r23.x * nh.z) + z23.x * h4.z;
    o.w = (1.f - z23.y) * ftanh(ni.w + r23.y * nh.w) + z23.y * h4.w;
    *(float4*)(hnew + (size_t)row * 128 + c4) = o;
    const uint32_t u0 = packh(o.x, o.y), u1 = packh(o.z, o.w);
    const int q0 = (c4 >> 1) & 7;
    {
        const int rl = row & 127;
        const size_t base = ((size_t)((row >> 7) * 8 + (c4 >> 4))) << 10;
        pl[base + IDX(rl, q0)]     = u0;
        pl[base + IDX(rl, q0 + 1)] = u1;
    }
    if (plp) {
        const int rowp = row ^ 1;
        const int rl = rowp & 127;
        const size_t base = ((size_t)((rowp >> 7) * 8 + (c4 >> 4))) << 10;
        plp[base + IDX(rl, q0)]     = u0;
        plp[base + IDX(rl, q0 + 1)] = u1;
    }
}

// ---------------- launch ------------------------------------------------------
extern "C" void kernel_launch(void* const* d_in, const int* in_sizes, int n_in,
                              void* d_out, int out_size)
{
    const int D = DIM;
    const int E = in_sizes[2];
    const int L = in_sizes[4] / D;
    const int C = in_sizes[5] / D;

    const int*   l_edge = (const int*)d_in[2];
    const int*   c_edge = (const int*)d_in[3];
    const float* l_emb0 = (const float*)d_in[4];
    const float* c_emb0 = (const float*)d_in[5];

    const float* l2c_W0 = (const float*)d_in[6];
    const float* l2c_b0 = (const float*)d_in[7];
    const float* l2c_W1 = (const float*)d_in[8];
    const float* l2c_b1 = (const float*)d_in[9];
    const float* c2l_W0 = (const float*)d_in[10];
    const float* c2l_b0 = (const float*)d_in[11];
    const float* c2l_W1 = (const float*)d_in[12];
    const float* c2l_b1 = (const float*)d_in[13];
    const float* l2l_W0 = (const float*)d_in[14];
    const float* l2l_b0 = (const float*)d_in[15];
    const float* l2l_W1 = (const float*)d_in[16];
    const float* l2l_b1 = (const float*)d_in[17];
    const float* c_Wih  = (const float*)d_in[18];
    const float* c_Whh  = (const float*)d_in[19];
    const float* c_bih  = (const float*)d_in[20];
    const float* c_bhh  = (const float*)d_in[21];
    const float* l_Wih  = (const float*)d_in[22];
    const float* l_Whh  = (const float*)d_in[23];
    const float* l_bih  = (const float*)d_in[24];
    const float* l_bhh  = (const float*)d_in[25];

    float* out   = (float*)d_out;
    float* louts = out;                                // [9, L, D]
    float* couts = out + (size_t)(NITER + 1) * L * D;  // [9, C, D]

    uint32_t *l2c_msg, *c2l_msg, *rz_c, *rz_l;
    float *n_c, *n_l;
    cudaGetSymbolAddress((void**)&l2c_msg, g_l2c_msg);
    cudaGetSymbolAddress((void**)&c2l_msg, g_c2l_msg);
    cudaGetSymbolAddress((void**)&rz_c,    g_rz_c);
    cudaGetSymbolAddress((void**)&n_c,     g_n_c);
    cudaGetSymbolAddress((void**)&rz_l,    g_rz_l);
    cudaGetSymbolAddress((void**)&n_l,     g_n_l);

    uint32_t *ac, *al, *mpl, *hc, *hl, *hlp;
    cudaGetSymbolAddress((void**)&ac,  g_ac);
    cudaGetSymbolAddress((void**)&al,  g_al);
    cudaGetSymbolAddress((void**)&mpl, g_m);
    cudaGetSymbolAddress((void**)&hc,  g_hc);
    cudaGetSymbolAddress((void**)&hl,  g_hl);
    cudaGetSymbolAddress((void**)&hlp, g_hlp);

    int *cnt_c, *cnt_l, *off_c, *off_l, *cur_c, *cur_l, *src_c, *src_l;
    cudaGetSymbolAddress((void**)&cnt_c, g_cnt_c);
    cudaGetSymbolAddress((void**)&cnt_l, g_cnt_l);
    cudaGetSymbolAddress((void**)&off_c, g_off_c);
    cudaGetSymbolAddress((void**)&off_l, g_off_l);
    cudaGetSymbolAddress((void**)&cur_c, g_cur_c);
    cudaGetSymbolAddress((void**)&cur_l, g_cur_l);
    cudaGetSymbolAddress((void**)&src_c, g_src_c);
    cudaGetSymbolAddress((void**)&src_l, g_src_l);

    uint32_t* whi;
    cudaGetSymbolAddress((void**)&whi, g_whi);

    cudaFuncSetAttribute(mlp2_multi, cudaFuncAttributeMaxDynamicSharedMemorySize,
                         MLP2_DSMEM);
    cudaFuncSetAttribute(gru_gemm_multi, cudaFuncAttributeMaxDynamicSharedMemorySize,
                         GRU_DSMEM);

    const int o_l2c0 = 0,      o_l2c1 = 8192,  o_c2l0 = 16384, o_c2l1 = 24576;
    const int o_l2l0 = 32768,  o_l2l1 = 40960;
    const int o_cih  = 49152,  o_chh  = 73728;
    const int o_lih  = 98304,  o_lhh  = 147456;

    // ---- pre-convert weights (fp16 single plane) ----
    split_w<<<32, 256>>>(l2c_W0, whi + o_l2c0, 8192, 64);
    split_w<<<32, 256>>>(l2c_W1, whi + o_l2c1, 8192, 64);
    split_w<<<32, 256>>>(c2l_W0, whi + o_c2l0, 8192, 64);
    split_w<<<32, 256>>>(c2l_W1, whi + o_c2l1, 8192, 64);
    split_w<<<32, 256>>>(l2l_W0, whi + o_l2l0, 8192, 64);
    split_w<<<32, 256>>>(l2l_W1, whi + o_l2l1, 8192, 64);
    split_w<<<96, 256>>>(c_Wih,  whi + o_cih,  24576, 64);
    split_w<<<96, 256>>>(c_Whh,  whi + o_chh,  24576, 64);
    split_w<<<192, 256>>>(l_Wih, whi + o_lih,  49152, 128);
    split_w<<<96, 256>>>(l_Whh,  whi + o_lhh,  24576, 64);

    // ---- CSR build ----
    cudaMemsetAsync(cnt_c, 0, (size_t)C * sizeof(int));
    cudaMemsetAsync(cnt_l, 0, (size_t)L * sizeof(int));
    hist2<<<(E + 255) / 256, 256>>>(l_edge, c_edge, cnt_l, cnt_c, E);
    exscan<<<1, 1024>>>(cnt_c, off_c, C);
    exscan<<<1, 1024>>>(cnt_l, off_l, L);
    cudaMemcpyAsync(cur_c, off_c, (size_t)C * sizeof(int), cudaMemcpyDeviceToDevice);
    cudaMemcpyAsync(cur_l, off_l, (size_t)L * sizeof(int), cudaMemcpyDeviceToDevice);
    fill2<<<(E + 255) / 256, 256>>>(l_edge, c_edge, cur_l, cur_c, src_l, src_c, E);

    // iteration-0 slices = inputs; seed state planes (normal + perm)
    cudaMemcpyAsync(louts, l_emb0, (size_t)L * D * sizeof(float), cudaMemcpyDeviceToDevice);
    cudaMemcpyAsync(couts, c_emb0, (size_t)C * D * sizeof(float), cudaMemcpyDeviceToDevice);
    split_act<<<(L * 64 + 255) / 256, 256>>>(l_emb0, hl,  L, 0);
    split_act<<<(L * 64 + 255) / 256, 256>>>(l_emb0, hlp, L, 1);
    split_act<<<(C * 64 + 255) / 256, 256>>>(c_emb0, hc,  C, 0);

    const int gLx = (L + 127) / 128;
    const int gCx = (C + 127) / 128;
    const int total_nodes = C + L;
    const dim3 gGemm(gCx + gLx, 4);

    for (int it = 0; it < NITER; it++) {
        const float* l_prev = louts + (size_t)it * L * D;
        const float* c_prev = couts + (size_t)it * C * D;
        float* l_next = louts + (size_t)(it + 1) * L * D;
        float* c_next = couts + (size_t)(it + 1) * C * D;

        // phase 1: all three message MLPs in one launch (A from planes)
        MlpP p0 = {hl,  whi + o_l2c0, l2c_b0, whi + o_l2c1, l2c_b1,
                   l2c_msg, nullptr, L, gLx};
        MlpP p1 = {hc,  whi + o_c2l0, c2l_b0, whi + o_c2l1, c2l_b1,
                   c2l_msg, nullptr, C, gCx};
        MlpP p2 = {hlp, whi + o_l2l0, l2l_b0, whi + o_l2l1, l2l_b1,
                   nullptr, mpl, L, gLx};
        mlp2_multi<<<gLx + gCx + gLx, 256, MLP2_DSMEM>>>(p0, p1, p2);

        // phase 2: both gathers in one launch (fp16 msgs -> planes)
        gather2<<<(total_nodes + 7) / 8, 256>>>(l2c_msg, off_c, src_c, ac, C,
                                                c2l_msg, off_l, src_l, al, L);

        // phase 3: all GRU gate GEMMs in one launch (depth-4 ring)
        GruP pc = {ac, nullptr, hc, 8, 0,
                   whi + o_cih, whi + o_chh, c_bih, c_bhh, rz_c, n_c, C, gCx};
        GruP pl = {al, mpl, hl, 8, 8,
                   whi + o_lih, whi + o_lhh, l_bih, l_bhh, rz_l, n_l, L, gLx};
        gru_gemm_multi<<<gGemm, 256, GRU_DSMEM>>>(pc, pl);

        // phase 4: both elementwise GRU updates (fp32 + planes; literal also perm)
        gru_elem2x2<<<(total_nodes * 32 + 255) / 256, 256>>>(
            rz_c, n_c, c_prev, c_next, hc, C,
            rz_l, n_l, l_prev, l_next, hl, hlp, L);
    }
}